// round 10
// baseline (speedup 1.0000x reference)
#include <cuda_runtime.h>
#include <cuda_bf16.h>
#include <cstdint>
#include <math.h>

#define Bc 4
#define Tc 1024
#define Cc 1024
#define Hc 16
#define Dc 64
#define BT (Bc*Tc)
#define SINKc 4

// ---------------- scratch ----------------
__device__ float g_h  [(size_t)BT*Cc];
__device__ float g_q  [(size_t)BT*Cc];        // (B,H,T,D) tf32-rounded
__device__ float g_k  [(size_t)BT*Cc];
__device__ float g_vt [(size_t)BT*Cc];        // (B,H,D,T)
__device__ float g_y  [(size_t)BT*Cc];        // (B,T,C)
__device__ float g_fc [(size_t)BT*4*Cc];
__device__ float g_x2 [(size_t)BT*Cc];
__device__ float g_eS [(size_t)Bc*Hc*Tc*Tc]; // unnormalized exp(scores), lower blocks
__device__ float g_invl[(size_t)Bc*Hc*Tc];
__device__ float g_p2 [(size_t)8*BT];        // colsum partials per q-octant
__device__ float g_imp[BT];
__device__ float g_wat [(size_t)3*Cc*Cc];
__device__ float g_wpt [(size_t)Cc*Cc];
__device__ float g_wft [(size_t)4*Cc*Cc];
__device__ float g_wf2t[(size_t)Cc*4*Cc];

// ---------------- helpers ----------------
__device__ __forceinline__ uint32_t smem_u32(const void* p) {
    uint32_t r;
    asm("{ .reg .u64 t; cvta.to.shared.u64 t, %1; cvt.u32.u64 %0, t; }"
        : "=r"(r) : "l"(p));
    return r;
}
__device__ __forceinline__ void ldsm4(uint32_t& r0, uint32_t& r1, uint32_t& r2, uint32_t& r3, uint32_t a) {
    asm volatile("ldmatrix.sync.aligned.m8n8.x4.shared.b16 {%0,%1,%2,%3},[%4];"
        : "=r"(r0), "=r"(r1), "=r"(r2), "=r"(r3) : "r"(a));
}
__device__ __forceinline__ void mma_tf32(float* c, uint32_t a0, uint32_t a1, uint32_t a2, uint32_t a3,
                                         uint32_t b0, uint32_t b1) {
    asm volatile("mma.sync.aligned.m16n8k8.row.col.f32.tf32.tf32.f32 "
        "{%0,%1,%2,%3},{%4,%5,%6,%7},{%8,%9},{%0,%1,%2,%3};"
        : "+f"(c[0]), "+f"(c[1]), "+f"(c[2]), "+f"(c[3])
        : "r"(a0), "r"(a1), "r"(a2), "r"(a3), "r"(b0), "r"(b1));
}
__device__ __forceinline__ uint32_t f2tf(float f) {
    uint32_t u;
    asm("cvt.rna.tf32.f32 %0, %1;" : "=r"(u) : "f"(f));
    return u;
}
__device__ __forceinline__ float rnd(float f) { return __uint_as_float(f2tf(f)); }
__device__ __forceinline__ void cp16(uint32_t s, const void* g) {
    asm volatile("cp.async.cg.shared.global [%0], [%1], 16;" :: "r"(s), "l"(g));
}
#define CP_COMMIT() asm volatile("cp.async.commit_group;")
#define CP_WAIT2()  asm volatile("cp.async.wait_group 2;")

// ---------------- weight transpose (tf32-rounded) ----------------
__global__ void __launch_bounds__(256) tr_kernel(const float* __restrict__ W,
                                                 float* __restrict__ Wt, int K, int N) {
    __shared__ float ts[32][33];
    int k0 = blockIdx.y * 32, n0 = blockIdx.x * 32;
    int tx = threadIdx.x & 31, ty = threadIdx.x >> 5;
    #pragma unroll
    for (int i = 0; i < 4; i++) {
        ts[ty + i*8][tx] = W[(size_t)(k0 + ty + i*8) * N + n0 + tx];
    }
    __syncthreads();
    #pragma unroll
    for (int i = 0; i < 4; i++) {
        Wt[(size_t)(n0 + ty + i*8) * K + k0 + tx] = rnd(ts[tx][ty + i*8]);
    }
}

// ---------------- LayerNorm (tf32-rounded out) ----------------
__global__ void __launch_bounds__(256) ln_kernel(const float* __restrict__ x,
                                                 const float* __restrict__ w,
                                                 const float* __restrict__ b,
                                                 float* __restrict__ out) {
    int row = blockIdx.x;
    int tid = threadIdx.x;
    const float* xr = x + (size_t)row * Cc;
    float4 v = *(const float4*)(xr + tid * 4);
    float s  = v.x + v.y + v.z + v.w;
    float s2 = v.x*v.x + v.y*v.y + v.z*v.z + v.w*v.w;
    #pragma unroll
    for (int o = 16; o; o >>= 1) {
        s  += __shfl_xor_sync(~0u, s,  o);
        s2 += __shfl_xor_sync(~0u, s2, o);
    }
    __shared__ float ws[8], ws2[8];
    int wid = tid >> 5, lid = tid & 31;
    if (lid == 0) { ws[wid] = s; ws2[wid] = s2; }
    __syncthreads();
    if (tid < 8) {
        float a = ws[tid], a2 = ws2[tid];
        #pragma unroll
        for (int o = 4; o; o >>= 1) {
            a  += __shfl_xor_sync(0xffu, a,  o);
            a2 += __shfl_xor_sync(0xffu, a2, o);
        }
        if (tid == 0) { ws[0] = a; ws2[0] = a2; }
    }
    __syncthreads();
    float mean = ws[0] * (1.0f / Cc);
    float var  = ws2[0] * (1.0f / Cc) - mean * mean;
    float inv  = rsqrtf(var + 1e-5f);
    int c = tid * 4;
    float4 wv = *(const float4*)(w + c);
    float4 bv = *(const float4*)(b + c);
    float4 ov;
    ov.x = rnd((v.x - mean) * inv * wv.x + bv.x);
    ov.y = rnd((v.y - mean) * inv * wv.y + bv.y);
    ov.z = rnd((v.z - mean) * inv * wv.z + bv.z);
    ov.w = rnd((v.w - mean) * inv * wv.w + bv.w);
    *(float4*)(out + (size_t)row * Cc + c) = ov;
}

// ---------------- tf32 MMA GEMM, cp.async 4-stage, occupancy 2 ----------------
#define GSTAGES 4
#define GSMEM_BYTES (GSTAGES * 2 * 128 * 20 * 4)
template<int EPI>
__global__ void __launch_bounds__(256, 2) mma_gemm(
    const float* __restrict__ A, const float* __restrict__ Bt,
    const float* __restrict__ bias, const float* __restrict__ res,
    float* __restrict__ outF, float* __restrict__ outQ,
    float* __restrict__ outK, float* __restrict__ outVt,
    int M, int N, int K)
{
    extern __shared__ float dsm[];
    typedef float (*Tile)[128][20];
    Tile As = (Tile)dsm;
    Tile Bs = (Tile)(dsm + GSTAGES * 128 * 20);

    int tid = threadIdx.x, lane = tid & 31, wid = tid >> 5;
    int wm = wid & 3, wn = wid >> 2;
    int bm = blockIdx.y * 128, bn = blockIdx.x * 128;

    float acc[2][8][4];
    #pragma unroll
    for (int i = 0; i < 2; i++) {
        #pragma unroll
        for (int j = 0; j < 8; j++) {
            #pragma unroll
            for (int k = 0; k < 4; k++) { acc[i][j][k] = 0.f; }
        }
    }

    int row = tid >> 1, kc = (tid & 1) * 8;
    const float* Ap = A  + (size_t)(bm + row) * K + kc;
    const float* Bp = Bt + (size_t)(bn + row) * K + kc;

    #pragma unroll
    for (int s = 0; s < GSTAGES - 1; s++) {
        int k0 = s * 16;
        cp16(smem_u32(&As[s][row][kc]),     Ap + k0);
        cp16(smem_u32(&As[s][row][kc + 4]), Ap + k0 + 4);
        cp16(smem_u32(&Bs[s][row][kc]),     Bp + k0);
        cp16(smem_u32(&Bs[s][row][kc + 4]), Bp + k0 + 4);
        CP_COMMIT();
    }

    int nk = K >> 4;
    for (int it = 0; it < nk; it++) {
        CP_WAIT2();
        __syncthreads();
        int st = it & (GSTAGES - 1);
        int nx = it + GSTAGES - 1;
        if (nx < nk) {
            int sx = nx & (GSTAGES - 1);
            int k0 = nx << 4;
            cp16(smem_u32(&As[sx][row][kc]),     Ap + k0);
            cp16(smem_u32(&As[sx][row][kc + 4]), Ap + k0 + 4);
            cp16(smem_u32(&Bs[sx][row][kc]),     Bp + k0);
            cp16(smem_u32(&Bs[sx][row][kc + 4]), Bp + k0 + 4);
        }
        CP_COMMIT();
        #pragma unroll
        for (int kk = 0; kk < 16; kk += 8) {
            uint32_t af[2][4];
            #pragma unroll
            for (int mt = 0; mt < 2; mt++) {
                ldsm4(af[mt][0], af[mt][1], af[mt][2], af[mt][3],
                      smem_u32(&As[st][wm*32 + mt*16 + (lane & 15)][kk + (lane >> 4) * 4]));
            }
            uint32_t bfr[8][2];
            #pragma unroll
            for (int np = 0; np < 4; np++) {
                uint32_t r0, r1, r2, r3;
                ldsm4(r0, r1, r2, r3,
                      smem_u32(&Bs[st][wn*64 + np*16 + (lane & 15)][kk + (lane >> 4) * 4]));
                bfr[np*2][0] = r0;   bfr[np*2][1] = r2;
                bfr[np*2+1][0] = r1; bfr[np*2+1][1] = r3;
            }
            #pragma unroll
            for (int mt = 0; mt < 2; mt++) {
                #pragma unroll
                for (int nt = 0; nt < 8; nt++) {
                    mma_tf32(acc[mt][nt], af[mt][0], af[mt][1], af[mt][2], af[mt][3],
                             bfr[nt][0], bfr[nt][1]);
                }
            }
        }
    }

    #pragma unroll
    for (int mt = 0; mt < 2; mt++) {
        #pragma unroll
        for (int nt = 0; nt < 8; nt++) {
            int r0 = bm + wm*32 + mt*16 + (lane >> 2);
            int c0 = bn + wn*64 + nt*8 + (lane & 3) * 2;
            float bb0 = bias[c0], bb1 = bias[c0 + 1];
            #pragma unroll
            for (int rr = 0; rr < 2; rr++) {
                int rg = r0 + rr * 8;
                float v0 = acc[mt][nt][rr*2 + 0] + bb0;
                float v1 = acc[mt][nt][rr*2 + 1] + bb1;
                if (EPI == 1) {
                    int sec = c0 >> 10, wc = c0 & 1023;
                    int h = wc >> 6, d = wc & 63;
                    int bbi = rg >> 10, t = rg & 1023;
                    if (sec == 0) {
                        float2 o; o.x = rnd(v0); o.y = rnd(v1);
                        *(float2*)&outQ[(((size_t)(bbi*Hc + h))*Tc + t)*Dc + d] = o;
                    } else if (sec == 1) {
                        float2 o; o.x = rnd(v0); o.y = rnd(v1);
                        *(float2*)&outK[(((size_t)(bbi*Hc + h))*Tc + t)*Dc + d] = o;
                    } else {
                        size_t vb = (((size_t)(bbi*Hc + h))*Dc + d)*Tc + t;
                        outVt[vb] = rnd(v0);
                        outVt[vb + Tc] = rnd(v1);
                    }
                } else if (EPI == 2) {
                    size_t idx = (size_t)rg * N + c0;
                    float2 rv = *(const float2*)(res + idx);
                    float2 o; o.x = v0 + rv.x; o.y = v1 + rv.y;
                    *(float2*)(outF + idx) = o;
                } else {
                    float g0 = 0.5f * v0 * (1.0f + erff(v0 * 0.70710678118654752f));
                    float g1 = 0.5f * v1 * (1.0f + erff(v1 * 0.70710678118654752f));
                    float2 o; o.x = rnd(g0); o.y = rnd(g1);
                    *(float2*)&outF[(size_t)rg * N + c0] = o;
                }
            }
        }
    }
}

// ================ single-pass flash attention (no max subtraction) ================
// smem floats: Qs[128][68] | Ks[128][68] | Ss[128][132] | Vs[64][132] | l_s[128] | red[256]
#define OFF_QS 0
#define OFF_KS 8704
#define OFF_SS 17408
#define OFF_VS 34304
#define OFF_L  42752
#define OFF_RED 42880
#define ATT_SMEM_FLOATS 43136
#define ATT_SMEM_BYTES (ATT_SMEM_FLOATS * 4)

__device__ __forceinline__ void compute_S(
    const float (*Qs)[68], const float (*Ks)[68],
    int wm, int wn, int lane, float acc[2][8][4])
{
    #pragma unroll
    for (int i = 0; i < 2; i++) {
        #pragma unroll
        for (int j = 0; j < 8; j++) {
            #pragma unroll
            for (int k = 0; k < 4; k++) { acc[i][j][k] = 0.f; }
        }
    }
    #pragma unroll
    for (int kk = 0; kk < 64; kk += 8) {
        uint32_t af[2][4];
        #pragma unroll
        for (int mt = 0; mt < 2; mt++) {
            ldsm4(af[mt][0], af[mt][1], af[mt][2], af[mt][3],
                  smem_u32(&Qs[wm*32 + mt*16 + (lane & 15)][kk + (lane >> 4) * 4]));
        }
        uint32_t bfr[8][2];
        #pragma unroll
        for (int np = 0; np < 4; np++) {
            uint32_t r0, r1, r2, r3;
            ldsm4(r0, r1, r2, r3,
                  smem_u32(&Ks[wn*64 + np*16 + (lane & 15)][kk + (lane >> 4) * 4]));
            bfr[np*2][0] = r0;   bfr[np*2][1] = r2;
            bfr[np*2+1][0] = r1; bfr[np*2+1][1] = r3;
        }
        #pragma unroll
        for (int mt = 0; mt < 2; mt++) {
            #pragma unroll
            for (int nt = 0; nt < 8; nt++) {
                mma_tf32(acc[mt][nt], af[mt][0], af[mt][1], af[mt][2], af[mt][3],
                         bfr[nt][0], bfr[nt][1]);
            }
        }
    }
}

__global__ void __launch_bounds__(256, 1) flash_kernel(const int* __restrict__ amask) {
    extern __shared__ float sm[];
    float (*Qs)[68]  = (float(*)[68]) (sm + OFF_QS);
    float (*Ks)[68]  = (float(*)[68]) (sm + OFF_KS);
    float (*Ss)[132] = (float(*)[132])(sm + OFF_SS);
    float (*Vs)[132] = (float(*)[132])(sm + OFF_VS);
    float* l_s = sm + OFF_L;
    float* red = sm + OFF_RED;

    int bh = blockIdx.y, b = bh >> 4, h = bh & 15;
    int qblk = (int)(gridDim.x - 1 - blockIdx.x);  // heavy blocks first
    int i0 = qblk << 7;
    int tid = threadIdx.x, lane = tid & 31, wid = tid >> 5;
    int wm = wid & 3, wn = wid >> 2;
    size_t esbase = (size_t)bh * Tc * Tc;

    // load Q block (already tf32-rounded)
    {
        int row = tid >> 1, c0 = (tid & 1) * 32;
        const float* qp = g_q + ((size_t)bh*Tc + i0 + row)*Dc + c0;
        #pragma unroll
        for (int c4 = 0; c4 < 32; c4 += 4) {
            *(float4*)&Qs[row][c0 + c4] = *(const float4*)(qp + c4);
        }
    }
    if (tid < 128) { l_s[tid] = 0.f; }
    __syncthreads();

    int nj = qblk + 1;
    float acc[2][8][4];
    float acco[8][4];
    #pragma unroll
    for (int j = 0; j < 8; j++) {
        #pragma unroll
        for (int k = 0; k < 4; k++) { acco[j][k] = 0.f; }
    }

    for (int jb = 0; jb < nj; jb++) {
        int j0 = jb << 7;
        {
            int row = tid >> 1, c0 = (tid & 1) * 32;
            const float* kp = g_k + ((size_t)bh*Tc + j0 + row)*Dc + c0;
            #pragma unroll
            for (int c4 = 0; c4 < 32; c4 += 4) {
                *(float4*)&Ks[row][c0 + c4] = *(const float4*)(kp + c4);
            }
            int rowv = tid >> 2, cv0 = (tid & 3) * 32;
            const float* vp = g_vt + ((size_t)bh*Dc + rowv)*Tc + j0 + cv0;
            #pragma unroll
            for (int c4 = 0; c4 < 32; c4 += 4) {
                *(float4*)&Vs[rowv][cv0 + c4] = *(const float4*)(vp + c4);
            }
        }
        __syncthreads();
        compute_S(Qs, Ks, wm, wn, lane, acc);

        // e = masked exp(s/8) (fp32, no max) -> acc; write global expS + smem tf32 P~
        #pragma unroll
        for (int mt = 0; mt < 2; mt++) {
            #pragma unroll
            for (int nt = 0; nt < 8; nt++) {
                int cl = wn*64 + nt*8 + (lane & 3) * 2;
                int c0 = j0 + cl;
                int am0 = amask[b*Tc + c0], am1 = amask[b*Tc + c0 + 1];
                #pragma unroll
                for (int rr = 0; rr < 2; rr++) {
                    int rl = wm*32 + mt*16 + rr*8 + (lane >> 2);
                    int r = i0 + rl;
                    float e0 = (c0     <= r && am0) ? __expf(acc[mt][nt][rr*2 + 0] * 0.125f) : 0.f;
                    float e1 = (c0 + 1 <= r && am1) ? __expf(acc[mt][nt][rr*2 + 1] * 0.125f) : 0.f;
                    acc[mt][nt][rr*2 + 0] = e0;
                    acc[mt][nt][rr*2 + 1] = e1;
                    float2 ef; ef.x = e0; ef.y = e1;
                    *(float2*)&g_eS[esbase + (size_t)r * Tc + c0] = ef;
                    float2 pv; pv.x = rnd(e0); pv.y = rnd(e1);
                    *(float2*)&Ss[rl][cl] = pv;
                }
            }
        }
        // per-row sums of e within this block
        #pragma unroll
        for (int mt = 0; mt < 2; mt++) {
            #pragma unroll
            for (int rr = 0; rr < 2; rr++) {
                float e = 0.f;
                #pragma unroll
                for (int nt = 0; nt < 8; nt++) {
                    e += acc[mt][nt][rr*2] + acc[mt][nt][rr*2 + 1];
                }
                e += __shfl_xor_sync(~0u, e, 1);
                e += __shfl_xor_sync(~0u, e, 2);
                if ((lane & 3) == 0) {
                    red[wn*128 + wm*32 + mt*16 + rr*8 + (lane >> 2)] = e;
                }
            }
        }
        __syncthreads();   // Ss + red visible
        if (wn == 0 && (lane & 3) == 0) {
            #pragma unroll
            for (int mt = 0; mt < 2; mt++) {
                #pragma unroll
                for (int rr = 0; rr < 2; rr++) {
                    int rl = wm*32 + mt*16 + rr*8 + (lane >> 2);
                    l_s[rl] += red[rl] + red[128 + rl];
                }
            }
        }
        // O~ += P~ @ V
        #pragma unroll
        for (int kk = 0; kk < 128; kk += 8) {
            uint32_t af[4];
            ldsm4(af[0], af[1], af[2], af[3],
                  smem_u32(&Ss[wid*16 + (lane & 15)][kk + (lane >> 4) * 4]));
            uint32_t bfr[8][2];
            #pragma unroll
            for (int np = 0; np < 4; np++) {
                uint32_t r0, r1, r2, r3;
                ldsm4(r0, r1, r2, r3,
                      smem_u32(&Vs[np*16 + (lane & 15)][kk + (lane >> 4) * 4]));
                bfr[np*2][0] = r0;   bfr[np*2][1] = r2;
                bfr[np*2+1][0] = r1; bfr[np*2+1][1] = r3;
            }
            #pragma unroll
            for (int nt = 0; nt < 8; nt++) {
                mma_tf32(acco[nt], af[0], af[1], af[2], af[3], bfr[nt][0], bfr[nt][1]);
            }
        }
        __syncthreads();   // before next K/V/Ss overwrite
    }

    // invert l, publish invl
    if (tid < 128) {
        float l = l_s[tid];
        float il = (l > 0.f) ? (1.0f / l) : 0.f;
        l_s[tid] = il;
        g_invl[(size_t)bh * Tc + i0 + tid] = il;
    }
    __syncthreads();

    // O = O~ * invl  -> g_y (tf32-rounded)
    #pragma unroll
    for (int nt = 0; nt < 8; nt++) {
        int d0 = nt*8 + (lane & 3) * 2;
        #pragma unroll
        for (int rr = 0; rr < 2; rr++) {
            int rl = wid*16 + rr*8 + (lane >> 2);
            int q = i0 + rl;
            float il = l_s[rl];
            float2 o;
            o.x = rnd(acco[nt][rr*2]     * il);
            o.y = rnd(acco[nt][rr*2 + 1] * il);
            *(float2*)&g_y[(size_t)(b*Tc + q) * Cc + h*64 + d0] = o;
        }
    }
}

// ---------------- colsum partials: imp_t partial over q-octant ----------------
__global__ void __launch_bounds__(256) colsum2_kernel() {
    int gt = blockIdx.x * 256 + threadIdx.x;   // 0..4095: b = gt>>10, t = gt&1023
    int qo = blockIdx.y;                        // 0..7
    int b = gt >> 10, t = gt & 1023;
    float s = 0.f;
    if (qo >= (t >> 7)) {
        #pragma unroll 1
        for (int h = 0; h < Hc; h++) {
            int bh = b * Hc + h;
            const float* es = g_eS + ((size_t)bh * Tc + qo * 128) * Tc + t;
            const float* il = g_invl + (size_t)bh * Tc + qo * 128;
            #pragma unroll 4
            for (int q = 0; q < 128; q++) {
                s += es[(size_t)q * Tc] * il[q];
            }
        }
    }
    g_p2[(size_t)qo * BT + gt] = s;
}

__global__ void __launch_bounds__(256) impreduce_kernel() {
    int gt = blockIdx.x * 256 + threadIdx.x;
    int t = gt & 1023;
    float s = 0.f;
    #pragma unroll
    for (int qo = 0; qo < 8; qo++) { s += g_p2[(size_t)qo * BT + gt]; }
    float posn = (float)(Tc - t) / (float)Tc;
    g_imp[gt] = (s / (float)Hc) / (posn + 1e-8f);
}

__global__ void __launch_bounds__(1024) finalize_kernel(const int* __restrict__ amask,
                                                        const float* __restrict__ thrp,
                                                        float* __restrict__ outp) {
    int tid = threadIdx.x;
    float m = -3.4e38f;
    for (int i = tid; i < BT; i += 1024) { m = fmaxf(m, g_imp[i]); }
    __shared__ float red[32];
    #pragma unroll
    for (int o = 16; o; o >>= 1) { m = fmaxf(m, __shfl_xor_sync(~0u, m, o)); }
    if ((tid & 31) == 0) red[tid >> 5] = m;
    __syncthreads();
    if (tid < 32) {
        float v = red[tid];
        #pragma unroll
        for (int o = 16; o; o >>= 1) { v = fmaxf(v, __shfl_xor_sync(~0u, v, o)); }
        if (tid == 0) red[0] = v;
    }
    __syncthreads();
    float maxv = red[0];
    float thr = *thrp;
    float* maskp = outp + (size_t)BT * Cc;
    float* impp  = maskp + BT;
    for (int i = tid; i < BT; i += 1024) {
        int t = i & 1023;
        float iv = g_imp[i];
        if (t < SINKc) iv = maxv + 1.0f;
        float mk = (iv >= thr) ? 1.0f : 0.0f;
        if (t < SINKc) mk = 1.0f;
        if (amask[i] == 0) mk = 0.0f;
        maskp[i] = mk;
        impp[i]  = iv;
    }
}

// ---------------- launch ----------------
extern "C" void kernel_launch(void* const* d_in, const int* in_sizes, int n_in,
                              void* d_out, int out_size) {
    (void)in_sizes; (void)n_in; (void)out_size;
    const float* x      = (const float*)d_in[0];
    const int*   amask  = (const int*)  d_in[1];
    const float* W_attn = (const float*)d_in[2];
    const float* b_attn = (const float*)d_in[3];
    const float* W_proj = (const float*)d_in[4];
    const float* b_proj = (const float*)d_in[5];
    const float* ln1_w  = (const float*)d_in[6];
    const float* ln1_b  = (const float*)d_in[7];
    const float* ln2_w  = (const float*)d_in[8];
    const float* ln2_b  = (const float*)d_in[9];
    const float* W_fc   = (const float*)d_in[10];
    const float* b_fc   = (const float*)d_in[11];
    const float* W_fc2  = (const float*)d_in[12];
    const float* b_fc2  = (const float*)d_in[13];
    const float* thr    = (const float*)d_in[14];
    float* outp = (float*)d_out;

    float *ph, *pq, *pk, *pvt, *py, *pfc, *px2, *pwat, *pwpt, *pwft, *pwf2t;
    cudaGetSymbolAddress((void**)&ph,    g_h);
    cudaGetSymbolAddress((void**)&pq,    g_q);
    cudaGetSymbolAddress((void**)&pk,    g_k);
    cudaGetSymbolAddress((void**)&pvt,   g_vt);
    cudaGetSymbolAddress((void**)&py,    g_y);
    cudaGetSymbolAddress((void**)&pfc,   g_fc);
    cudaGetSymbolAddress((void**)&px2,   g_x2);
    cudaGetSymbolAddress((void**)&pwat,  g_wat);
    cudaGetSymbolAddress((void**)&pwpt,  g_wpt);
    cudaGetSymbolAddress((void**)&pwft,  g_wft);
    cudaGetSymbolAddress((void**)&pwf2t, g_wf2t);

    cudaFuncSetAttribute(mma_gemm<1>, cudaFuncAttributeMaxDynamicSharedMemorySize, GSMEM_BYTES);
    cudaFuncSetAttribute(mma_gemm<2>, cudaFuncAttributeMaxDynamicSharedMemorySize, GSMEM_BYTES);
    cudaFuncSetAttribute(mma_gemm<3>, cudaFuncAttributeMaxDynamicSharedMemorySize, GSMEM_BYTES);
    cudaFuncSetAttribute(flash_kernel, cudaFuncAttributeMaxDynamicSharedMemorySize, ATT_SMEM_BYTES);

    tr_kernel<<<dim3(3*Cc/32, Cc/32),   256>>>(W_attn, pwat,  Cc,   3*Cc);
    tr_kernel<<<dim3(Cc/32,   Cc/32),   256>>>(W_proj, pwpt,  Cc,   Cc);
    tr_kernel<<<dim3(4*Cc/32, Cc/32),   256>>>(W_fc,   pwft,  Cc,   4*Cc);
    tr_kernel<<<dim3(Cc/32,   4*Cc/32), 256>>>(W_fc2,  pwf2t, 4*Cc, Cc);

    ln_kernel<<<BT, 256>>>(x, ln1_w, ln1_b, ph);
    mma_gemm<1><<<dim3(3*Cc/128, BT/128), 256, GSMEM_BYTES>>>(ph, pwat, b_attn, nullptr,
                                                 nullptr, pq, pk, pvt, BT, 3*Cc, Cc);
    flash_kernel<<<dim3(Tc/128, Bc*Hc), 256, ATT_SMEM_BYTES>>>(amask);
    colsum2_kernel<<<dim3(BT/256, 8), 256>>>();
    impreduce_kernel<<<BT/256, 256>>>();
    mma_gemm<2><<<dim3(Cc/128, BT/128), 256, GSMEM_BYTES>>>(py, pwpt, b_proj, x,
                                               px2, nullptr, nullptr, nullptr, BT, Cc, Cc);
    ln_kernel<<<BT, 256>>>(px2, ln2_w, ln2_b, ph);
    mma_gemm<3><<<dim3(4*Cc/128, BT/128), 256, GSMEM_BYTES>>>(ph, pwft, b_fc, nullptr,
                                                 pfc, nullptr, nullptr, nullptr, BT, 4*Cc, Cc);
    mma_gemm<2><<<dim3(Cc/128, BT/128), 256, GSMEM_BYTES>>>(pfc, pwf2t, b_fc2, px2,
                                               outp, nullptr, nullptr, nullptr, BT, Cc, 4*Cc);
    finalize_kernel<<<1, 1024>>>(amask, thr, outp);
}

// round 11
// speedup vs baseline: 1.2038x; 1.2038x over previous
#include <cuda_runtime.h>
#include <cuda_bf16.h>
#include <cstdint>
#include <math.h>

#define Bc 4
#define Tc 1024
#define Cc 1024
#define Hc 16
#define Dc 64
#define BT (Bc*Tc)
#define SINKc 4

// ---------------- scratch ----------------
__device__ float g_h  [(size_t)BT*Cc];
__device__ float g_q  [(size_t)BT*Cc];        // (B,H,T,D) tf32-rounded
__device__ float g_k  [(size_t)BT*Cc];
__device__ float g_vt [(size_t)BT*Cc];        // (B,H,D,T)
__device__ float g_y  [(size_t)BT*Cc];        // (B,T,C)
__device__ float g_fc [(size_t)BT*4*Cc];
__device__ float g_x2 [(size_t)BT*Cc];
__device__ float g_part[(size_t)Bc*Hc*8*Tc];
__device__ float g_imp[BT];
__device__ float g_wat [(size_t)3*Cc*Cc];
__device__ float g_wpt [(size_t)Cc*Cc];
__device__ float g_wft [(size_t)4*Cc*Cc];
__device__ float g_wf2t[(size_t)Cc*4*Cc];

// ---------------- helpers ----------------
__device__ __forceinline__ uint32_t smem_u32(const void* p) {
    uint32_t r;
    asm("{ .reg .u64 t; cvta.to.shared.u64 t, %1; cvt.u32.u64 %0, t; }"
        : "=r"(r) : "l"(p));
    return r;
}
__device__ __forceinline__ void ldsm4(uint32_t& r0, uint32_t& r1, uint32_t& r2, uint32_t& r3, uint32_t a) {
    asm volatile("ldmatrix.sync.aligned.m8n8.x4.shared.b16 {%0,%1,%2,%3},[%4];"
        : "=r"(r0), "=r"(r1), "=r"(r2), "=r"(r3) : "r"(a));
}
__device__ __forceinline__ void mma_tf32(float* c, uint32_t a0, uint32_t a1, uint32_t a2, uint32_t a3,
                                         uint32_t b0, uint32_t b1) {
    asm volatile("mma.sync.aligned.m16n8k8.row.col.f32.tf32.tf32.f32 "
        "{%0,%1,%2,%3},{%4,%5,%6,%7},{%8,%9},{%0,%1,%2,%3};"
        : "+f"(c[0]), "+f"(c[1]), "+f"(c[2]), "+f"(c[3])
        : "r"(a0), "r"(a1), "r"(a2), "r"(a3), "r"(b0), "r"(b1));
}
__device__ __forceinline__ uint32_t f2tf(float f) {
    uint32_t u;
    asm("cvt.rna.tf32.f32 %0, %1;" : "=r"(u) : "f"(f));
    return u;
}
__device__ __forceinline__ float rnd(float f) { return __uint_as_float(f2tf(f)); }
__device__ __forceinline__ void cp16(uint32_t s, const void* g) {
    asm volatile("cp.async.cg.shared.global [%0], [%1], 16;" :: "r"(s), "l"(g));
}
#define CP_COMMIT() asm volatile("cp.async.commit_group;")
#define CP_WAIT2()  asm volatile("cp.async.wait_group 2;")

// ---------------- weight transpose (tf32-rounded) ----------------
__global__ void __launch_bounds__(256) tr_kernel(const float* __restrict__ W,
                                                 float* __restrict__ Wt, int K, int N) {
    __shared__ float ts[32][33];
    int k0 = blockIdx.y * 32, n0 = blockIdx.x * 32;
    int tx = threadIdx.x & 31, ty = threadIdx.x >> 5;
    #pragma unroll
    for (int i = 0; i < 4; i++) {
        ts[ty + i*8][tx] = W[(size_t)(k0 + ty + i*8) * N + n0 + tx];
    }
    __syncthreads();
    #pragma unroll
    for (int i = 0; i < 4; i++) {
        Wt[(size_t)(n0 + ty + i*8) * K + k0 + tx] = rnd(ts[tx][ty + i*8]);
    }
}

// ---------------- LayerNorm (tf32-rounded out) ----------------
__global__ void __launch_bounds__(256) ln_kernel(const float* __restrict__ x,
                                                 const float* __restrict__ w,
                                                 const float* __restrict__ b,
                                                 float* __restrict__ out) {
    int row = blockIdx.x;
    int tid = threadIdx.x;
    const float* xr = x + (size_t)row * Cc;
    float4 v = *(const float4*)(xr + tid * 4);
    float s  = v.x + v.y + v.z + v.w;
    float s2 = v.x*v.x + v.y*v.y + v.z*v.z + v.w*v.w;
    #pragma unroll
    for (int o = 16; o; o >>= 1) {
        s  += __shfl_xor_sync(~0u, s,  o);
        s2 += __shfl_xor_sync(~0u, s2, o);
    }
    __shared__ float ws[8], ws2[8];
    int wid = tid >> 5, lid = tid & 31;
    if (lid == 0) { ws[wid] = s; ws2[wid] = s2; }
    __syncthreads();
    if (tid < 8) {
        float a = ws[tid], a2 = ws2[tid];
        #pragma unroll
        for (int o = 4; o; o >>= 1) {
            a  += __shfl_xor_sync(0xffu, a,  o);
            a2 += __shfl_xor_sync(0xffu, a2, o);
        }
        if (tid == 0) { ws[0] = a; ws2[0] = a2; }
    }
    __syncthreads();
    float mean = ws[0] * (1.0f / Cc);
    float var  = ws2[0] * (1.0f / Cc) - mean * mean;
    float inv  = rsqrtf(var + 1e-5f);
    int c = tid * 4;
    float4 wv = *(const float4*)(w + c);
    float4 bv = *(const float4*)(b + c);
    float4 ov;
    ov.x = rnd((v.x - mean) * inv * wv.x + bv.x);
    ov.y = rnd((v.y - mean) * inv * wv.y + bv.y);
    ov.z = rnd((v.z - mean) * inv * wv.z + bv.z);
    ov.w = rnd((v.w - mean) * inv * wv.w + bv.w);
    *(float4*)(out + (size_t)row * Cc + c) = ov;
}

// ---------------- tf32 MMA GEMM, cp.async 4-stage, occupancy 2 ----------------
#define GSTAGES 4
#define GSMEM_BYTES (GSTAGES * 2 * 128 * 20 * 4)
template<int EPI>
__global__ void __launch_bounds__(256, 2) mma_gemm(
    const float* __restrict__ A, const float* __restrict__ Bt,
    const float* __restrict__ bias, const float* __restrict__ res,
    float* __restrict__ outF, float* __restrict__ outQ,
    float* __restrict__ outK, float* __restrict__ outVt,
    int M, int N, int K)
{
    extern __shared__ float dsm[];
    typedef float (*Tile)[128][20];
    Tile As = (Tile)dsm;
    Tile Bs = (Tile)(dsm + GSTAGES * 128 * 20);

    int tid = threadIdx.x, lane = tid & 31, wid = tid >> 5;
    int wm = wid & 3, wn = wid >> 2;
    int bm = blockIdx.y * 128, bn = blockIdx.x * 128;

    float acc[2][8][4];
    #pragma unroll
    for (int i = 0; i < 2; i++) {
        #pragma unroll
        for (int j = 0; j < 8; j++) {
            #pragma unroll
            for (int k = 0; k < 4; k++) { acc[i][j][k] = 0.f; }
        }
    }

    int row = tid >> 1, kc = (tid & 1) * 8;
    const float* Ap = A  + (size_t)(bm + row) * K + kc;
    const float* Bp = Bt + (size_t)(bn + row) * K + kc;

    #pragma unroll
    for (int s = 0; s < GSTAGES - 1; s++) {
        int k0 = s * 16;
        cp16(smem_u32(&As[s][row][kc]),     Ap + k0);
        cp16(smem_u32(&As[s][row][kc + 4]), Ap + k0 + 4);
        cp16(smem_u32(&Bs[s][row][kc]),     Bp + k0);
        cp16(smem_u32(&Bs[s][row][kc + 4]), Bp + k0 + 4);
        CP_COMMIT();
    }

    int nk = K >> 4;
    for (int it = 0; it < nk; it++) {
        CP_WAIT2();
        __syncthreads();
        int st = it & (GSTAGES - 1);
        int nx = it + GSTAGES - 1;
        if (nx < nk) {
            int sx = nx & (GSTAGES - 1);
            int k0 = nx << 4;
            cp16(smem_u32(&As[sx][row][kc]),     Ap + k0);
            cp16(smem_u32(&As[sx][row][kc + 4]), Ap + k0 + 4);
            cp16(smem_u32(&Bs[sx][row][kc]),     Bp + k0);
            cp16(smem_u32(&Bs[sx][row][kc + 4]), Bp + k0 + 4);
        }
        CP_COMMIT();
        #pragma unroll
        for (int kk = 0; kk < 16; kk += 8) {
            uint32_t af[2][4];
            #pragma unroll
            for (int mt = 0; mt < 2; mt++) {
                ldsm4(af[mt][0], af[mt][1], af[mt][2], af[mt][3],
                      smem_u32(&As[st][wm*32 + mt*16 + (lane & 15)][kk + (lane >> 4) * 4]));
            }
            uint32_t bfr[8][2];
            #pragma unroll
            for (int np = 0; np < 4; np++) {
                uint32_t r0, r1, r2, r3;
                ldsm4(r0, r1, r2, r3,
                      smem_u32(&Bs[st][wn*64 + np*16 + (lane & 15)][kk + (lane >> 4) * 4]));
                bfr[np*2][0] = r0;   bfr[np*2][1] = r2;
                bfr[np*2+1][0] = r1; bfr[np*2+1][1] = r3;
            }
            #pragma unroll
            for (int mt = 0; mt < 2; mt++) {
                #pragma unroll
                for (int nt = 0; nt < 8; nt++) {
                    mma_tf32(acc[mt][nt], af[mt][0], af[mt][1], af[mt][2], af[mt][3],
                             bfr[nt][0], bfr[nt][1]);
                }
            }
        }
    }

    #pragma unroll
    for (int mt = 0; mt < 2; mt++) {
        #pragma unroll
        for (int nt = 0; nt < 8; nt++) {
            int r0 = bm + wm*32 + mt*16 + (lane >> 2);
            int c0 = bn + wn*64 + nt*8 + (lane & 3) * 2;
            float bb0 = bias[c0], bb1 = bias[c0 + 1];
            #pragma unroll
            for (int rr = 0; rr < 2; rr++) {
                int rg = r0 + rr * 8;
                float v0 = acc[mt][nt][rr*2 + 0] + bb0;
                float v1 = acc[mt][nt][rr*2 + 1] + bb1;
                if (EPI == 1) {
                    int sec = c0 >> 10, wc = c0 & 1023;
                    int h = wc >> 6, d = wc & 63;
                    int bbi = rg >> 10, t = rg & 1023;
                    if (sec == 0) {
                        float2 o; o.x = rnd(v0); o.y = rnd(v1);
                        *(float2*)&outQ[(((size_t)(bbi*Hc + h))*Tc + t)*Dc + d] = o;
                    } else if (sec == 1) {
                        float2 o; o.x = rnd(v0); o.y = rnd(v1);
                        *(float2*)&outK[(((size_t)(bbi*Hc + h))*Tc + t)*Dc + d] = o;
                    } else {
                        size_t vb = (((size_t)(bbi*Hc + h))*Dc + d)*Tc + t;
                        outVt[vb] = rnd(v0);
                        outVt[vb + Tc] = rnd(v1);
                    }
                } else if (EPI == 2) {
                    size_t idx = (size_t)rg * N + c0;
                    float2 rv = *(const float2*)(res + idx);
                    float2 o; o.x = v0 + rv.x; o.y = v1 + rv.y;
                    *(float2*)(outF + idx) = o;
                } else {
                    float g0 = 0.5f * v0 * (1.0f + erff(v0 * 0.70710678118654752f));
                    float g1 = 0.5f * v1 * (1.0f + erff(v1 * 0.70710678118654752f));
                    float2 o; o.x = rnd(g0); o.y = rnd(g1);
                    *(float2*)&outF[(size_t)rg * N + c0] = o;
                }
            }
        }
    }
}

// ================ fused flash attention (two-pass, j-block=64, occupancy 2) ================
// smem floats: Qs[128][68] | Ks[64][68] | Ss[128][68] | Vs[64][68] | m/l/mn[128]x3 | red[256]
#define OFF_QS 0
#define OFF_KS 8704
#define OFF_SS 13056
#define OFF_VS 21760
#define OFF_M  26112
#define OFF_L  26240
#define OFF_MN 26368
#define OFF_RED 26496
#define ATT_SMEM_FLOATS 26752
#define ATT_SMEM_BYTES (ATT_SMEM_FLOATS * 4)

// S = Q(128xD) @ K(64xD)^T -> acc[mt 2][nt 4][4]; warp tile 32 rows x 32 cols
__device__ __forceinline__ void compute_S64(
    const float (*Qs)[68], const float (*Ks)[68],
    int wm, int wn, int lane, float acc[2][4][4])
{
    #pragma unroll
    for (int i = 0; i < 2; i++) {
        #pragma unroll
        for (int j = 0; j < 4; j++) {
            #pragma unroll
            for (int k = 0; k < 4; k++) { acc[i][j][k] = 0.f; }
        }
    }
    #pragma unroll
    for (int kk = 0; kk < 64; kk += 8) {
        uint32_t af[2][4];
        #pragma unroll
        for (int mt = 0; mt < 2; mt++) {
            ldsm4(af[mt][0], af[mt][1], af[mt][2], af[mt][3],
                  smem_u32(&Qs[wm*32 + mt*16 + (lane & 15)][kk + (lane >> 4) * 4]));
        }
        uint32_t bfr[4][2];
        #pragma unroll
        for (int np = 0; np < 2; np++) {
            uint32_t r0, r1, r2, r3;
            ldsm4(r0, r1, r2, r3,
                  smem_u32(&Ks[wn*32 + np*16 + (lane & 15)][kk + (lane >> 4) * 4]));
            bfr[np*2][0] = r0;   bfr[np*2][1] = r2;
            bfr[np*2+1][0] = r1; bfr[np*2+1][1] = r3;
        }
        #pragma unroll
        for (int mt = 0; mt < 2; mt++) {
            #pragma unroll
            for (int nt = 0; nt < 4; nt++) {
                mma_tf32(acc[mt][nt], af[mt][0], af[mt][1], af[mt][2], af[mt][3],
                         bfr[nt][0], bfr[nt][1]);
            }
        }
    }
}

__global__ void __launch_bounds__(256, 2) flash_kernel(const int* __restrict__ amask) {
    extern __shared__ float sm[];
    float (*Qs)[68] = (float(*)[68])(sm + OFF_QS);
    float (*Ks)[68] = (float(*)[68])(sm + OFF_KS);
    float (*Ss)[68] = (float(*)[68])(sm + OFF_SS);
    float (*Vs)[68] = (float(*)[68])(sm + OFF_VS);
    float* m_s  = sm + OFF_M;
    float* l_s  = sm + OFF_L;
    float* mn_s = sm + OFF_MN;
    float* red  = sm + OFF_RED;

    int bh = blockIdx.y, b = bh >> 4, h = bh & 15;
    int qblk = (int)(gridDim.x - 1 - blockIdx.x);   // heavy blocks first
    int i0 = qblk << 7;
    int tid = threadIdx.x, lane = tid & 31, wid = tid >> 5;
    int wm = wid & 3, wn = wid >> 2;

    // load Q block (128 x 64)
    {
        int row = tid >> 1, c0 = (tid & 1) * 32;
        const float* qp = g_q + ((size_t)bh*Tc + i0 + row)*Dc + c0;
        #pragma unroll
        for (int c4 = 0; c4 < 32; c4 += 4) {
            *(float4*)&Qs[row][c0 + c4] = *(const float4*)(qp + c4);
        }
    }
    if (tid < 128) { m_s[tid] = -3.0e38f; l_s[tid] = 0.f; }
    __syncthreads();

    int nj = (qblk + 1) * 2;    // 64-wide j-blocks
    float acc[2][4][4];

    // ---------- pass A: row max + sum ----------
    for (int jb = 0; jb < nj; jb++) {
        int j0 = jb << 6;
        {
            int rowk = tid >> 2, ck = (tid & 3) * 16;
            const float* kp = g_k + ((size_t)bh*Tc + j0 + rowk)*Dc + ck;
            #pragma unroll
            for (int c4 = 0; c4 < 16; c4 += 4) {
                *(float4*)&Ks[rowk][ck + c4] = *(const float4*)(kp + c4);
            }
        }
        __syncthreads();
        compute_S64(Qs, Ks, wm, wn, lane, acc);
        // scale + mask
        #pragma unroll
        for (int mt = 0; mt < 2; mt++) {
            #pragma unroll
            for (int nt = 0; nt < 4; nt++) {
                int c0 = j0 + wn*32 + nt*8 + (lane & 3) * 2;
                int am0 = amask[b*Tc + c0], am1 = amask[b*Tc + c0 + 1];
                #pragma unroll
                for (int rr = 0; rr < 2; rr++) {
                    int r = i0 + wm*32 + mt*16 + rr*8 + (lane >> 2);
                    float s0 = acc[mt][nt][rr*2 + 0] * 0.125f;
                    float s1 = acc[mt][nt][rr*2 + 1] * 0.125f;
                    acc[mt][nt][rr*2 + 0] = (c0     <= r && am0) ? s0 : -1e30f;
                    acc[mt][nt][rr*2 + 1] = (c0 + 1 <= r && am1) ? s1 : -1e30f;
                }
            }
        }
        // block row-max
        #pragma unroll
        for (int mt = 0; mt < 2; mt++) {
            #pragma unroll
            for (int rr = 0; rr < 2; rr++) {
                float bmx = -3.4e38f;
                #pragma unroll
                for (int nt = 0; nt < 4; nt++) {
                    bmx = fmaxf(bmx, fmaxf(acc[mt][nt][rr*2], acc[mt][nt][rr*2 + 1]));
                }
                bmx = fmaxf(bmx, __shfl_xor_sync(~0u, bmx, 1));
                bmx = fmaxf(bmx, __shfl_xor_sync(~0u, bmx, 2));
                if ((lane & 3) == 0) {
                    red[wn*128 + wm*32 + mt*16 + rr*8 + (lane >> 2)] = bmx;
                }
            }
        }
        __syncthreads();
        if (wn == 0 && (lane & 3) == 0) {
            #pragma unroll
            for (int mt = 0; mt < 2; mt++) {
                #pragma unroll
                for (int rr = 0; rr < 2; rr++) {
                    int rl = wm*32 + mt*16 + rr*8 + (lane >> 2);
                    mn_s[rl] = fmaxf(m_s[rl], fmaxf(red[rl], red[128 + rl]));
                }
            }
        }
        __syncthreads();
        // block row-sum of exp
        #pragma unroll
        for (int mt = 0; mt < 2; mt++) {
            #pragma unroll
            for (int rr = 0; rr < 2; rr++) {
                int rl = wm*32 + mt*16 + rr*8 + (lane >> 2);
                float mnew = mn_s[rl];
                float e = 0.f;
                #pragma unroll
                for (int nt = 0; nt < 4; nt++) {
                    e += __expf(acc[mt][nt][rr*2]     - mnew);
                    e += __expf(acc[mt][nt][rr*2 + 1] - mnew);
                }
                e += __shfl_xor_sync(~0u, e, 1);
                e += __shfl_xor_sync(~0u, e, 2);
                if ((lane & 3) == 0) { red[wn*128 + rl] = e; }
            }
        }
        __syncthreads();
        if (wn == 0 && (lane & 3) == 0) {
            #pragma unroll
            for (int mt = 0; mt < 2; mt++) {
                #pragma unroll
                for (int rr = 0; rr < 2; rr++) {
                    int rl = wm*32 + mt*16 + rr*8 + (lane >> 2);
                    float mnew = mn_s[rl];
                    l_s[rl] = l_s[rl] * __expf(m_s[rl] - mnew) + red[rl] + red[128 + rl];
                    m_s[rl] = mnew;
                }
            }
        }
        __syncthreads();
    }
    if (tid < 128) {
        float l = l_s[tid];
        l_s[tid] = (l > 0.f) ? (1.0f / l) : 0.f;
    }
    __syncthreads();

    float acco[8][4];
    #pragma unroll
    for (int j = 0; j < 8; j++) {
        #pragma unroll
        for (int k = 0; k < 4; k++) { acco[j][k] = 0.f; }
    }

    // ---------- pass B: P, colsum, O = P@V ----------
    for (int jb = 0; jb < nj; jb++) {
        int j0 = jb << 6;
        {
            int rowk = tid >> 2, ck = (tid & 3) * 16;
            const float* kp = g_k + ((size_t)bh*Tc + j0 + rowk)*Dc + ck;
            #pragma unroll
            for (int c4 = 0; c4 < 16; c4 += 4) {
                *(float4*)&Ks[rowk][ck + c4] = *(const float4*)(kp + c4);
            }
            int rowv = tid >> 2, cv = (tid & 3) * 16;
            const float* vp = g_vt + ((size_t)bh*Dc + rowv)*Tc + j0 + cv;
            #pragma unroll
            for (int c4 = 0; c4 < 16; c4 += 4) {
                *(float4*)&Vs[rowv][cv + c4] = *(const float4*)(vp + c4);
            }
        }
        __syncthreads();
        compute_S64(Qs, Ks, wm, wn, lane, acc);
        // P = exp(s - m) * invl -> Ss (tf32-rounded)
        #pragma unroll
        for (int mt = 0; mt < 2; mt++) {
            #pragma unroll
            for (int nt = 0; nt < 4; nt++) {
                int cl = wn*32 + nt*8 + (lane & 3) * 2;
                int c0 = j0 + cl;
                int am0 = amask[b*Tc + c0], am1 = amask[b*Tc + c0 + 1];
                #pragma unroll
                for (int rr = 0; rr < 2; rr++) {
                    int rl = wm*32 + mt*16 + rr*8 + (lane >> 2);
                    int r = i0 + rl;
                    float ml = m_s[rl], il = l_s[rl];
                    float s0 = acc[mt][nt][rr*2 + 0] * 0.125f;
                    float s1 = acc[mt][nt][rr*2 + 1] * 0.125f;
                    float p0 = (c0     <= r && am0) ? (__expf(s0 - ml) * il) : 0.f;
                    float p1 = (c0 + 1 <= r && am1) ? (__expf(s1 - ml) * il) : 0.f;
                    float2 pv; pv.x = rnd(p0); pv.y = rnd(p1);
                    *(float2*)&Ss[rl][cl] = pv;
                }
            }
        }
        __syncthreads();
        // exact colsum of P for this j-block (deterministic)
        if (tid < 64) {
            float s = 0.f;
            #pragma unroll 8
            for (int r = 0; r < 128; r++) { s += Ss[r][tid]; }
            g_part[((size_t)bh*8 + qblk)*Tc + j0 + tid] = s;
        }
        // O += P @ V
        #pragma unroll
        for (int kk = 0; kk < 64; kk += 8) {
            uint32_t af[4];
            ldsm4(af[0], af[1], af[2], af[3],
                  smem_u32(&Ss[wid*16 + (lane & 15)][kk + (lane >> 4) * 4]));
            uint32_t bfr[8][2];
            #pragma unroll
            for (int np = 0; np < 4; np++) {
                uint32_t r0, r1, r2, r3;
                ldsm4(r0, r1, r2, r3,
                      smem_u32(&Vs[np*16 + (lane & 15)][kk + (lane >> 4) * 4]));
                bfr[np*2][0] = r0;   bfr[np*2][1] = r2;
                bfr[np*2+1][0] = r1; bfr[np*2+1][1] = r3;
            }
            #pragma unroll
            for (int nt = 0; nt < 8; nt++) {
                mma_tf32(acco[nt], af[0], af[1], af[2], af[3], bfr[nt][0], bfr[nt][1]);
            }
        }
        __syncthreads();
    }

    // write y (tf32-rounded)
    #pragma unroll
    for (int nt = 0; nt < 8; nt++) {
        int q0 = i0 + wid*16 + (lane >> 2);
        int d0 = nt*8 + (lane & 3) * 2;
        #pragma unroll
        for (int rr = 0; rr < 2; rr++) {
            int q = q0 + rr * 8;
            float2 o; o.x = rnd(acco[nt][rr*2]); o.y = rnd(acco[nt][rr*2 + 1]);
            *(float2*)&g_y[(size_t)(b*Tc + q) * Cc + h*64 + d0] = o;
        }
    }
    // zero untouched colsum tail
    for (int c = i0 + 128 + tid; c < Tc; c += 256) {
        g_part[((size_t)bh*8 + qblk)*Tc + c] = 0.f;
    }
}

// ---------------- imp reduce ----------------
__global__ void __launch_bounds__(256) impreduce_kernel() {
    int gt = blockIdx.x * 256 + threadIdx.x;
    int b = gt >> 10, t = gt & 1023;
    float s = 0.f;
    const float* p = g_part + (size_t)b * 128 * Tc + t;
    for (int i = 0; i < 128; i++) { s += p[(size_t)i * Tc]; }
    float posn = (float)(Tc - t) / (float)Tc;
    g_imp[gt] = (s / (float)Hc) / (posn + 1e-8f);
}

__global__ void __launch_bounds__(1024) finalize_kernel(const int* __restrict__ amask,
                                                        const float* __restrict__ thrp,
                                                        float* __restrict__ outp) {
    int tid = threadIdx.x;
    float m = -3.4e38f;
    for (int i = tid; i < BT; i += 1024) { m = fmaxf(m, g_imp[i]); }
    __shared__ float red[32];
    #pragma unroll
    for (int o = 16; o; o >>= 1) { m = fmaxf(m, __shfl_xor_sync(~0u, m, o)); }
    if ((tid & 31) == 0) red[tid >> 5] = m;
    __syncthreads();
    if (tid < 32) {
        float v = red[tid];
        #pragma unroll
        for (int o = 16; o; o >>= 1) { v = fmaxf(v, __shfl_xor_sync(~0u, v, o)); }
        if (tid == 0) red[0] = v;
    }
    __syncthreads();
    float maxv = red[0];
    float thr = *thrp;
    float* maskp = outp + (size_t)BT * Cc;
    float* impp  = maskp + BT;
    for (int i = tid; i < BT; i += 1024) {
        int t = i & 1023;
        float iv = g_imp[i];
        if (t < SINKc) iv = maxv + 1.0f;
        float mk = (iv >= thr) ? 1.0f : 0.0f;
        if (t < SINKc) mk = 1.0f;
        if (amask[i] == 0) mk = 0.0f;
        maskp[i] = mk;
        impp[i]  = iv;
    }
}

// ---------------- launch ----------------
extern "C" void kernel_launch(void* const* d_in, const int* in_sizes, int n_in,
                              void* d_out, int out_size) {
    (void)in_sizes; (void)n_in; (void)out_size;
    const float* x      = (const float*)d_in[0];
    const int*   amask  = (const int*)  d_in[1];
    const float* W_attn = (const float*)d_in[2];
    const float* b_attn = (const float*)d_in[3];
    const float* W_proj = (const float*)d_in[4];
    const float* b_proj = (const float*)d_in[5];
    const float* ln1_w  = (const float*)d_in[6];
    const float* ln1_b  = (const float*)d_in[7];
    const float* ln2_w  = (const float*)d_in[8];
    const float* ln2_b  = (const float*)d_in[9];
    const float* W_fc   = (const float*)d_in[10];
    const float* b_fc   = (const float*)d_in[11];
    const float* W_fc2  = (const float*)d_in[12];
    const float* b_fc2  = (const float*)d_in[13];
    const float* thr    = (const float*)d_in[14];
    float* outp = (float*)d_out;

    float *ph, *pq, *pk, *pvt, *py, *pfc, *px2, *pwat, *pwpt, *pwft, *pwf2t;
    cudaGetSymbolAddress((void**)&ph,    g_h);
    cudaGetSymbolAddress((void**)&pq,    g_q);
    cudaGetSymbolAddress((void**)&pk,    g_k);
    cudaGetSymbolAddress((void**)&pvt,   g_vt);
    cudaGetSymbolAddress((void**)&py,    g_y);
    cudaGetSymbolAddress((void**)&pfc,   g_fc);
    cudaGetSymbolAddress((void**)&px2,   g_x2);
    cudaGetSymbolAddress((void**)&pwat,  g_wat);
    cudaGetSymbolAddress((void**)&pwpt,  g_wpt);
    cudaGetSymbolAddress((void**)&pwft,  g_wft);
    cudaGetSymbolAddress((void**)&pwf2t, g_wf2t);

    cudaFuncSetAttribute(mma_gemm<1>, cudaFuncAttributeMaxDynamicSharedMemorySize, GSMEM_BYTES);
    cudaFuncSetAttribute(mma_gemm<2>, cudaFuncAttributeMaxDynamicSharedMemorySize, GSMEM_BYTES);
    cudaFuncSetAttribute(mma_gemm<3>, cudaFuncAttributeMaxDynamicSharedMemorySize, GSMEM_BYTES);
    cudaFuncSetAttribute(flash_kernel, cudaFuncAttributeMaxDynamicSharedMemorySize, ATT_SMEM_BYTES);

    tr_kernel<<<dim3(3*Cc/32, Cc/32),   256>>>(W_attn, pwat,  Cc,   3*Cc);
    tr_kernel<<<dim3(Cc/32,   Cc/32),   256>>>(W_proj, pwpt,  Cc,   Cc);
    tr_kernel<<<dim3(4*Cc/32, Cc/32),   256>>>(W_fc,   pwft,  Cc,   4*Cc);
    tr_kernel<<<dim3(Cc/32,   4*Cc/32), 256>>>(W_fc2,  pwf2t, 4*Cc, Cc);

    ln_kernel<<<BT, 256>>>(x, ln1_w, ln1_b, ph);
    mma_gemm<1><<<dim3(3*Cc/128, BT/128), 256, GSMEM_BYTES>>>(ph, pwat, b_attn, nullptr,
                                                 nullptr, pq, pk, pvt, BT, 3*Cc, Cc);
    flash_kernel<<<dim3(Tc/128, Bc*Hc), 256, ATT_SMEM_BYTES>>>(amask);
    impreduce_kernel<<<16, 256>>>();
    mma_gemm<2><<<dim3(Cc/128, BT/128), 256, GSMEM_BYTES>>>(py, pwpt, b_proj, x,
                                               px2, nullptr, nullptr, nullptr, BT, Cc, Cc);
    ln_kernel<<<BT, 256>>>(px2, ln2_w, ln2_b, ph);
    mma_gemm<3><<<dim3(4*Cc/128, BT/128), 256, GSMEM_BYTES>>>(ph, pwft, b_fc, nullptr,
                                                 pfc, nullptr, nullptr, nullptr, BT, 4*Cc, Cc);
    mma_gemm<2><<<dim3(Cc/128, BT/128), 256, GSMEM_BYTES>>>(pfc, pwf2t, b_fc2, px2,
                                               outp, nullptr, nullptr, nullptr, BT, Cc, 4*Cc);
    finalize_kernel<<<1, 1024>>>(amask, thr, outp);
}

// round 12
// speedup vs baseline: 2.1425x; 1.7798x over previous
#include <cuda_runtime.h>
#include <cuda_fp16.h>
#include <cstdint>
#include <math.h>

#define Bc 4
#define Tc 1024
#define Cc 1024
#define Hc 16
#define Dc 64
#define BT (Bc*Tc)
#define SINKc 4

typedef __half h16;

// ---------------- scratch ----------------
__device__ h16   g_h  [(size_t)BT*Cc];
__device__ h16   g_q  [(size_t)BT*Cc];        // (B,H,T,D)
__device__ h16   g_k  [(size_t)BT*Cc];
__device__ h16   g_vt [(size_t)BT*Cc];        // (B,H,D,T)
__device__ h16   g_y  [(size_t)BT*Cc];        // (B,T,C)
__device__ h16   g_fc [(size_t)BT*4*Cc];
__device__ float g_x2 [(size_t)BT*Cc];
__device__ float g_part[(size_t)Bc*Hc*8*Tc];
__device__ float g_imp[BT];
__device__ h16   g_wat [(size_t)3*Cc*Cc];     // [N][K]
__device__ h16   g_wpt [(size_t)Cc*Cc];
__device__ h16   g_wft [(size_t)4*Cc*Cc];
__device__ h16   g_wf2t[(size_t)Cc*4*Cc];

// ---------------- helpers ----------------
__device__ __forceinline__ uint32_t smem_u32(const void* p) {
    uint32_t r;
    asm("{ .reg .u64 t; cvta.to.shared.u64 t, %1; cvt.u32.u64 %0, t; }"
        : "=r"(r) : "l"(p));
    return r;
}
__device__ __forceinline__ void ldsm4(uint32_t& r0, uint32_t& r1, uint32_t& r2, uint32_t& r3, uint32_t a) {
    asm volatile("ldmatrix.sync.aligned.m8n8.x4.shared.b16 {%0,%1,%2,%3},[%4];"
        : "=r"(r0), "=r"(r1), "=r"(r2), "=r"(r3) : "r"(a));
}
__device__ __forceinline__ void mma_f16(float* c, uint32_t a0, uint32_t a1, uint32_t a2, uint32_t a3,
                                        uint32_t b0, uint32_t b1) {
    asm volatile("mma.sync.aligned.m16n8k16.row.col.f32.f16.f16.f32 "
        "{%0,%1,%2,%3},{%4,%5,%6,%7},{%8,%9},{%0,%1,%2,%3};"
        : "+f"(c[0]), "+f"(c[1]), "+f"(c[2]), "+f"(c[3])
        : "r"(a0), "r"(a1), "r"(a2), "r"(a3), "r"(b0), "r"(b1));
}
__device__ __forceinline__ uint32_t f2h2(float a, float b) {
    __half2 h = __floats2half2_rn(a, b);
    uint32_t r;
    memcpy(&r, &h, 4);
    return r;
}
__device__ __forceinline__ void cp16(uint32_t s, const void* g) {
    asm volatile("cp.async.cg.shared.global [%0], [%1], 16;" :: "r"(s), "l"(g));
}
#define CP_COMMIT() asm volatile("cp.async.commit_group;")
#define CP_WAIT2()  asm volatile("cp.async.wait_group 2;")

// ---------------- weight transpose + fp16 convert: Wt[n][k] = W[k][n] ----------------
__global__ void __launch_bounds__(256) tr_kernel(const float* __restrict__ W,
                                                 h16* __restrict__ Wt, int K, int N) {
    __shared__ float ts[32][33];
    int k0 = blockIdx.y * 32, n0 = blockIdx.x * 32;
    int tx = threadIdx.x & 31, ty = threadIdx.x >> 5;
    #pragma unroll
    for (int i = 0; i < 4; i++) {
        ts[ty + i*8][tx] = W[(size_t)(k0 + ty + i*8) * N + n0 + tx];
    }
    __syncthreads();
    #pragma unroll
    for (int i = 0; i < 4; i++) {
        Wt[(size_t)(n0 + ty + i*8) * K + k0 + tx] = __float2half_rn(ts[tx][ty + i*8]);
    }
}

// ---------------- LayerNorm (fp32 in, fp16 out) ----------------
__global__ void __launch_bounds__(256) ln_kernel(const float* __restrict__ x,
                                                 const float* __restrict__ w,
                                                 const float* __restrict__ b,
                                                 h16* __restrict__ out) {
    int row = blockIdx.x;
    int tid = threadIdx.x;
    const float* xr = x + (size_t)row * Cc;
    float4 v = *(const float4*)(xr + tid * 4);
    float s  = v.x + v.y + v.z + v.w;
    float s2 = v.x*v.x + v.y*v.y + v.z*v.z + v.w*v.w;
    #pragma unroll
    for (int o = 16; o; o >>= 1) {
        s  += __shfl_xor_sync(~0u, s,  o);
        s2 += __shfl_xor_sync(~0u, s2, o);
    }
    __shared__ float ws[8], ws2[8];
    int wid = tid >> 5, lid = tid & 31;
    if (lid == 0) { ws[wid] = s; ws2[wid] = s2; }
    __syncthreads();
    if (tid < 8) {
        float a = ws[tid], a2 = ws2[tid];
        #pragma unroll
        for (int o = 4; o; o >>= 1) {
            a  += __shfl_xor_sync(0xffu, a,  o);
            a2 += __shfl_xor_sync(0xffu, a2, o);
        }
        if (tid == 0) { ws[0] = a; ws2[0] = a2; }
    }
    __syncthreads();
    float mean = ws[0] * (1.0f / Cc);
    float var  = ws2[0] * (1.0f / Cc) - mean * mean;
    float inv  = rsqrtf(var + 1e-5f);
    int c = tid * 4;
    float4 wv = *(const float4*)(w + c);
    float4 bv = *(const float4*)(b + c);
    uint2 pk;
    pk.x = f2h2((v.x - mean) * inv * wv.x + bv.x, (v.y - mean) * inv * wv.y + bv.y);
    pk.y = f2h2((v.z - mean) * inv * wv.z + bv.z, (v.w - mean) * inv * wv.w + bv.w);
    *(uint2*)(out + (size_t)row * Cc + c) = pk;
}

// ---------------- fp16 MMA GEMM 128x128x32, cp.async 4-stage, occ 2 ----------------
// A: [M][K] half.  Bt: [N][K] half.  EPI 1: qkv split; 2: +bias+res fp32; 3: gelu -> half
#define GSTAGES 4
#define GSMEM_BYTES (GSTAGES * 2 * 128 * 40 * 2)
template<int EPI>
__global__ void __launch_bounds__(256, 2) mma_gemm(
    const h16* __restrict__ A, const h16* __restrict__ Bt,
    const float* __restrict__ bias, const float* __restrict__ res,
    float* __restrict__ outF, h16* __restrict__ outQ,
    h16* __restrict__ outK, h16* __restrict__ outVt,
    h16* __restrict__ outH,
    int M, int N, int K)
{
    extern __shared__ h16 dsm[];
    typedef h16 (*Tile)[128][40];
    Tile As = (Tile)dsm;
    Tile Bs = (Tile)(dsm + (size_t)GSTAGES * 128 * 40);

    int tid = threadIdx.x, lane = tid & 31, wid = tid >> 5;
    int wm = wid & 3, wn = wid >> 2;
    int bm = blockIdx.y * 128, bn = blockIdx.x * 128;

    float acc[2][8][4];
    #pragma unroll
    for (int i = 0; i < 2; i++) {
        #pragma unroll
        for (int j = 0; j < 8; j++) {
            #pragma unroll
            for (int k = 0; k < 4; k++) { acc[i][j][k] = 0.f; }
        }
    }

    int row = tid >> 1, kc = (tid & 1) * 16;   // halves
    const h16* Ap = A  + (size_t)(bm + row) * K + kc;
    const h16* Bp = Bt + (size_t)(bn + row) * K + kc;

    #pragma unroll
    for (int s = 0; s < GSTAGES - 1; s++) {
        int k0 = s * 32;
        cp16(smem_u32(&As[s][row][kc]),     Ap + k0);
        cp16(smem_u32(&As[s][row][kc + 8]), Ap + k0 + 8);
        cp16(smem_u32(&Bs[s][row][kc]),     Bp + k0);
        cp16(smem_u32(&Bs[s][row][kc + 8]), Bp + k0 + 8);
        CP_COMMIT();
    }

    int nk = K >> 5;
    for (int it = 0; it < nk; it++) {
        CP_WAIT2();
        __syncthreads();
        int st = it & (GSTAGES - 1);
        int nx = it + GSTAGES - 1;
        if (nx < nk) {
            int sx = nx & (GSTAGES - 1);
            int k0 = nx << 5;
            cp16(smem_u32(&As[sx][row][kc]),     Ap + k0);
            cp16(smem_u32(&As[sx][row][kc + 8]), Ap + k0 + 8);
            cp16(smem_u32(&Bs[sx][row][kc]),     Bp + k0);
            cp16(smem_u32(&Bs[sx][row][kc + 8]), Bp + k0 + 8);
        }
        CP_COMMIT();
        #pragma unroll
        for (int kk = 0; kk < 32; kk += 16) {
            uint32_t af[2][4];
            #pragma unroll
            for (int mt = 0; mt < 2; mt++) {
                ldsm4(af[mt][0], af[mt][1], af[mt][2], af[mt][3],
                      smem_u32(&As[st][wm*32 + mt*16 + (lane & 15)][kk + (lane >> 4) * 8]));
            }
            uint32_t bfr[8][2];
            #pragma unroll
            for (int np = 0; np < 4; np++) {
                uint32_t r0, r1, r2, r3;
                ldsm4(r0, r1, r2, r3,
                      smem_u32(&Bs[st][wn*64 + np*16 + (lane & 15)][kk + (lane >> 4) * 8]));
                bfr[np*2][0] = r0;   bfr[np*2][1] = r2;
                bfr[np*2+1][0] = r1; bfr[np*2+1][1] = r3;
            }
            #pragma unroll
            for (int mt = 0; mt < 2; mt++) {
                #pragma unroll
                for (int nt = 0; nt < 8; nt++) {
                    mma_f16(acc[mt][nt], af[mt][0], af[mt][1], af[mt][2], af[mt][3],
                            bfr[nt][0], bfr[nt][1]);
                }
            }
        }
    }

    #pragma unroll
    for (int mt = 0; mt < 2; mt++) {
        #pragma unroll
        for (int nt = 0; nt < 8; nt++) {
            int r0 = bm + wm*32 + mt*16 + (lane >> 2);
            int c0 = bn + wn*64 + nt*8 + (lane & 3) * 2;
            float bb0 = bias[c0], bb1 = bias[c0 + 1];
            #pragma unroll
            for (int rr = 0; rr < 2; rr++) {
                int rg = r0 + rr * 8;
                float v0 = acc[mt][nt][rr*2 + 0] + bb0;
                float v1 = acc[mt][nt][rr*2 + 1] + bb1;
                if (EPI == 1) {
                    int sec = c0 >> 10, wc = c0 & 1023;
                    int h = wc >> 6, d = wc & 63;
                    int bbi = rg >> 10, t = rg & 1023;
                    if (sec == 0) {
                        *(uint32_t*)&outQ[(((size_t)(bbi*Hc + h))*Tc + t)*Dc + d] = f2h2(v0, v1);
                    } else if (sec == 1) {
                        *(uint32_t*)&outK[(((size_t)(bbi*Hc + h))*Tc + t)*Dc + d] = f2h2(v0, v1);
                    } else {
                        size_t vb = (((size_t)(bbi*Hc + h))*Dc + d)*Tc + t;
                        outVt[vb] = __float2half_rn(v0);
                        outVt[vb + Tc] = __float2half_rn(v1);
                    }
                } else if (EPI == 2) {
                    size_t idx = (size_t)rg * N + c0;
                    float2 rv = *(const float2*)(res + idx);
                    float2 o; o.x = v0 + rv.x; o.y = v1 + rv.y;
                    *(float2*)(outF + idx) = o;
                } else {
                    float g0 = 0.5f * v0 * (1.0f + erff(v0 * 0.70710678118654752f));
                    float g1 = 0.5f * v1 * (1.0f + erff(v1 * 0.70710678118654752f));
                    *(uint32_t*)&outH[(size_t)rg * N + c0] = f2h2(g0, g1);
                }
            }
        }
    }
}

// ================ fused flash attention (fp16, two-pass, j-block=64, occ 2) ================
// smem bytes: Qs[128][72]h | Ks[64][72]h | Ss[128][72]h | Vs[64][72]h | m/l/mn[128]f | red[256]f
#define OFFB_QS 0
#define OFFB_KS 18432
#define OFFB_SS 27648
#define OFFB_VS 46080
#define OFFB_M  55296
#define OFFB_L  55808
#define OFFB_MN 56320
#define OFFB_RED 56832
#define ATT_SMEM_BYTES 57856

// S = Q(128x64) @ K(64x64)^T; warp tile 32 rows x 32 cols; fp16 m16n8k16
__device__ __forceinline__ void compute_S64(
    const h16 (*Qs)[72], const h16 (*Ks)[72],
    int wm, int wn, int lane, float acc[2][4][4])
{
    #pragma unroll
    for (int i = 0; i < 2; i++) {
        #pragma unroll
        for (int j = 0; j < 4; j++) {
            #pragma unroll
            for (int k = 0; k < 4; k++) { acc[i][j][k] = 0.f; }
        }
    }
    #pragma unroll
    for (int kk = 0; kk < 64; kk += 16) {
        uint32_t af[2][4];
        #pragma unroll
        for (int mt = 0; mt < 2; mt++) {
            ldsm4(af[mt][0], af[mt][1], af[mt][2], af[mt][3],
                  smem_u32(&Qs[wm*32 + mt*16 + (lane & 15)][kk + (lane >> 4) * 8]));
        }
        uint32_t bfr[4][2];
        #pragma unroll
        for (int np = 0; np < 2; np++) {
            uint32_t r0, r1, r2, r3;
            ldsm4(r0, r1, r2, r3,
                  smem_u32(&Ks[wn*32 + np*16 + (lane & 15)][kk + (lane >> 4) * 8]));
            bfr[np*2][0] = r0;   bfr[np*2][1] = r2;
            bfr[np*2+1][0] = r1; bfr[np*2+1][1] = r3;
        }
        #pragma unroll
        for (int mt = 0; mt < 2; mt++) {
            #pragma unroll
            for (int nt = 0; nt < 4; nt++) {
                mma_f16(acc[mt][nt], af[mt][0], af[mt][1], af[mt][2], af[mt][3],
                        bfr[nt][0], bfr[nt][1]);
            }
        }
    }
}

__global__ void __launch_bounds__(256, 2) flash_kernel(const int* __restrict__ amask) {
    extern __shared__ char smc[];
    h16 (*Qs)[72] = (h16(*)[72])(smc + OFFB_QS);
    h16 (*Ks)[72] = (h16(*)[72])(smc + OFFB_KS);
    h16 (*Ss)[72] = (h16(*)[72])(smc + OFFB_SS);
    h16 (*Vs)[72] = (h16(*)[72])(smc + OFFB_VS);
    float* m_s  = (float*)(smc + OFFB_M);
    float* l_s  = (float*)(smc + OFFB_L);
    float* mn_s = (float*)(smc + OFFB_MN);
    float* red  = (float*)(smc + OFFB_RED);

    int bh = blockIdx.y, b = bh >> 4, h = bh & 15;
    int qblk = (int)(gridDim.x - 1 - blockIdx.x);   // heavy blocks first
    int i0 = qblk << 7;
    int tid = threadIdx.x, lane = tid & 31, wid = tid >> 5;
    int wm = wid & 3, wn = wid >> 2;

    // load Q block (128 x 64 halves)
    {
        int row = tid >> 1, c0 = (tid & 1) * 32;
        const h16* qp = g_q + ((size_t)bh*Tc + i0 + row)*Dc + c0;
        #pragma unroll
        for (int c8 = 0; c8 < 32; c8 += 8) {
            *(uint4*)&Qs[row][c0 + c8] = *(const uint4*)(qp + c8);
        }
    }
    if (tid < 128) { m_s[tid] = -3.0e38f; l_s[tid] = 0.f; }
    __syncthreads();

    int nj = (qblk + 1) * 2;
    float acc[2][4][4];

    // ---------- pass A: row max + sum ----------
    for (int jb = 0; jb < nj; jb++) {
        int j0 = jb << 6;
        {
            int rowk = tid >> 2, ck = (tid & 3) * 16;
            const h16* kp = g_k + ((size_t)bh*Tc + j0 + rowk)*Dc + ck;
            *(uint4*)&Ks[rowk][ck]     = *(const uint4*)(kp);
            *(uint4*)&Ks[rowk][ck + 8] = *(const uint4*)(kp + 8);
        }
        __syncthreads();
        compute_S64(Qs, Ks, wm, wn, lane, acc);
        #pragma unroll
        for (int mt = 0; mt < 2; mt++) {
            #pragma unroll
            for (int nt = 0; nt < 4; nt++) {
                int c0 = j0 + wn*32 + nt*8 + (lane & 3) * 2;
                int am0 = amask[b*Tc + c0], am1 = amask[b*Tc + c0 + 1];
                #pragma unroll
                for (int rr = 0; rr < 2; rr++) {
                    int r = i0 + wm*32 + mt*16 + rr*8 + (lane >> 2);
                    float s0 = acc[mt][nt][rr*2 + 0] * 0.125f;
                    float s1 = acc[mt][nt][rr*2 + 1] * 0.125f;
                    acc[mt][nt][rr*2 + 0] = (c0     <= r && am0) ? s0 : -1e30f;
                    acc[mt][nt][rr*2 + 1] = (c0 + 1 <= r && am1) ? s1 : -1e30f;
                }
            }
        }
        #pragma unroll
        for (int mt = 0; mt < 2; mt++) {
            #pragma unroll
            for (int rr = 0; rr < 2; rr++) {
                float bmx = -3.4e38f;
                #pragma unroll
                for (int nt = 0; nt < 4; nt++) {
                    bmx = fmaxf(bmx, fmaxf(acc[mt][nt][rr*2], acc[mt][nt][rr*2 + 1]));
                }
                bmx = fmaxf(bmx, __shfl_xor_sync(~0u, bmx, 1));
                bmx = fmaxf(bmx, __shfl_xor_sync(~0u, bmx, 2));
                if ((lane & 3) == 0) {
                    red[wn*128 + wm*32 + mt*16 + rr*8 + (lane >> 2)] = bmx;
                }
            }
        }
        __syncthreads();
        if (wn == 0 && (lane & 3) == 0) {
            #pragma unroll
            for (int mt = 0; mt < 2; mt++) {
                #pragma unroll
                for (int rr = 0; rr < 2; rr++) {
                    int rl = wm*32 + mt*16 + rr*8 + (lane >> 2);
                    mn_s[rl] = fmaxf(m_s[rl], fmaxf(red[rl], red[128 + rl]));
                }
            }
        }
        __syncthreads();
        #pragma unroll
        for (int mt = 0; mt < 2; mt++) {
            #pragma unroll
            for (int rr = 0; rr < 2; rr++) {
                int rl = wm*32 + mt*16 + rr*8 + (lane >> 2);
                float mnew = mn_s[rl];
                float e = 0.f;
                #pragma unroll
                for (int nt = 0; nt < 4; nt++) {
                    e += __expf(acc[mt][nt][rr*2]     - mnew);
                    e += __expf(acc[mt][nt][rr*2 + 1] - mnew);
                }
                e += __shfl_xor_sync(~0u, e, 1);
                e += __shfl_xor_sync(~0u, e, 2);
                if ((lane & 3) == 0) { red[wn*128 + rl] = e; }
            }
        }
        __syncthreads();
        if (wn == 0 && (lane & 3) == 0) {
            #pragma unroll
            for (int mt = 0; mt < 2; mt++) {
                #pragma unroll
                for (int rr = 0; rr < 2; rr++) {
                    int rl = wm*32 + mt*16 + rr*8 + (lane >> 2);
                    float mnew = mn_s[rl];
                    l_s[rl] = l_s[rl] * __expf(m_s[rl] - mnew) + red[rl] + red[128 + rl];
                    m_s[rl] = mnew;
                }
            }
        }
        __syncthreads();
    }
    if (tid < 128) {
        float l = l_s[tid];
        l_s[tid] = (l > 0.f) ? (1.0f / l) : 0.f;
    }
    __syncthreads();

    float acco[8][4];
    #pragma unroll
    for (int j = 0; j < 8; j++) {
        #pragma unroll
        for (int k = 0; k < 4; k++) { acco[j][k] = 0.f; }
    }

    // ---------- pass B: P, colsum, O = P@V ----------
    for (int jb = 0; jb < nj; jb++) {
        int j0 = jb << 6;
        {
            int rowk = tid >> 2, ck = (tid & 3) * 16;
            const h16* kp = g_k + ((size_t)bh*Tc + j0 + rowk)*Dc + ck;
            *(uint4*)&Ks[rowk][ck]     = *(const uint4*)(kp);
            *(uint4*)&Ks[rowk][ck + 8] = *(const uint4*)(kp + 8);
            const h16* vp = g_vt + ((size_t)bh*Dc + rowk)*Tc + j0 + ck;
            *(uint4*)&Vs[rowk][ck]     = *(const uint4*)(vp);
            *(uint4*)&Vs[rowk][ck + 8] = *(const uint4*)(vp + 8);
        }
        __syncthreads();
        compute_S64(Qs, Ks, wm, wn, lane, acc);
        #pragma unroll
        for (int mt = 0; mt < 2; mt++) {
            #pragma unroll
            for (int nt = 0; nt < 4; nt++) {
                int cl = wn*32 + nt*8 + (lane & 3) * 2;
                int c0 = j0 + cl;
                int am0 = amask[b*Tc + c0], am1 = amask[b*Tc + c0 + 1];
                #pragma unroll
                for (int rr = 0; rr < 2; rr++) {
                    int rl = wm*32 + mt*16 + rr*8 + (lane >> 2);
                    int r = i0 + rl;
                    float ml = m_s[rl], il = l_s[rl];
                    float s0 = acc[mt][nt][rr*2 + 0] * 0.125f;
                    float s1 = acc[mt][nt][rr*2 + 1] * 0.125f;
                    float p0 = (c0     <= r && am0) ? (__expf(s0 - ml) * il) : 0.f;
                    float p1 = (c0 + 1 <= r && am1) ? (__expf(s1 - ml) * il) : 0.f;
                    *(uint32_t*)&Ss[rl][cl] = f2h2(p0, p1);
                }
            }
        }
        __syncthreads();
        // exact colsum of P for this j-block (deterministic)
        if (tid < 64) {
            float s = 0.f;
            #pragma unroll 8
            for (int r = 0; r < 128; r++) { s += __half2float(Ss[r][tid]); }
            g_part[((size_t)bh*8 + qblk)*Tc + j0 + tid] = s;
        }
        // O += P @ V
        #pragma unroll
        for (int kk = 0; kk < 64; kk += 16) {
            uint32_t af[4];
            ldsm4(af[0], af[1], af[2], af[3],
                  smem_u32(&Ss[wid*16 + (lane & 15)][kk + (lane >> 4) * 8]));
            uint32_t bfr[8][2];
            #pragma unroll
            for (int np = 0; np < 4; np++) {
                uint32_t r0, r1, r2, r3;
                ldsm4(r0, r1, r2, r3,
                      smem_u32(&Vs[np*16 + (lane & 15)][kk + (lane >> 4) * 8]));
                bfr[np*2][0] = r0;   bfr[np*2][1] = r2;
                bfr[np*2+1][0] = r1; bfr[np*2+1][1] = r3;
            }
            #pragma unroll
            for (int nt = 0; nt < 8; nt++) {
                mma_f16(acco[nt], af[0], af[1], af[2], af[3], bfr[nt][0], bfr[nt][1]);
            }
        }
        __syncthreads();
    }

    // write y (fp16)
    #pragma unroll
    for (int nt = 0; nt < 8; nt++) {
        int q0 = i0 + wid*16 + (lane >> 2);
        int d0 = nt*8 + (lane & 3) * 2;
        #pragma unroll
        for (int rr = 0; rr < 2; rr++) {
            int q = q0 + rr * 8;
            *(uint32_t*)&g_y[(size_t)(b*Tc + q) * Cc + h*64 + d0] =
                f2h2(acco[nt][rr*2], acco[nt][rr*2 + 1]);
        }
    }
    for (int c = i0 + 128 + tid; c < Tc; c += 256) {
        g_part[((size_t)bh*8 + qblk)*Tc + c] = 0.f;
    }
}

// ---------------- imp reduce ----------------
__global__ void __launch_bounds__(256) impreduce_kernel() {
    int gt = blockIdx.x * 256 + threadIdx.x;
    int b = gt >> 10, t = gt & 1023;
    float s = 0.f;
    const float* p = g_part + (size_t)b * 128 * Tc + t;
    for (int i = 0; i < 128; i++) { s += p[(size_t)i * Tc]; }
    float posn = (float)(Tc - t) / (float)Tc;
    g_imp[gt] = (s / (float)Hc) / (posn + 1e-8f);
}

__global__ void __launch_bounds__(1024) finalize_kernel(const int* __restrict__ amask,
                                                        const float* __restrict__ thrp,
                                                        float* __restrict__ outp) {
    int tid = threadIdx.x;
    float m = -3.4e38f;
    for (int i = tid; i < BT; i += 1024) { m = fmaxf(m, g_imp[i]); }
    __shared__ float red[32];
    #pragma unroll
    for (int o = 16; o; o >>= 1) { m = fmaxf(m, __shfl_xor_sync(~0u, m, o)); }
    if ((tid & 31) == 0) red[tid >> 5] = m;
    __syncthreads();
    if (tid < 32) {
        float v = red[tid];
        #pragma unroll
        for (int o = 16; o; o >>= 1) { v = fmaxf(v, __shfl_xor_sync(~0u, v, o)); }
        if (tid == 0) red[0] = v;
    }
    __syncthreads();
    float maxv = red[0];
    float thr = *thrp;
    float* maskp = outp + (size_t)BT * Cc;
    float* impp  = maskp + BT;
    for (int i = tid; i < BT; i += 1024) {
        int t = i & 1023;
        float iv = g_imp[i];
        if (t < SINKc) iv = maxv + 1.0f;
        float mk = (iv >= thr) ? 1.0f : 0.0f;
        if (t < SINKc) mk = 1.0f;
        if (amask[i] == 0) mk = 0.0f;
        maskp[i] = mk;
        impp[i]  = iv;
    }
}

// ---------------- launch ----------------
extern "C" void kernel_launch(void* const* d_in, const int* in_sizes, int n_in,
                              void* d_out, int out_size) {
    (void)in_sizes; (void)n_in; (void)out_size;
    const float* x      = (const float*)d_in[0];
    const int*   amask  = (const int*)  d_in[1];
    const float* W_attn = (const float*)d_in[2];
    const float* b_attn = (const float*)d_in[3];
    const float* W_proj = (const float*)d_in[4];
    const float* b_proj = (const float*)d_in[5];
    const float* ln1_w  = (const float*)d_in[6];
    const float* ln1_b  = (const float*)d_in[7];
    const float* ln2_w  = (const float*)d_in[8];
    const float* ln2_b  = (const float*)d_in[9];
    const float* W_fc   = (const float*)d_in[10];
    const float* b_fc   = (const float*)d_in[11];
    const float* W_fc2  = (const float*)d_in[12];
    const float* b_fc2  = (const float*)d_in[13];
    const float* thr    = (const float*)d_in[14];
    float* outp = (float*)d_out;

    h16 *ph, *pq, *pk, *pvt, *py, *pfc, *pwat, *pwpt, *pwft, *pwf2t;
    float *px2;
    cudaGetSymbolAddress((void**)&ph,    g_h);
    cudaGetSymbolAddress((void**)&pq,    g_q);
    cudaGetSymbolAddress((void**)&pk,    g_k);
    cudaGetSymbolAddress((void**)&pvt,   g_vt);
    cudaGetSymbolAddress((void**)&py,    g_y);
    cudaGetSymbolAddress((void**)&pfc,   g_fc);
    cudaGetSymbolAddress((void**)&px2,   g_x2);
    cudaGetSymbolAddress((void**)&pwat,  g_wat);
    cudaGetSymbolAddress((void**)&pwpt,  g_wpt);
    cudaGetSymbolAddress((void**)&pwft,  g_wft);
    cudaGetSymbolAddress((void**)&pwf2t, g_wf2t);

    cudaFuncSetAttribute(mma_gemm<1>, cudaFuncAttributeMaxDynamicSharedMemorySize, GSMEM_BYTES);
    cudaFuncSetAttribute(mma_gemm<2>, cudaFuncAttributeMaxDynamicSharedMemorySize, GSMEM_BYTES);
    cudaFuncSetAttribute(mma_gemm<3>, cudaFuncAttributeMaxDynamicSharedMemorySize, GSMEM_BYTES);
    cudaFuncSetAttribute(flash_kernel, cudaFuncAttributeMaxDynamicSharedMemorySize, ATT_SMEM_BYTES);

    tr_kernel<<<dim3(3*Cc/32, Cc/32),   256>>>(W_attn, pwat,  Cc,   3*Cc);
    tr_kernel<<<dim3(Cc/32,   Cc/32),   256>>>(W_proj, pwpt,  Cc,   Cc);
    tr_kernel<<<dim3(4*Cc/32, Cc/32),   256>>>(W_fc,   pwft,  Cc,   4*Cc);
    tr_kernel<<<dim3(Cc/32,   4*Cc/32), 256>>>(W_fc2,  pwf2t, 4*Cc, Cc);

    ln_kernel<<<BT, 256>>>(x, ln1_w, ln1_b, ph);
    mma_gemm<1><<<dim3(3*Cc/128, BT/128), 256, GSMEM_BYTES>>>(ph, pwat, b_attn, nullptr,
                                                 nullptr, pq, pk, pvt, nullptr, BT, 3*Cc, Cc);
    flash_kernel<<<dim3(Tc/128, Bc*Hc), 256, ATT_SMEM_BYTES>>>(amask);
    impreduce_kernel<<<16, 256>>>();
    mma_gemm<2><<<dim3(Cc/128, BT/128), 256, GSMEM_BYTES>>>(py, pwpt, b_proj, x,
                                               px2, nullptr, nullptr, nullptr, nullptr, BT, Cc, Cc);
    ln_kernel<<<BT, 256>>>(px2, ln2_w, ln2_b, ph);
    mma_gemm<3><<<dim3(4*Cc/128, BT/128), 256, GSMEM_BYTES>>>(ph, pwft, b_fc, nullptr,
                                                 nullptr, nullptr, nullptr, nullptr, pfc, BT, 4*Cc, Cc);
    mma_gemm<2><<<dim3(Cc/128, BT/128), 256, GSMEM_BYTES>>>(pfc, pwf2t, b_fc2, px2,
                                               outp, nullptr, nullptr, nullptr, nullptr, BT, Cc, 4*Cc);
    finalize_kernel<<<1, 1024>>>(amask, thr, outp);
}

// round 13
// speedup vs baseline: 2.1644x; 1.0102x over previous
#include <cuda_runtime.h>
#include <cuda_fp16.h>
#include <cstdint>
#include <math.h>

#define Bc 4
#define Tc 1024
#define Cc 1024
#define Hc 16
#define Dc 64
#define BT (Bc*Tc)
#define SINKc 4

typedef __half h16;

// ---------------- scratch ----------------
__device__ h16   g_h  [(size_t)BT*Cc];
__device__ h16   g_q  [(size_t)BT*Cc];        // (B,H,T,D)
__device__ h16   g_k  [(size_t)BT*Cc];
__device__ h16   g_vt [(size_t)BT*Cc];        // (B,H,D,T)
__device__ h16   g_y  [(size_t)BT*Cc];        // (B,T,C)
__device__ h16   g_fc [(size_t)BT*4*Cc];
__device__ float g_x2 [(size_t)BT*Cc];
__device__ float g_part[(size_t)Bc*Hc*8*Tc];
__device__ float g_imp[BT];
__device__ h16   g_wat [(size_t)3*Cc*Cc];     // [N][K]
__device__ h16   g_wpt [(size_t)Cc*Cc];
__device__ h16   g_wft [(size_t)4*Cc*Cc];
__device__ h16   g_wf2t[(size_t)Cc*4*Cc];

// ---------------- helpers ----------------
__device__ __forceinline__ uint32_t smem_u32(const void* p) {
    uint32_t r;
    asm("{ .reg .u64 t; cvta.to.shared.u64 t, %1; cvt.u32.u64 %0, t; }"
        : "=r"(r) : "l"(p));
    return r;
}
__device__ __forceinline__ void ldsm4(uint32_t& r0, uint32_t& r1, uint32_t& r2, uint32_t& r3, uint32_t a) {
    asm volatile("ldmatrix.sync.aligned.m8n8.x4.shared.b16 {%0,%1,%2,%3},[%4];"
        : "=r"(r0), "=r"(r1), "=r"(r2), "=r"(r3) : "r"(a));
}
__device__ __forceinline__ void mma_f16(float* c, uint32_t a0, uint32_t a1, uint32_t a2, uint32_t a3,
                                        uint32_t b0, uint32_t b1) {
    asm volatile("mma.sync.aligned.m16n8k16.row.col.f32.f16.f16.f32 "
        "{%0,%1,%2,%3},{%4,%5,%6,%7},{%8,%9},{%0,%1,%2,%3};"
        : "+f"(c[0]), "+f"(c[1]), "+f"(c[2]), "+f"(c[3])
        : "r"(a0), "r"(a1), "r"(a2), "r"(a3), "r"(b0), "r"(b1));
}
__device__ __forceinline__ uint32_t f2h2(float a, float b) {
    __half2 h = __floats2half2_rn(a, b);
    uint32_t r;
    memcpy(&r, &h, 4);
    return r;
}
__device__ __forceinline__ void cp16(uint32_t s, const void* g) {
    asm volatile("cp.async.cg.shared.global [%0], [%1], 16;" :: "r"(s), "l"(g));
}
#define CP_COMMIT() asm volatile("cp.async.commit_group;")
#define CP_WAIT2()  asm volatile("cp.async.wait_group 2;")

// ---------------- fused weight transpose (all 4 weights, fp16 out) ----------------
__global__ void __launch_bounds__(256) trall_kernel(
    const float* __restrict__ W0, h16* __restrict__ T0,
    const float* __restrict__ W1, h16* __restrict__ T1,
    const float* __restrict__ W2, h16* __restrict__ T2,
    const float* __restrict__ W3, h16* __restrict__ T3)
{
    __shared__ float ts[32][33];
    int bidx = blockIdx.x;
    const float* W; h16* Wt; int K, N, gx, local;
    if (bidx < 3072)      { W = W0; Wt = T0; K = 1024; N = 3072; gx = 96;  local = bidx; }
    else if (bidx < 4096) { W = W1; Wt = T1; K = 1024; N = 1024; gx = 32;  local = bidx - 3072; }
    else if (bidx < 8192) { W = W2; Wt = T2; K = 1024; N = 4096; gx = 128; local = bidx - 4096; }
    else                  { W = W3; Wt = T3; K = 4096; N = 1024; gx = 32;  local = bidx - 8192; }
    int k0 = (local / gx) * 32, n0 = (local % gx) * 32;
    int tx = threadIdx.x & 31, ty = threadIdx.x >> 5;
    #pragma unroll
    for (int i = 0; i < 4; i++) {
        ts[ty + i*8][tx] = W[(size_t)(k0 + ty + i*8) * N + n0 + tx];
    }
    __syncthreads();
    #pragma unroll
    for (int i = 0; i < 4; i++) {
        Wt[(size_t)(n0 + ty + i*8) * K + k0 + tx] = __float2half_rn(ts[tx][ty + i*8]);
    }
}

// ---------------- LayerNorm (fp32 in, fp16 out) ----------------
__global__ void __launch_bounds__(256) ln_kernel(const float* __restrict__ x,
                                                 const float* __restrict__ w,
                                                 const float* __restrict__ b,
                                                 h16* __restrict__ out) {
    int row = blockIdx.x;
    int tid = threadIdx.x;
    const float* xr = x + (size_t)row * Cc;
    float4 v = *(const float4*)(xr + tid * 4);
    float s  = v.x + v.y + v.z + v.w;
    float s2 = v.x*v.x + v.y*v.y + v.z*v.z + v.w*v.w;
    #pragma unroll
    for (int o = 16; o; o >>= 1) {
        s  += __shfl_xor_sync(~0u, s,  o);
        s2 += __shfl_xor_sync(~0u, s2, o);
    }
    __shared__ float ws[8], ws2[8];
    int wid = tid >> 5, lid = tid & 31;
    if (lid == 0) { ws[wid] = s; ws2[wid] = s2; }
    __syncthreads();
    if (tid < 8) {
        float a = ws[tid], a2 = ws2[tid];
        #pragma unroll
        for (int o = 4; o; o >>= 1) {
            a  += __shfl_xor_sync(0xffu, a,  o);
            a2 += __shfl_xor_sync(0xffu, a2, o);
        }
        if (tid == 0) { ws[0] = a; ws2[0] = a2; }
    }
    __syncthreads();
    float mean = ws[0] * (1.0f / Cc);
    float var  = ws2[0] * (1.0f / Cc) - mean * mean;
    float inv  = rsqrtf(var + 1e-5f);
    int c = tid * 4;
    float4 wv = *(const float4*)(w + c);
    float4 bv = *(const float4*)(b + c);
    uint2 pk;
    pk.x = f2h2((v.x - mean) * inv * wv.x + bv.x, (v.y - mean) * inv * wv.y + bv.y);
    pk.y = f2h2((v.z - mean) * inv * wv.z + bv.z, (v.w - mean) * inv * wv.w + bv.w);
    *(uint2*)(out + (size_t)row * Cc + c) = pk;
}

// ---------------- fp16 MMA GEMM 128x128x32, cp.async 4-stage, occ 2 ----------------
#define GSTAGES 4
#define GSMEM_BYTES (GSTAGES * 2 * 128 * 40 * 2)
template<int EPI>
__global__ void __launch_bounds__(256, 2) mma_gemm(
    const h16* __restrict__ A, const h16* __restrict__ Bt,
    const float* __restrict__ bias, const float* __restrict__ res,
    float* __restrict__ outF, h16* __restrict__ outQ,
    h16* __restrict__ outK, h16* __restrict__ outVt,
    h16* __restrict__ outH,
    int M, int N, int K)
{
    extern __shared__ h16 dsm[];
    typedef h16 (*Tile)[128][40];
    Tile As = (Tile)dsm;
    Tile Bs = (Tile)(dsm + (size_t)GSTAGES * 128 * 40);

    int tid = threadIdx.x, lane = tid & 31, wid = tid >> 5;
    int wm = wid & 3, wn = wid >> 2;
    int bm = blockIdx.y * 128, bn = blockIdx.x * 128;

    float acc[2][8][4];
    #pragma unroll
    for (int i = 0; i < 2; i++) {
        #pragma unroll
        for (int j = 0; j < 8; j++) {
            #pragma unroll
            for (int k = 0; k < 4; k++) { acc[i][j][k] = 0.f; }
        }
    }

    int row = tid >> 1, kc = (tid & 1) * 16;
    const h16* Ap = A  + (size_t)(bm + row) * K + kc;
    const h16* Bp = Bt + (size_t)(bn + row) * K + kc;

    #pragma unroll
    for (int s = 0; s < GSTAGES - 1; s++) {
        int k0 = s * 32;
        cp16(smem_u32(&As[s][row][kc]),     Ap + k0);
        cp16(smem_u32(&As[s][row][kc + 8]), Ap + k0 + 8);
        cp16(smem_u32(&Bs[s][row][kc]),     Bp + k0);
        cp16(smem_u32(&Bs[s][row][kc + 8]), Bp + k0 + 8);
        CP_COMMIT();
    }

    int nk = K >> 5;
    for (int it = 0; it < nk; it++) {
        CP_WAIT2();
        __syncthreads();
        int st = it & (GSTAGES - 1);
        int nx = it + GSTAGES - 1;
        if (nx < nk) {
            int sx = nx & (GSTAGES - 1);
            int k0 = nx << 5;
            cp16(smem_u32(&As[sx][row][kc]),     Ap + k0);
            cp16(smem_u32(&As[sx][row][kc + 8]), Ap + k0 + 8);
            cp16(smem_u32(&Bs[sx][row][kc]),     Bp + k0);
            cp16(smem_u32(&Bs[sx][row][kc + 8]), Bp + k0 + 8);
        }
        CP_COMMIT();
        #pragma unroll
        for (int kk = 0; kk < 32; kk += 16) {
            uint32_t af[2][4];
            #pragma unroll
            for (int mt = 0; mt < 2; mt++) {
                ldsm4(af[mt][0], af[mt][1], af[mt][2], af[mt][3],
                      smem_u32(&As[st][wm*32 + mt*16 + (lane & 15)][kk + (lane >> 4) * 8]));
            }
            uint32_t bfr[8][2];
            #pragma unroll
            for (int np = 0; np < 4; np++) {
                uint32_t r0, r1, r2, r3;
                ldsm4(r0, r1, r2, r3,
                      smem_u32(&Bs[st][wn*64 + np*16 + (lane & 15)][kk + (lane >> 4) * 8]));
                bfr[np*2][0] = r0;   bfr[np*2][1] = r2;
                bfr[np*2+1][0] = r1; bfr[np*2+1][1] = r3;
            }
            #pragma unroll
            for (int mt = 0; mt < 2; mt++) {
                #pragma unroll
                for (int nt = 0; nt < 8; nt++) {
                    mma_f16(acc[mt][nt], af[mt][0], af[mt][1], af[mt][2], af[mt][3],
                            bfr[nt][0], bfr[nt][1]);
                }
            }
        }
    }

    #pragma unroll
    for (int mt = 0; mt < 2; mt++) {
        #pragma unroll
        for (int nt = 0; nt < 8; nt++) {
            int r0 = bm + wm*32 + mt*16 + (lane >> 2);
            int c0 = bn + wn*64 + nt*8 + (lane & 3) * 2;
            float bb0 = bias[c0], bb1 = bias[c0 + 1];
            #pragma unroll
            for (int rr = 0; rr < 2; rr++) {
                int rg = r0 + rr * 8;
                float v0 = acc[mt][nt][rr*2 + 0] + bb0;
                float v1 = acc[mt][nt][rr*2 + 1] + bb1;
                if (EPI == 1) {
                    int sec = c0 >> 10, wc = c0 & 1023;
                    int h = wc >> 6, d = wc & 63;
                    int bbi = rg >> 10, t = rg & 1023;
                    if (sec == 0) {
                        *(uint32_t*)&outQ[(((size_t)(bbi*Hc + h))*Tc + t)*Dc + d] = f2h2(v0, v1);
                    } else if (sec == 1) {
                        *(uint32_t*)&outK[(((size_t)(bbi*Hc + h))*Tc + t)*Dc + d] = f2h2(v0, v1);
                    } else {
                        size_t vb = (((size_t)(bbi*Hc + h))*Dc + d)*Tc + t;
                        outVt[vb] = __float2half_rn(v0);
                        outVt[vb + Tc] = __float2half_rn(v1);
                    }
                } else if (EPI == 2) {
                    size_t idx = (size_t)rg * N + c0;
                    float2 rv = *(const float2*)(res + idx);
                    float2 o; o.x = v0 + rv.x; o.y = v1 + rv.y;
                    *(float2*)(outF + idx) = o;
                } else {
                    float g0 = 0.5f * v0 * (1.0f + erff(v0 * 0.70710678118654752f));
                    float g1 = 0.5f * v1 * (1.0f + erff(v1 * 0.70710678118654752f));
                    *(uint32_t*)&outH[(size_t)rg * N + c0] = f2h2(g0, g1);
                }
            }
        }
    }
}

// ================ fused flash attention (fp16, two-pass, NO MAX, j=64, occ 2) ================
#define OFFB_QS 0
#define OFFB_KS 18432
#define OFFB_SS 27648
#define OFFB_VS 46080
#define OFFB_L  55296
#define OFFB_RED 55808
#define ATT_SMEM_BYTES 56832

__device__ __forceinline__ void compute_S64(
    const h16 (*Qs)[72], const h16 (*Ks)[72],
    int wm, int wn, int lane, float acc[2][4][4])
{
    #pragma unroll
    for (int i = 0; i < 2; i++) {
        #pragma unroll
        for (int j = 0; j < 4; j++) {
            #pragma unroll
            for (int k = 0; k < 4; k++) { acc[i][j][k] = 0.f; }
        }
    }
    #pragma unroll
    for (int kk = 0; kk < 64; kk += 16) {
        uint32_t af[2][4];
        #pragma unroll
        for (int mt = 0; mt < 2; mt++) {
            ldsm4(af[mt][0], af[mt][1], af[mt][2], af[mt][3],
                  smem_u32(&Qs[wm*32 + mt*16 + (lane & 15)][kk + (lane >> 4) * 8]));
        }
        uint32_t bfr[4][2];
        #pragma unroll
        for (int np = 0; np < 2; np++) {
            uint32_t r0, r1, r2, r3;
            ldsm4(r0, r1, r2, r3,
                  smem_u32(&Ks[wn*32 + np*16 + (lane & 15)][kk + (lane >> 4) * 8]));
            bfr[np*2][0] = r0;   bfr[np*2][1] = r2;
            bfr[np*2+1][0] = r1; bfr[np*2+1][1] = r3;
        }
        #pragma unroll
        for (int mt = 0; mt < 2; mt++) {
            #pragma unroll
            for (int nt = 0; nt < 4; nt++) {
                mma_f16(acc[mt][nt], af[mt][0], af[mt][1], af[mt][2], af[mt][3],
                        bfr[nt][0], bfr[nt][1]);
            }
        }
    }
}

__global__ void __launch_bounds__(256, 2) flash_kernel(const int* __restrict__ amask) {
    extern __shared__ char smc[];
    h16 (*Qs)[72] = (h16(*)[72])(smc + OFFB_QS);
    h16 (*Ks)[72] = (h16(*)[72])(smc + OFFB_KS);
    h16 (*Ss)[72] = (h16(*)[72])(smc + OFFB_SS);
    h16 (*Vs)[72] = (h16(*)[72])(smc + OFFB_VS);
    float* l_s = (float*)(smc + OFFB_L);
    float* red = (float*)(smc + OFFB_RED);

    int bh = blockIdx.y, b = bh >> 4, h = bh & 15;
    int qblk = (int)(gridDim.x - 1 - blockIdx.x);
    int i0 = qblk << 7;
    int tid = threadIdx.x, lane = tid & 31, wid = tid >> 5;
    int wm = wid & 3, wn = wid >> 2;

    {
        int row = tid >> 1, c0 = (tid & 1) * 32;
        const h16* qp = g_q + ((size_t)bh*Tc + i0 + row)*Dc + c0;
        #pragma unroll
        for (int c8 = 0; c8 < 32; c8 += 8) {
            *(uint4*)&Qs[row][c0 + c8] = *(const uint4*)(qp + c8);
        }
    }
    if (tid < 128) { l_s[tid] = 0.f; }
    __syncthreads();

    int nj = (qblk + 1) * 2;
    float acc[2][4][4];

    // ---------- pass A (lean, no max): l = sum exp(s/8) ----------
    for (int jb = 0; jb < nj; jb++) {
        int j0 = jb << 6;
        {
            int rowk = tid >> 2, ck = (tid & 3) * 16;
            const h16* kp = g_k + ((size_t)bh*Tc + j0 + rowk)*Dc + ck;
            *(uint4*)&Ks[rowk][ck]     = *(const uint4*)(kp);
            *(uint4*)&Ks[rowk][ck + 8] = *(const uint4*)(kp + 8);
        }
        __syncthreads();      // K visible; also orders prior red-read before red-write below
        compute_S64(Qs, Ks, wm, wn, lane, acc);
        #pragma unroll
        for (int mt = 0; mt < 2; mt++) {
            #pragma unroll
            for (int rr = 0; rr < 2; rr++) {
                float e = 0.f;
                #pragma unroll
                for (int nt = 0; nt < 4; nt++) {
                    int c0 = j0 + wn*32 + nt*8 + (lane & 3) * 2;
                    int r = i0 + wm*32 + mt*16 + rr*8 + (lane >> 2);
                    int am0 = amask[b*Tc + c0], am1 = amask[b*Tc + c0 + 1];
                    if (c0     <= r && am0) { e += __expf(acc[mt][nt][rr*2 + 0] * 0.125f); }
                    if (c0 + 1 <= r && am1) { e += __expf(acc[mt][nt][rr*2 + 1] * 0.125f); }
                }
                e += __shfl_xor_sync(~0u, e, 1);
                e += __shfl_xor_sync(~0u, e, 2);
                if ((lane & 3) == 0) {
                    red[wn*128 + wm*32 + mt*16 + rr*8 + (lane >> 2)] = e;
                }
            }
        }
        __syncthreads();
        if (wn == 0 && (lane & 3) == 0) {
            #pragma unroll
            for (int mt = 0; mt < 2; mt++) {
                #pragma unroll
                for (int rr = 0; rr < 2; rr++) {
                    int rl = wm*32 + mt*16 + rr*8 + (lane >> 2);
                    l_s[rl] += red[rl] + red[128 + rl];
                }
            }
        }
        // next iteration's first sync orders this read before red overwrite
    }
    __syncthreads();
    if (tid < 128) {
        float l = l_s[tid];
        l_s[tid] = (l > 0.f) ? (1.0f / l) : 0.f;
    }
    __syncthreads();

    float acco[8][4];
    #pragma unroll
    for (int j = 0; j < 8; j++) {
        #pragma unroll
        for (int k = 0; k < 4; k++) { acco[j][k] = 0.f; }
    }

    // ---------- pass B: P = exp(s/8)*invl, colsum, O = P@V ----------
    for (int jb = 0; jb < nj; jb++) {
        int j0 = jb << 6;
        {
            int rowk = tid >> 2, ck = (tid & 3) * 16;
            const h16* kp = g_k + ((size_t)bh*Tc + j0 + rowk)*Dc + ck;
            *(uint4*)&Ks[rowk][ck]     = *(const uint4*)(kp);
            *(uint4*)&Ks[rowk][ck + 8] = *(const uint4*)(kp + 8);
            const h16* vp = g_vt + ((size_t)bh*Dc + rowk)*Tc + j0 + ck;
            *(uint4*)&Vs[rowk][ck]     = *(const uint4*)(vp);
            *(uint4*)&Vs[rowk][ck + 8] = *(const uint4*)(vp + 8);
        }
        __syncthreads();
        compute_S64(Qs, Ks, wm, wn, lane, acc);
        #pragma unroll
        for (int mt = 0; mt < 2; mt++) {
            #pragma unroll
            for (int nt = 0; nt < 4; nt++) {
                int cl = wn*32 + nt*8 + (lane & 3) * 2;
                int c0 = j0 + cl;
                int am0 = amask[b*Tc + c0], am1 = amask[b*Tc + c0 + 1];
                #pragma unroll
                for (int rr = 0; rr < 2; rr++) {
                    int rl = wm*32 + mt*16 + rr*8 + (lane >> 2);
                    int r = i0 + rl;
                    float il = l_s[rl];
                    float p0 = (c0     <= r && am0) ? (__expf(acc[mt][nt][rr*2 + 0] * 0.125f) * il) : 0.f;
                    float p1 = (c0 + 1 <= r && am1) ? (__expf(acc[mt][nt][rr*2 + 1] * 0.125f) * il) : 0.f;
                    *(uint32_t*)&Ss[rl][cl] = f2h2(p0, p1);
                }
            }
        }
        __syncthreads();
        if (tid < 64) {
            float s = 0.f;
            #pragma unroll 8
            for (int r = 0; r < 128; r++) { s += __half2float(Ss[r][tid]); }
            g_part[((size_t)bh*8 + qblk)*Tc + j0 + tid] = s;
        }
        #pragma unroll
        for (int kk = 0; kk < 64; kk += 16) {
            uint32_t af[4];
            ldsm4(af[0], af[1], af[2], af[3],
                  smem_u32(&Ss[wid*16 + (lane & 15)][kk + (lane >> 4) * 8]));
            uint32_t bfr[8][2];
            #pragma unroll
            for (int np = 0; np < 4; np++) {
                uint32_t r0, r1, r2, r3;
                ldsm4(r0, r1, r2, r3,
                      smem_u32(&Vs[np*16 + (lane & 15)][kk + (lane >> 4) * 8]));
                bfr[np*2][0] = r0;   bfr[np*2][1] = r2;
                bfr[np*2+1][0] = r1; bfr[np*2+1][1] = r3;
            }
            #pragma unroll
            for (int nt = 0; nt < 8; nt++) {
                mma_f16(acco[nt], af[0], af[1], af[2], af[3], bfr[nt][0], bfr[nt][1]);
            }
        }
        __syncthreads();
    }

    #pragma unroll
    for (int nt = 0; nt < 8; nt++) {
        int q0 = i0 + wid*16 + (lane >> 2);
        int d0 = nt*8 + (lane & 3) * 2;
        #pragma unroll
        for (int rr = 0; rr < 2; rr++) {
            int q = q0 + rr * 8;
            *(uint32_t*)&g_y[(size_t)(b*Tc + q) * Cc + h*64 + d0] =
                f2h2(acco[nt][rr*2], acco[nt][rr*2 + 1]);
        }
    }
    for (int c = i0 + 128 + tid; c < Tc; c += 256) {
        g_part[((size_t)bh*8 + qblk)*Tc + c] = 0.f;
    }
}

// ---------------- imp reduce ----------------
__global__ void __launch_bounds__(256) impreduce_kernel() {
    int gt = blockIdx.x * 256 + threadIdx.x;
    int b = gt >> 10, t = gt & 1023;
    float s = 0.f;
    const float* p = g_part + (size_t)b * 128 * Tc + t;
    for (int i = 0; i < 128; i++) { s += p[(size_t)i * Tc]; }
    float posn = (float)(Tc - t) / (float)Tc;
    g_imp[gt] = (s / (float)Hc) / (posn + 1e-8f);
}

__global__ void __launch_bounds__(1024) finalize_kernel(const int* __restrict__ amask,
                                                        const float* __restrict__ thrp,
                                                        float* __restrict__ outp) {
    int tid = threadIdx.x;
    float m = -3.4e38f;
    for (int i = tid; i < BT; i += 1024) { m = fmaxf(m, g_imp[i]); }
    __shared__ float red[32];
    #pragma unroll
    for (int o = 16; o; o >>= 1) { m = fmaxf(m, __shfl_xor_sync(~0u, m, o)); }
    if ((tid & 31) == 0) red[tid >> 5] = m;
    __syncthreads();
    if (tid < 32) {
        float v = red[tid];
        #pragma unroll
        for (int o = 16; o; o >>= 1) { v = fmaxf(v, __shfl_xor_sync(~0u, v, o)); }
        if (tid == 0) red[0] = v;
    }
    __syncthreads();
    float maxv = red[0];
    float thr = *thrp;
    float* maskp = outp + (size_t)BT * Cc;
    float* impp  = maskp + BT;
    for (int i = tid; i < BT; i += 1024) {
        int t = i & 1023;
        float iv = g_imp[i];
        if (t < SINKc) iv = maxv + 1.0f;
        float mk = (iv >= thr) ? 1.0f : 0.0f;
        if (t < SINKc) mk = 1.0f;
        if (amask[i] == 0) mk = 0.0f;
        maskp[i] = mk;
        impp[i]  = iv;
    }
}

// ---------------- launch ----------------
extern "C" void kernel_launch(void* const* d_in, const int* in_sizes, int n_in,
                              void* d_out, int out_size) {
    (void)in_sizes; (void)n_in; (void)out_size;
    const float* x      = (const float*)d_in[0];
    const int*   amask  = (const int*)  d_in[1];
    const float* W_attn = (const float*)d_in[2];
    const float* b_attn = (const float*)d_in[3];
    const float* W_proj = (const float*)d_in[4];
    const float* b_proj = (const float*)d_in[5];
    const float* ln1_w  = (const float*)d_in[6];
    const float* ln1_b  = (const float*)d_in[7];
    const float* ln2_w  = (const float*)d_in[8];
    const float* ln2_b  = (const float*)d_in[9];
    const float* W_fc   = (const float*)d_in[10];
    const float* b_fc   = (const float*)d_in[11];
    const float* W_fc2  = (const float*)d_in[12];
    const float* b_fc2  = (const float*)d_in[13];
    const float* thr    = (const float*)d_in[14];
    float* outp = (float*)d_out;

    h16 *ph, *pq, *pk, *pvt, *py, *pfc, *pwat, *pwpt, *pwft, *pwf2t;
    float *px2;
    cudaGetSymbolAddress((void**)&ph,    g_h);
    cudaGetSymbolAddress((void**)&pq,    g_q);
    cudaGetSymbolAddress((void**)&pk,    g_k);
    cudaGetSymbolAddress((void**)&pvt,   g_vt);
    cudaGetSymbolAddress((void**)&py,    g_y);
    cudaGetSymbolAddress((void**)&pfc,   g_fc);
    cudaGetSymbolAddress((void**)&px2,   g_x2);
    cudaGetSymbolAddress((void**)&pwat,  g_wat);
    cudaGetSymbolAddress((void**)&pwpt,  g_wpt);
    cudaGetSymbolAddress((void**)&pwft,  g_wft);
    cudaGetSymbolAddress((void**)&pwf2t, g_wf2t);

    cudaFuncSetAttribute(mma_gemm<1>, cudaFuncAttributeMaxDynamicSharedMemorySize, GSMEM_BYTES);
    cudaFuncSetAttribute(mma_gemm<2>, cudaFuncAttributeMaxDynamicSharedMemorySize, GSMEM_BYTES);
    cudaFuncSetAttribute(mma_gemm<3>, cudaFuncAttributeMaxDynamicSharedMemorySize, GSMEM_BYTES);
    cudaFuncSetAttribute(flash_kernel, cudaFuncAttributeMaxDynamicSharedMemorySize, ATT_SMEM_BYTES);

    trall_kernel<<<12288, 256>>>(W_attn, pwat, W_proj, pwpt, W_fc, pwft, W_fc2, pwf2t);

    ln_kernel<<<BT, 256>>>(x, ln1_w, ln1_b, ph);
    mma_gemm<1><<<dim3(3*Cc/128, BT/128), 256, GSMEM_BYTES>>>(ph, pwat, b_attn, nullptr,
                                                 nullptr, pq, pk, pvt, nullptr, BT, 3*Cc, Cc);
    flash_kernel<<<dim3(Tc/128, Bc*Hc), 256, ATT_SMEM_BYTES>>>(amask);
    impreduce_kernel<<<16, 256>>>();
    mma_gemm<2><<<dim3(Cc/128, BT/128), 256, GSMEM_BYTES>>>(py, pwpt, b_proj, x,
                                               px2, nullptr, nullptr, nullptr, nullptr, BT, Cc, Cc);
    ln_kernel<<<BT, 256>>>(px2, ln2_w, ln2_b, ph);
    mma_gemm<3><<<dim3(4*Cc/128, BT/128), 256, GSMEM_BYTES>>>(ph, pwft, b_fc, nullptr,
                                                 nullptr, nullptr, nullptr, nullptr, pfc, BT, 4*Cc, Cc);
    mma_gemm<2><<<dim3(Cc/128, BT/128), 256, GSMEM_BYTES>>>(pfc, pwf2t, b_fc2, px2,
                                               outp, nullptr, nullptr, nullptr, nullptr, BT, Cc, 4*Cc);
    finalize_kernel<<<1, 1024>>>(amask, thr, outp);
}

// round 14
// speedup vs baseline: 2.2484x; 1.0388x over previous
#include <cuda_runtime.h>
#include <cuda_fp16.h>
#include <cstdint>
#include <math.h>

#define Bc 4
#define Tc 1024
#define Cc 1024
#define Hc 16
#define Dc 64
#define BT (Bc*Tc)
#define SINKc 4

typedef __half h16;

// ---------------- scratch ----------------
__device__ h16   g_h  [(size_t)BT*Cc];
__device__ h16   g_q  [(size_t)BT*Cc];        // (B,H,T,D)
__device__ h16   g_k  [(size_t)BT*Cc];
__device__ h16   g_vt [(size_t)BT*Cc];        // (B,H,D,T)
__device__ h16   g_y  [(size_t)BT*Cc];        // (B,T,C)
__device__ h16   g_fc [(size_t)BT*4*Cc];
__device__ float g_x2 [(size_t)BT*Cc];
__device__ float g_part[(size_t)Bc*Hc*8*Tc];
__device__ float g_imp[BT];
__device__ h16   g_wat [(size_t)3*Cc*Cc];     // [N][K]
__device__ h16   g_wpt [(size_t)Cc*Cc];
__device__ h16   g_wft [(size_t)4*Cc*Cc];
__device__ h16   g_wf2t[(size_t)Cc*4*Cc];

// ---------------- helpers ----------------
__device__ __forceinline__ uint32_t smem_u32(const void* p) {
    uint32_t r;
    asm("{ .reg .u64 t; cvta.to.shared.u64 t, %1; cvt.u32.u64 %0, t; }"
        : "=r"(r) : "l"(p));
    return r;
}
__device__ __forceinline__ void ldsm4(uint32_t& r0, uint32_t& r1, uint32_t& r2, uint32_t& r3, uint32_t a) {
    asm volatile("ldmatrix.sync.aligned.m8n8.x4.shared.b16 {%0,%1,%2,%3},[%4];"
        : "=r"(r0), "=r"(r1), "=r"(r2), "=r"(r3) : "r"(a));
}
__device__ __forceinline__ void mma_f16(float* c, uint32_t a0, uint32_t a1, uint32_t a2, uint32_t a3,
                                        uint32_t b0, uint32_t b1) {
    asm volatile("mma.sync.aligned.m16n8k16.row.col.f32.f16.f16.f32 "
        "{%0,%1,%2,%3},{%4,%5,%6,%7},{%8,%9},{%0,%1,%2,%3};"
        : "+f"(c[0]), "+f"(c[1]), "+f"(c[2]), "+f"(c[3])
        : "r"(a0), "r"(a1), "r"(a2), "r"(a3), "r"(b0), "r"(b1));
}
__device__ __forceinline__ uint32_t f2h2(float a, float b) {
    __half2 h = __floats2half2_rn(a, b);
    uint32_t r;
    memcpy(&r, &h, 4);
    return r;
}
__device__ __forceinline__ void cp16(uint32_t s, const void* g) {
    asm volatile("cp.async.cg.shared.global [%0], [%1], 16;" :: "r"(s), "l"(g));
}
#define CP_COMMIT() asm volatile("cp.async.commit_group;")
#define CP_WAIT0()  asm volatile("cp.async.wait_group 0;" ::: "memory")
#define CP_WAIT2()  asm volatile("cp.async.wait_group 2;")

// ---------------- fused weight transpose ----------------
__global__ void __launch_bounds__(256) trall_kernel(
    const float* __restrict__ W0, h16* __restrict__ T0,
    const float* __restrict__ W1, h16* __restrict__ T1,
    const float* __restrict__ W2, h16* __restrict__ T2,
    const float* __restrict__ W3, h16* __restrict__ T3)
{
    __shared__ float ts[32][33];
    int bidx = blockIdx.x;
    const float* W; h16* Wt; int K, N, gx, local;
    if (bidx < 3072)      { W = W0; Wt = T0; K = 1024; N = 3072; gx = 96;  local = bidx; }
    else if (bidx < 4096) { W = W1; Wt = T1; K = 1024; N = 1024; gx = 32;  local = bidx - 3072; }
    else if (bidx < 8192) { W = W2; Wt = T2; K = 1024; N = 4096; gx = 128; local = bidx - 4096; }
    else                  { W = W3; Wt = T3; K = 4096; N = 1024; gx = 32;  local = bidx - 8192; }
    int k0 = (local / gx) * 32, n0 = (local % gx) * 32;
    int tx = threadIdx.x & 31, ty = threadIdx.x >> 5;
    #pragma unroll
    for (int i = 0; i < 4; i++) {
        ts[ty + i*8][tx] = W[(size_t)(k0 + ty + i*8) * N + n0 + tx];
    }
    __syncthreads();
    #pragma unroll
    for (int i = 0; i < 4; i++) {
        Wt[(size_t)(n0 + ty + i*8) * K + k0 + tx] = __float2half_rn(ts[tx][ty + i*8]);
    }
}

// ---------------- LayerNorm (fp32 in, fp16 out) ----------------
__global__ void __launch_bounds__(256) ln_kernel(const float* __restrict__ x,
                                                 const float* __restrict__ w,
                                                 const float* __restrict__ b,
                                                 h16* __restrict__ out) {
    int row = blockIdx.x;
    int tid = threadIdx.x;
    const float* xr = x + (size_t)row * Cc;
    float4 v = *(const float4*)(xr + tid * 4);
    float s  = v.x + v.y + v.z + v.w;
    float s2 = v.x*v.x + v.y*v.y + v.z*v.z + v.w*v.w;
    #pragma unroll
    for (int o = 16; o; o >>= 1) {
        s  += __shfl_xor_sync(~0u, s,  o);
        s2 += __shfl_xor_sync(~0u, s2, o);
    }
    __shared__ float ws[8], ws2[8];
    int wid = tid >> 5, lid = tid & 31;
    if (lid == 0) { ws[wid] = s; ws2[wid] = s2; }
    __syncthreads();
    if (tid < 8) {
        float a = ws[tid], a2 = ws2[tid];
        #pragma unroll
        for (int o = 4; o; o >>= 1) {
            a  += __shfl_xor_sync(0xffu, a,  o);
            a2 += __shfl_xor_sync(0xffu, a2, o);
        }
        if (tid == 0) { ws[0] = a; ws2[0] = a2; }
    }
    __syncthreads();
    float mean = ws[0] * (1.0f / Cc);
    float var  = ws2[0] * (1.0f / Cc) - mean * mean;
    float inv  = rsqrtf(var + 1e-5f);
    int c = tid * 4;
    float4 wv = *(const float4*)(w + c);
    float4 bv = *(const float4*)(b + c);
    uint2 pk;
    pk.x = f2h2((v.x - mean) * inv * wv.x + bv.x, (v.y - mean) * inv * wv.y + bv.y);
    pk.y = f2h2((v.z - mean) * inv * wv.z + bv.z, (v.w - mean) * inv * wv.w + bv.w);
    *(uint2*)(out + (size_t)row * Cc + c) = pk;
}

// ---------------- fp16 MMA GEMM 128x128x32, cp.async 4-stage, occ 2 ----------------
#define GSTAGES 4
#define GSMEM_BYTES (GSTAGES * 2 * 128 * 40 * 2)
template<int EPI>
__global__ void __launch_bounds__(256, 2) mma_gemm(
    const h16* __restrict__ A, const h16* __restrict__ Bt,
    const float* __restrict__ bias, const float* __restrict__ res,
    float* __restrict__ outF, h16* __restrict__ outQ,
    h16* __restrict__ outK, h16* __restrict__ outVt,
    h16* __restrict__ outH,
    int M, int N, int K)
{
    extern __shared__ h16 dsm[];
    typedef h16 (*Tile)[128][40];
    Tile As = (Tile)dsm;
    Tile Bs = (Tile)(dsm + (size_t)GSTAGES * 128 * 40);

    int tid = threadIdx.x, lane = tid & 31, wid = tid >> 5;
    int wm = wid & 3, wn = wid >> 2;
    int bm = blockIdx.y * 128, bn = blockIdx.x * 128;

    float acc[2][8][4];
    #pragma unroll
    for (int i = 0; i < 2; i++) {
        #pragma unroll
        for (int j = 0; j < 8; j++) {
            #pragma unroll
            for (int k = 0; k < 4; k++) { acc[i][j][k] = 0.f; }
        }
    }

    int row = tid >> 1, kc = (tid & 1) * 16;
    const h16* Ap = A  + (size_t)(bm + row) * K + kc;
    const h16* Bp = Bt + (size_t)(bn + row) * K + kc;

    #pragma unroll
    for (int s = 0; s < GSTAGES - 1; s++) {
        int k0 = s * 32;
        cp16(smem_u32(&As[s][row][kc]),     Ap + k0);
        cp16(smem_u32(&As[s][row][kc + 8]), Ap + k0 + 8);
        cp16(smem_u32(&Bs[s][row][kc]),     Bp + k0);
        cp16(smem_u32(&Bs[s][row][kc + 8]), Bp + k0 + 8);
        CP_COMMIT();
    }

    int nk = K >> 5;
    for (int it = 0; it < nk; it++) {
        CP_WAIT2();
        __syncthreads();
        int st = it & (GSTAGES - 1);
        int nx = it + GSTAGES - 1;
        if (nx < nk) {
            int sx = nx & (GSTAGES - 1);
            int k0 = nx << 5;
            cp16(smem_u32(&As[sx][row][kc]),     Ap + k0);
            cp16(smem_u32(&As[sx][row][kc + 8]), Ap + k0 + 8);
            cp16(smem_u32(&Bs[sx][row][kc]),     Bp + k0);
            cp16(smem_u32(&Bs[sx][row][kc + 8]), Bp + k0 + 8);
        }
        CP_COMMIT();
        #pragma unroll
        for (int kk = 0; kk < 32; kk += 16) {
            uint32_t af[2][4];
            #pragma unroll
            for (int mt = 0; mt < 2; mt++) {
                ldsm4(af[mt][0], af[mt][1], af[mt][2], af[mt][3],
                      smem_u32(&As[st][wm*32 + mt*16 + (lane & 15)][kk + (lane >> 4) * 8]));
            }
            uint32_t bfr[8][2];
            #pragma unroll
            for (int np = 0; np < 4; np++) {
                uint32_t r0, r1, r2, r3;
                ldsm4(r0, r1, r2, r3,
                      smem_u32(&Bs[st][wn*64 + np*16 + (lane & 15)][kk + (lane >> 4) * 8]));
                bfr[np*2][0] = r0;   bfr[np*2][1] = r2;
                bfr[np*2+1][0] = r1; bfr[np*2+1][1] = r3;
            }
            #pragma unroll
            for (int mt = 0; mt < 2; mt++) {
                #pragma unroll
                for (int nt = 0; nt < 8; nt++) {
                    mma_f16(acc[mt][nt], af[mt][0], af[mt][1], af[mt][2], af[mt][3],
                            bfr[nt][0], bfr[nt][1]);
                }
            }
        }
    }

    #pragma unroll
    for (int mt = 0; mt < 2; mt++) {
        #pragma unroll
        for (int nt = 0; nt < 8; nt++) {
            int r0 = bm + wm*32 + mt*16 + (lane >> 2);
            int c0 = bn + wn*64 + nt*8 + (lane & 3) * 2;
            float bb0 = bias[c0], bb1 = bias[c0 + 1];
            #pragma unroll
            for (int rr = 0; rr < 2; rr++) {
                int rg = r0 + rr * 8;
                float v0 = acc[mt][nt][rr*2 + 0] + bb0;
                float v1 = acc[mt][nt][rr*2 + 1] + bb1;
                if (EPI == 1) {
                    int sec = c0 >> 10, wc = c0 & 1023;
                    int h = wc >> 6, d = wc & 63;
                    int bbi = rg >> 10, t = rg & 1023;
                    if (sec == 0) {
                        *(uint32_t*)&outQ[(((size_t)(bbi*Hc + h))*Tc + t)*Dc + d] = f2h2(v0, v1);
                    } else if (sec == 1) {
                        *(uint32_t*)&outK[(((size_t)(bbi*Hc + h))*Tc + t)*Dc + d] = f2h2(v0, v1);
                    } else {
                        size_t vb = (((size_t)(bbi*Hc + h))*Dc + d)*Tc + t;
                        outVt[vb] = __float2half_rn(v0);
                        outVt[vb + Tc] = __float2half_rn(v1);
                    }
                } else if (EPI == 2) {
                    size_t idx = (size_t)rg * N + c0;
                    float2 rv = *(const float2*)(res + idx);
                    float2 o; o.x = v0 + rv.x; o.y = v1 + rv.y;
                    *(float2*)(outF + idx) = o;
                } else {
                    float g0 = 0.5f * v0 * (1.0f + erff(v0 * 0.70710678118654752f));
                    float g1 = 0.5f * v1 * (1.0f + erff(v1 * 0.70710678118654752f));
                    *(uint32_t*)&outH[(size_t)rg * N + c0] = f2h2(g0, g1);
                }
            }
        }
    }
}

// ================ flash attention: warp-private rows (16x64/warp), cp.async, no max ================
// smem bytes: Qs[128][72] | Ks[2][64][72] | Vs[2][64][72] | Ss[128][72]
#define OFFB_QS 0
#define OFFB_KS 18432
#define OFFB_VS 36864
#define OFFB_SS 55296
#define ATT_SMEM_BYTES 73728

// S-tile: warp computes 16 rows x 64 cols; acc[8][4]
__device__ __forceinline__ void compute_S_w(
    const h16 (*Qs)[72], const h16 (*Ks)[72],
    int wid, int lane, float acc[8][4])
{
    #pragma unroll
    for (int j = 0; j < 8; j++) {
        #pragma unroll
        for (int k = 0; k < 4; k++) { acc[j][k] = 0.f; }
    }
    #pragma unroll
    for (int kk = 0; kk < 64; kk += 16) {
        uint32_t af[4];
        ldsm4(af[0], af[1], af[2], af[3],
              smem_u32(&Qs[wid*16 + (lane & 15)][kk + (lane >> 4) * 8]));
        uint32_t bfr[8][2];
        #pragma unroll
        for (int np = 0; np < 4; np++) {
            uint32_t r0, r1, r2, r3;
            ldsm4(r0, r1, r2, r3,
                  smem_u32(&Ks[np*16 + (lane & 15)][kk + (lane >> 4) * 8]));
            bfr[np*2][0] = r0;   bfr[np*2][1] = r2;
            bfr[np*2+1][0] = r1; bfr[np*2+1][1] = r3;
        }
        #pragma unroll
        for (int nt = 0; nt < 8; nt++) {
            mma_f16(acc[nt], af[0], af[1], af[2], af[3], bfr[nt][0], bfr[nt][1]);
        }
    }
}

__global__ void __launch_bounds__(256, 2) flash_kernel(const int* __restrict__ amask) {
    extern __shared__ char smc[];
    h16 (*Qs)[72] = (h16(*)[72])(smc + OFFB_QS);
    h16 (*Ks)[2][64][72] = (h16(*)[2][64][72])(smc + OFFB_KS);  // indexed (*Ks)[buf]
    h16 (*Vs)[2][64][72] = (h16(*)[2][64][72])(smc + OFFB_VS);
    h16 (*Ss)[72] = (h16(*)[72])(smc + OFFB_SS);

    int bh = blockIdx.y, b = bh >> 4, h = bh & 15;
    int qblk = (int)(gridDim.x - 1 - blockIdx.x);
    int i0 = qblk << 7;
    int tid = threadIdx.x, lane = tid & 31, wid = tid >> 5;
    int rowk = tid >> 2, ck = (tid & 3) * 16;
    const h16* kbase = g_k  + ((size_t)bh*Tc) * Dc;
    const h16* vbase = g_vt + ((size_t)bh*Dc) * Tc;

    // load Q block
    {
        int row = tid >> 1, c0 = (tid & 1) * 32;
        const h16* qp = g_q + ((size_t)bh*Tc + i0 + row)*Dc + c0;
        #pragma unroll
        for (int c8 = 0; c8 < 32; c8 += 8) {
            *(uint4*)&Qs[row][c0 + c8] = *(const uint4*)(qp + c8);
        }
    }

    int nj = (qblk + 1) * 2;
    float acc[8][4];
    float l0 = 0.f, l1 = 0.f;
    int ra = i0 + wid*16 + (lane >> 2);
    int rb = ra + 8;

    // ---------- pass A: l = sum exp(s/8); K double-buffered cp.async ----------
    {
        const h16* kp = kbase + (size_t)rowk * Dc + ck;
        cp16(smem_u32(&(*Ks)[0][rowk][ck]),     kp);
        cp16(smem_u32(&(*Ks)[0][rowk][ck + 8]), kp + 8);
        CP_COMMIT();
    }
    for (int jb = 0; jb < nj; jb++) {
        int j0 = jb << 6;
        CP_WAIT0();
        __syncthreads();          // K[jb] visible; prior iter fully done by all warps
        if (jb + 1 < nj) {
            const h16* kp = kbase + (size_t)(j0 + 64 + rowk) * Dc + ck;
            int bf = (jb + 1) & 1;
            cp16(smem_u32(&(*Ks)[bf][rowk][ck]),     kp);
            cp16(smem_u32(&(*Ks)[bf][rowk][ck + 8]), kp + 8);
        }
        CP_COMMIT();
        compute_S_w(Qs, (*Ks)[jb & 1], wid, lane, acc);
        float e0 = 0.f, e1 = 0.f;
        #pragma unroll
        for (int nt = 0; nt < 8; nt++) {
            int c0 = j0 + nt*8 + (lane & 3) * 2;
            int am0 = amask[b*Tc + c0], am1 = amask[b*Tc + c0 + 1];
            if (c0     <= ra && am0) { e0 += __expf(acc[nt][0] * 0.125f); }
            if (c0 + 1 <= ra && am1) { e0 += __expf(acc[nt][1] * 0.125f); }
            if (c0     <= rb && am0) { e1 += __expf(acc[nt][2] * 0.125f); }
            if (c0 + 1 <= rb && am1) { e1 += __expf(acc[nt][3] * 0.125f); }
        }
        e0 += __shfl_xor_sync(~0u, e0, 1);
        e0 += __shfl_xor_sync(~0u, e0, 2);
        e1 += __shfl_xor_sync(~0u, e1, 1);
        e1 += __shfl_xor_sync(~0u, e1, 2);
        l0 += e0;
        l1 += e1;
    }
    float il0 = (l0 > 0.f) ? (1.0f / l0) : 0.f;
    float il1 = (l1 > 0.f) ? (1.0f / l1) : 0.f;

    float acco[8][4];
    #pragma unroll
    for (int j = 0; j < 8; j++) {
        #pragma unroll
        for (int k = 0; k < 4; k++) { acco[j][k] = 0.f; }
    }

    // ---------- pass B: P = exp(s/8)*invl -> Ss; colsum; O += P@V ----------
    __syncthreads();              // pass A reads of Ks complete everywhere
    {
        const h16* kp = kbase + (size_t)rowk * Dc + ck;
        cp16(smem_u32(&(*Ks)[0][rowk][ck]),     kp);
        cp16(smem_u32(&(*Ks)[0][rowk][ck + 8]), kp + 8);
        const h16* vp = vbase + (size_t)rowk * Tc + ck;
        cp16(smem_u32(&(*Vs)[0][rowk][ck]),     vp);
        cp16(smem_u32(&(*Vs)[0][rowk][ck + 8]), vp + 8);
        CP_COMMIT();
    }
    for (int jb = 0; jb < nj; jb++) {
        int j0 = jb << 6;
        CP_WAIT0();
        __syncthreads();          // K/V[jb] visible; all warps done with prior Ss reads
        if (jb + 1 < nj) {
            int bf = (jb + 1) & 1;
            const h16* kp = kbase + (size_t)(j0 + 64 + rowk) * Dc + ck;
            cp16(smem_u32(&(*Ks)[bf][rowk][ck]),     kp);
            cp16(smem_u32(&(*Ks)[bf][rowk][ck + 8]), kp + 8);
            const h16* vp = vbase + (size_t)rowk * Tc + j0 + 64 + ck;
            cp16(smem_u32(&(*Vs)[bf][rowk][ck]),     vp);
            cp16(smem_u32(&(*Vs)[bf][rowk][ck + 8]), vp + 8);
        }
        CP_COMMIT();
        compute_S_w(Qs, (*Ks)[jb & 1], wid, lane, acc);
        #pragma unroll
        for (int nt = 0; nt < 8; nt++) {
            int cl = nt*8 + (lane & 3) * 2;
            int c0 = j0 + cl;
            int am0 = amask[b*Tc + c0], am1 = amask[b*Tc + c0 + 1];
            float p0 = (c0     <= ra && am0) ? (__expf(acc[nt][0] * 0.125f) * il0) : 0.f;
            float p1 = (c0 + 1 <= ra && am1) ? (__expf(acc[nt][1] * 0.125f) * il0) : 0.f;
            float p2 = (c0     <= rb && am0) ? (__expf(acc[nt][2] * 0.125f) * il1) : 0.f;
            float p3 = (c0 + 1 <= rb && am1) ? (__expf(acc[nt][3] * 0.125f) * il1) : 0.f;
            *(uint32_t*)&Ss[wid*16 + (lane >> 2)][cl]     = f2h2(p0, p1);
            *(uint32_t*)&Ss[wid*16 + (lane >> 2) + 8][cl] = f2h2(p2, p3);
        }
        __syncthreads();          // Ss visible for colsum + PV
        if (tid < 64) {
            float s = 0.f;
            #pragma unroll 8
            for (int r = 0; r < 128; r++) { s += __half2float(Ss[r][tid]); }
            g_part[((size_t)bh*8 + qblk)*Tc + j0 + tid] = s;
        }
        #pragma unroll
        for (int kk = 0; kk < 64; kk += 16) {
            uint32_t af[4];
            ldsm4(af[0], af[1], af[2], af[3],
                  smem_u32(&Ss[wid*16 + (lane & 15)][kk + (lane >> 4) * 8]));
            uint32_t bfr[8][2];
            #pragma unroll
            for (int np = 0; np < 4; np++) {
                uint32_t r0, r1, r2, r3;
                ldsm4(r0, r1, r2, r3,
                      smem_u32(&(*Vs)[jb & 1][np*16 + (lane & 15)][kk + (lane >> 4) * 8]));
                bfr[np*2][0] = r0;   bfr[np*2][1] = r2;
                bfr[np*2+1][0] = r1; bfr[np*2+1][1] = r3;
            }
            #pragma unroll
            for (int nt = 0; nt < 8; nt++) {
                mma_f16(acco[nt], af[0], af[1], af[2], af[3], bfr[nt][0], bfr[nt][1]);
            }
        }
    }

    #pragma unroll
    for (int nt = 0; nt < 8; nt++) {
        int q0 = i0 + wid*16 + (lane >> 2);
        int d0 = nt*8 + (lane & 3) * 2;
        #pragma unroll
        for (int rr = 0; rr < 2; rr++) {
            int q = q0 + rr * 8;
            *(uint32_t*)&g_y[(size_t)(b*Tc + q) * Cc + h*64 + d0] =
                f2h2(acco[nt][rr*2], acco[nt][rr*2 + 1]);
        }
    }
    for (int c = i0 + 128 + tid; c < Tc; c += 256) {
        g_part[((size_t)bh*8 + qblk)*Tc + c] = 0.f;
    }
}

// ---------------- imp reduce ----------------
__global__ void __launch_bounds__(256) impreduce_kernel() {
    int gt = blockIdx.x * 256 + threadIdx.x;
    int b = gt >> 10, t = gt & 1023;
    float s = 0.f;
    const float* p = g_part + (size_t)b * 128 * Tc + t;
    for (int i = 0; i < 128; i++) { s += p[(size_t)i * Tc]; }
    float posn = (float)(Tc - t) / (float)Tc;
    g_imp[gt] = (s / (float)Hc) / (posn + 1e-8f);
}

__global__ void __launch_bounds__(1024) finalize_kernel(const int* __restrict__ amask,
                                                        const float* __restrict__ thrp,
                                                        float* __restrict__ outp) {
    int tid = threadIdx.x;
    float m = -3.4e38f;
    for (int i = tid; i < BT; i += 1024) { m = fmaxf(m, g_imp[i]); }
    __shared__ float red[32];
    #pragma unroll
    for (int o = 16; o; o >>= 1) { m = fmaxf(m, __shfl_xor_sync(~0u, m, o)); }
    if ((tid & 31) == 0) red[tid >> 5] = m;
    __syncthreads();
    if (tid < 32) {
        float v = red[tid];
        #pragma unroll
        for (int o = 16; o; o >>= 1) { v = fmaxf(v, __shfl_xor_sync(~0u, v, o)); }
        if (tid == 0) red[0] = v;
    }
    __syncthreads();
    float maxv = red[0];
    float thr = *thrp;
    float* maskp = outp + (size_t)BT * Cc;
    float* impp  = maskp + BT;
    for (int i = tid; i < BT; i += 1024) {
        int t = i & 1023;
        float iv = g_imp[i];
        if (t < SINKc) iv = maxv + 1.0f;
        float mk = (iv >= thr) ? 1.0f : 0.0f;
        if (t < SINKc) mk = 1.0f;
        if (amask[i] == 0) mk = 0.0f;
        maskp[i] = mk;
        impp[i]  = iv;
    }
}

// ---------------- launch ----------------
extern "C" void kernel_launch(void* const* d_in, const int* in_sizes, int n_in,
                              void* d_out, int out_size) {
    (void)in_sizes; (void)n_in; (void)out_size;
    const float* x      = (const float*)d_in[0];
    const int*   amask  = (const int*)  d_in[1];
    const float* W_attn = (const float*)d_in[2];
    const float* b_attn = (const float*)d_in[3];
    const float* W_proj = (const float*)d_in[4];
    const float* b_proj = (const float*)d_in[5];
    const float* ln1_w  = (const float*)d_in[6];
    const float* ln1_b  = (const float*)d_in[7];
    const float* ln2_w  = (const float*)d_in[8];
    const float* ln2_b  = (const float*)d_in[9];
    const float* W_fc   = (const float*)d_in[10];
    const float* b_fc   = (const float*)d_in[11];
    const float* W_fc2  = (const float*)d_in[12];
    const float* b_fc2  = (const float*)d_in[13];
    const float* thr    = (const float*)d_in[14];
    float* outp = (float*)d_out;

    h16 *ph, *pq, *pk, *pvt, *py, *pfc, *pwat, *pwpt, *pwft, *pwf2t;
    float *px2;
    cudaGetSymbolAddress((void**)&ph,    g_h);
    cudaGetSymbolAddress((void**)&pq,    g_q);
    cudaGetSymbolAddress((void**)&pk,    g_k);
    cudaGetSymbolAddress((void**)&pvt,   g_vt);
    cudaGetSymbolAddress((void**)&py,    g_y);
    cudaGetSymbolAddress((void**)&pfc,   g_fc);
    cudaGetSymbolAddress((void**)&px2,   g_x2);
    cudaGetSymbolAddress((void**)&pwat,  g_wat);
    cudaGetSymbolAddress((void**)&pwpt,  g_wpt);
    cudaGetSymbolAddress((void**)&pwft,  g_wft);
    cudaGetSymbolAddress((void**)&pwf2t, g_wf2t);

    cudaFuncSetAttribute(mma_gemm<1>, cudaFuncAttributeMaxDynamicSharedMemorySize, GSMEM_BYTES);
    cudaFuncSetAttribute(mma_gemm<2>, cudaFuncAttributeMaxDynamicSharedMemorySize, GSMEM_BYTES);
    cudaFuncSetAttribute(mma_gemm<3>, cudaFuncAttributeMaxDynamicSharedMemorySize, GSMEM_BYTES);
    cudaFuncSetAttribute(flash_kernel, cudaFuncAttributeMaxDynamicSharedMemorySize, ATT_SMEM_BYTES);

    trall_kernel<<<12288, 256>>>(W_attn, pwat, W_proj, pwpt, W_fc, pwft, W_fc2, pwf2t);

    ln_kernel<<<BT, 256>>>(x, ln1_w, ln1_b, ph);
    mma_gemm<1><<<dim3(3*Cc/128, BT/128), 256, GSMEM_BYTES>>>(ph, pwat, b_attn, nullptr,
                                                 nullptr, pq, pk, pvt, nullptr, BT, 3*Cc, Cc);
    flash_kernel<<<dim3(Tc/128, Bc*Hc), 256, ATT_SMEM_BYTES>>>(amask);
    impreduce_kernel<<<16, 256>>>();
    mma_gemm<2><<<dim3(Cc/128, BT/128), 256, GSMEM_BYTES>>>(py, pwpt, b_proj, x,
                                               px2, nullptr, nullptr, nullptr, nullptr, BT, Cc, Cc);
    ln_kernel<<<BT, 256>>>(px2, ln2_w, ln2_b, ph);
    mma_gemm<3><<<dim3(4*Cc/128, BT/128), 256, GSMEM_BYTES>>>(ph, pwft, b_fc, nullptr,
                                                 nullptr, nullptr, nullptr, nullptr, pfc, BT, 4*Cc, Cc);
    mma_gemm<2><<<dim3(Cc/128, BT/128), 256, GSMEM_BYTES>>>(pfc, pwf2t, b_fc2, px2,
                                               outp, nullptr, nullptr, nullptr, nullptr, BT, Cc, 4*Cc);
    finalize_kernel<<<1, 1024>>>(amask, thr, outp);
}

// round 15
// speedup vs baseline: 2.2843x; 1.0160x over previous
#include <cuda_runtime.h>
#include <cuda_fp16.h>
#include <cstdint>
#include <math.h>

#define Bc 4
#define Tc 1024
#define Cc 1024
#define Hc 16
#define Dc 64
#define BT (Bc*Tc)
#define SINKc 4
#define QSCALE 0.18033688011112042f   // log2(e)/8

typedef __half h16;

// ---------------- scratch ----------------
__device__ h16   g_h  [(size_t)BT*Cc];
__device__ h16   g_q  [(size_t)BT*Cc];        // (B,H,T,D), pre-scaled by QSCALE
__device__ h16   g_k  [(size_t)BT*Cc];
__device__ h16   g_vt [(size_t)BT*Cc];        // (B,H,D,T)
__device__ h16   g_y  [(size_t)BT*Cc];        // (B,T,C)
__device__ h16   g_fc [(size_t)BT*4*Cc];
__device__ float g_x2 [(size_t)BT*Cc];
__device__ float g_part[(size_t)Bc*Hc*8*Tc];
__device__ float g_imp[BT];
__device__ h16   g_wat [(size_t)3*Cc*Cc];     // [N][K]
__device__ h16   g_wpt [(size_t)Cc*Cc];
__device__ h16   g_wft [(size_t)4*Cc*Cc];
__device__ h16   g_wf2t[(size_t)Cc*4*Cc];

// ---------------- helpers ----------------
__device__ __forceinline__ uint32_t smem_u32(const void* p) {
    uint32_t r;
    asm("{ .reg .u64 t; cvta.to.shared.u64 t, %1; cvt.u32.u64 %0, t; }"
        : "=r"(r) : "l"(p));
    return r;
}
__device__ __forceinline__ void ldsm4(uint32_t& r0, uint32_t& r1, uint32_t& r2, uint32_t& r3, uint32_t a) {
    asm volatile("ldmatrix.sync.aligned.m8n8.x4.shared.b16 {%0,%1,%2,%3},[%4];"
        : "=r"(r0), "=r"(r1), "=r"(r2), "=r"(r3) : "r"(a));
}
__device__ __forceinline__ void mma_f16(float* c, uint32_t a0, uint32_t a1, uint32_t a2, uint32_t a3,
                                        uint32_t b0, uint32_t b1) {
    asm volatile("mma.sync.aligned.m16n8k16.row.col.f32.f16.f16.f32 "
        "{%0,%1,%2,%3},{%4,%5,%6,%7},{%8,%9},{%0,%1,%2,%3};"
        : "+f"(c[0]), "+f"(c[1]), "+f"(c[2]), "+f"(c[3])
        : "r"(a0), "r"(a1), "r"(a2), "r"(a3), "r"(b0), "r"(b1));
}
__device__ __forceinline__ uint32_t f2h2(float a, float b) {
    __half2 h = __floats2half2_rn(a, b);
    uint32_t r;
    memcpy(&r, &h, 4);
    return r;
}
__device__ __forceinline__ uint32_t ex2h2(float a, float b) {
    uint32_t u = f2h2(a, b);
    uint32_t r;
    asm("ex2.approx.f16x2 %0, %1;" : "=r"(r) : "r"(u));
    return r;
}
__device__ __forceinline__ void cp16(uint32_t s, const void* g) {
    asm volatile("cp.async.cg.shared.global [%0], [%1], 16;" :: "r"(s), "l"(g));
}
#define CP_COMMIT() asm volatile("cp.async.commit_group;")
#define CP_WAIT0()  asm volatile("cp.async.wait_group 0;" ::: "memory")
#define CP_WAIT2()  asm volatile("cp.async.wait_group 2;")

// ---------------- fused weight transpose ----------------
__global__ void __launch_bounds__(256) trall_kernel(
    const float* __restrict__ W0, h16* __restrict__ T0,
    const float* __restrict__ W1, h16* __restrict__ T1,
    const float* __restrict__ W2, h16* __restrict__ T2,
    const float* __restrict__ W3, h16* __restrict__ T3)
{
    __shared__ float ts[32][33];
    int bidx = blockIdx.x;
    const float* W; h16* Wt; int K, N, gx, local;
    if (bidx < 3072)      { W = W0; Wt = T0; K = 1024; N = 3072; gx = 96;  local = bidx; }
    else if (bidx < 4096) { W = W1; Wt = T1; K = 1024; N = 1024; gx = 32;  local = bidx - 3072; }
    else if (bidx < 8192) { W = W2; Wt = T2; K = 1024; N = 4096; gx = 128; local = bidx - 4096; }
    else                  { W = W3; Wt = T3; K = 4096; N = 1024; gx = 32;  local = bidx - 8192; }
    int k0 = (local / gx) * 32, n0 = (local % gx) * 32;
    int tx = threadIdx.x & 31, ty = threadIdx.x >> 5;
    #pragma unroll
    for (int i = 0; i < 4; i++) {
        ts[ty + i*8][tx] = W[(size_t)(k0 + ty + i*8) * N + n0 + tx];
    }
    __syncthreads();
    #pragma unroll
    for (int i = 0; i < 4; i++) {
        Wt[(size_t)(n0 + ty + i*8) * K + k0 + tx] = __float2half_rn(ts[tx][ty + i*8]);
    }
}

// ---------------- LayerNorm (fp32 in, fp16 out) ----------------
__global__ void __launch_bounds__(256) ln_kernel(const float* __restrict__ x,
                                                 const float* __restrict__ w,
                                                 const float* __restrict__ b,
                                                 h16* __restrict__ out) {
    int row = blockIdx.x;
    int tid = threadIdx.x;
    const float* xr = x + (size_t)row * Cc;
    float4 v = *(const float4*)(xr + tid * 4);
    float s  = v.x + v.y + v.z + v.w;
    float s2 = v.x*v.x + v.y*v.y + v.z*v.z + v.w*v.w;
    #pragma unroll
    for (int o = 16; o; o >>= 1) {
        s  += __shfl_xor_sync(~0u, s,  o);
        s2 += __shfl_xor_sync(~0u, s2, o);
    }
    __shared__ float ws[8], ws2[8];
    int wid = tid >> 5, lid = tid & 31;
    if (lid == 0) { ws[wid] = s; ws2[wid] = s2; }
    __syncthreads();
    if (tid < 8) {
        float a = ws[tid], a2 = ws2[tid];
        #pragma unroll
        for (int o = 4; o; o >>= 1) {
            a  += __shfl_xor_sync(0xffu, a,  o);
            a2 += __shfl_xor_sync(0xffu, a2, o);
        }
        if (tid == 0) { ws[0] = a; ws2[0] = a2; }
    }
    __syncthreads();
    float mean = ws[0] * (1.0f / Cc);
    float var  = ws2[0] * (1.0f / Cc) - mean * mean;
    float inv  = rsqrtf(var + 1e-5f);
    int c = tid * 4;
    float4 wv = *(const float4*)(w + c);
    float4 bv = *(const float4*)(b + c);
    uint2 pk;
    pk.x = f2h2((v.x - mean) * inv * wv.x + bv.x, (v.y - mean) * inv * wv.y + bv.y);
    pk.y = f2h2((v.z - mean) * inv * wv.z + bv.z, (v.w - mean) * inv * wv.w + bv.w);
    *(uint2*)(out + (size_t)row * Cc + c) = pk;
}

// ---------------- fp16 MMA GEMM 128x128x32, cp.async 4-stage, occ 2 ----------------
#define GSTAGES 4
#define GSMEM_BYTES (GSTAGES * 2 * 128 * 40 * 2)
template<int EPI>
__global__ void __launch_bounds__(256, 2) mma_gemm(
    const h16* __restrict__ A, const h16* __restrict__ Bt,
    const float* __restrict__ bias, const float* __restrict__ res,
    float* __restrict__ outF, h16* __restrict__ outQ,
    h16* __restrict__ outK, h16* __restrict__ outVt,
    h16* __restrict__ outH,
    int M, int N, int K)
{
    extern __shared__ h16 dsm[];
    typedef h16 (*Tile)[128][40];
    Tile As = (Tile)dsm;
    Tile Bs = (Tile)(dsm + (size_t)GSTAGES * 128 * 40);

    int tid = threadIdx.x, lane = tid & 31, wid = tid >> 5;
    int wm = wid & 3, wn = wid >> 2;
    int bm = blockIdx.y * 128, bn = blockIdx.x * 128;

    float acc[2][8][4];
    #pragma unroll
    for (int i = 0; i < 2; i++) {
        #pragma unroll
        for (int j = 0; j < 8; j++) {
            #pragma unroll
            for (int k = 0; k < 4; k++) { acc[i][j][k] = 0.f; }
        }
    }

    int row = tid >> 1, kc = (tid & 1) * 16;
    const h16* Ap = A  + (size_t)(bm + row) * K + kc;
    const h16* Bp = Bt + (size_t)(bn + row) * K + kc;

    #pragma unroll
    for (int s = 0; s < GSTAGES - 1; s++) {
        int k0 = s * 32;
        cp16(smem_u32(&As[s][row][kc]),     Ap + k0);
        cp16(smem_u32(&As[s][row][kc + 8]), Ap + k0 + 8);
        cp16(smem_u32(&Bs[s][row][kc]),     Bp + k0);
        cp16(smem_u32(&Bs[s][row][kc + 8]), Bp + k0 + 8);
        CP_COMMIT();
    }

    int nk = K >> 5;
    for (int it = 0; it < nk; it++) {
        CP_WAIT2();
        __syncthreads();
        int st = it & (GSTAGES - 1);
        int nx = it + GSTAGES - 1;
        if (nx < nk) {
            int sx = nx & (GSTAGES - 1);
            int k0 = nx << 5;
            cp16(smem_u32(&As[sx][row][kc]),     Ap + k0);
            cp16(smem_u32(&As[sx][row][kc + 8]), Ap + k0 + 8);
            cp16(smem_u32(&Bs[sx][row][kc]),     Bp + k0);
            cp16(smem_u32(&Bs[sx][row][kc + 8]), Bp + k0 + 8);
        }
        CP_COMMIT();
        #pragma unroll
        for (int kk = 0; kk < 32; kk += 16) {
            uint32_t af[2][4];
            #pragma unroll
            for (int mt = 0; mt < 2; mt++) {
                ldsm4(af[mt][0], af[mt][1], af[mt][2], af[mt][3],
                      smem_u32(&As[st][wm*32 + mt*16 + (lane & 15)][kk + (lane >> 4) * 8]));
            }
            uint32_t bfr[8][2];
            #pragma unroll
            for (int np = 0; np < 4; np++) {
                uint32_t r0, r1, r2, r3;
                ldsm4(r0, r1, r2, r3,
                      smem_u32(&Bs[st][wn*64 + np*16 + (lane & 15)][kk + (lane >> 4) * 8]));
                bfr[np*2][0] = r0;   bfr[np*2][1] = r2;
                bfr[np*2+1][0] = r1; bfr[np*2+1][1] = r3;
            }
            #pragma unroll
            for (int mt = 0; mt < 2; mt++) {
                #pragma unroll
                for (int nt = 0; nt < 8; nt++) {
                    mma_f16(acc[mt][nt], af[mt][0], af[mt][1], af[mt][2], af[mt][3],
                            bfr[nt][0], bfr[nt][1]);
                }
            }
        }
    }

    #pragma unroll
    for (int mt = 0; mt < 2; mt++) {
        #pragma unroll
        for (int nt = 0; nt < 8; nt++) {
            int r0 = bm + wm*32 + mt*16 + (lane >> 2);
            int c0 = bn + wn*64 + nt*8 + (lane & 3) * 2;
            float bb0 = bias[c0], bb1 = bias[c0 + 1];
            #pragma unroll
            for (int rr = 0; rr < 2; rr++) {
                int rg = r0 + rr * 8;
                float v0 = acc[mt][nt][rr*2 + 0] + bb0;
                float v1 = acc[mt][nt][rr*2 + 1] + bb1;
                if (EPI == 1) {
                    int sec = c0 >> 10, wc = c0 & 1023;
                    int h = wc >> 6, d = wc & 63;
                    int bbi = rg >> 10, t = rg & 1023;
                    if (sec == 0) {
                        *(uint32_t*)&outQ[(((size_t)(bbi*Hc + h))*Tc + t)*Dc + d] =
                            f2h2(v0 * QSCALE, v1 * QSCALE);
                    } else if (sec == 1) {
                        *(uint32_t*)&outK[(((size_t)(bbi*Hc + h))*Tc + t)*Dc + d] = f2h2(v0, v1);
                    } else {
                        size_t vb = (((size_t)(bbi*Hc + h))*Dc + d)*Tc + t;
                        outVt[vb] = __float2half_rn(v0);
                        outVt[vb + Tc] = __float2half_rn(v1);
                    }
                } else if (EPI == 2) {
                    size_t idx = (size_t)rg * N + c0;
                    float2 rv = *(const float2*)(res + idx);
                    float2 o; o.x = v0 + rv.x; o.y = v1 + rv.y;
                    *(float2*)(outF + idx) = o;
                } else {
                    float g0 = 0.5f * v0 * (1.0f + erff(v0 * 0.70710678118654752f));
                    float g1 = 0.5f * v1 * (1.0f + erff(v1 * 0.70710678118654752f));
                    *(uint32_t*)&outH[(size_t)rg * N + c0] = f2h2(g0, g1);
                }
            }
        }
    }
}

// ================ flash attention: warp-private rows, log2-domain exp, reg-PV ================
// smem bytes: Qs[128][72] | Ks[2][64][72] | Vs[2][64][72] | Ss[128][72]
#define OFFB_QS 0
#define OFFB_KS 18432
#define OFFB_VS 36864
#define OFFB_SS 55296
#define ATT_SMEM_BYTES 73728

__device__ __forceinline__ void compute_S_w(
    const h16 (*Qs)[72], const h16 (*Ks)[72],
    int wid, int lane, float acc[8][4])
{
    #pragma unroll
    for (int j = 0; j < 8; j++) {
        #pragma unroll
        for (int k = 0; k < 4; k++) { acc[j][k] = 0.f; }
    }
    #pragma unroll
    for (int kk = 0; kk < 64; kk += 16) {
        uint32_t af[4];
        ldsm4(af[0], af[1], af[2], af[3],
              smem_u32(&Qs[wid*16 + (lane & 15)][kk + (lane >> 4) * 8]));
        uint32_t bfr[8][2];
        #pragma unroll
        for (int np = 0; np < 4; np++) {
            uint32_t r0, r1, r2, r3;
            ldsm4(r0, r1, r2, r3,
                  smem_u32(&Ks[np*16 + (lane & 15)][kk + (lane >> 4) * 8]));
            bfr[np*2][0] = r0;   bfr[np*2][1] = r2;
            bfr[np*2+1][0] = r1; bfr[np*2+1][1] = r3;
        }
        #pragma unroll
        for (int nt = 0; nt < 8; nt++) {
            mma_f16(acc[nt], af[0], af[1], af[2], af[3], bfr[nt][0], bfr[nt][1]);
        }
    }
}

__global__ void __launch_bounds__(256, 2) flash_kernel(const int* __restrict__ amask) {
    extern __shared__ char smc[];
    h16 (*Qs)[72] = (h16(*)[72])(smc + OFFB_QS);
    h16 (*Ks)[2][64][72] = (h16(*)[2][64][72])(smc + OFFB_KS);
    h16 (*Vs)[2][64][72] = (h16(*)[2][64][72])(smc + OFFB_VS);
    h16 (*Ss)[72] = (h16(*)[72])(smc + OFFB_SS);

    int bh = blockIdx.y, b = bh >> 4, h = bh & 15;
    int qblk = (int)(gridDim.x - 1 - blockIdx.x);
    int i0 = qblk << 7;
    int tid = threadIdx.x, lane = tid & 31, wid = tid >> 5;
    int rowk = tid >> 2, ck = (tid & 3) * 16;
    const h16* kbase = g_k  + ((size_t)bh*Tc) * Dc;
    const h16* vbase = g_vt + ((size_t)bh*Dc) * Tc;

    {
        int row = tid >> 1, c0 = (tid & 1) * 32;
        const h16* qp = g_q + ((size_t)bh*Tc + i0 + row)*Dc + c0;
        #pragma unroll
        for (int c8 = 0; c8 < 32; c8 += 8) {
            *(uint4*)&Qs[row][c0 + c8] = *(const uint4*)(qp + c8);
        }
    }

    int nj = (qblk + 1) * 2;
    float acc[8][4];
    float l0 = 0.f, l1 = 0.f;
    int ra = i0 + wid*16 + (lane >> 2);
    int rb = ra + 8;

    // ---------- pass A: l = sum 2^S (S already log2-domain) ----------
    {
        const h16* kp = kbase + (size_t)rowk * Dc + ck;
        cp16(smem_u32(&(*Ks)[0][rowk][ck]),     kp);
        cp16(smem_u32(&(*Ks)[0][rowk][ck + 8]), kp + 8);
        CP_COMMIT();
    }
    for (int jb = 0; jb < nj; jb++) {
        int j0 = jb << 6;
        CP_WAIT0();
        __syncthreads();
        if (jb + 1 < nj) {
            const h16* kp = kbase + (size_t)(j0 + 64 + rowk) * Dc + ck;
            int bf = (jb + 1) & 1;
            cp16(smem_u32(&(*Ks)[bf][rowk][ck]),     kp);
            cp16(smem_u32(&(*Ks)[bf][rowk][ck + 8]), kp + 8);
        }
        CP_COMMIT();
        compute_S_w(Qs, (*Ks)[jb & 1], wid, lane, acc);
        float e0 = 0.f, e1 = 0.f;
        #pragma unroll
        for (int nt = 0; nt < 8; nt++) {
            int c0 = j0 + nt*8 + (lane & 3) * 2;
            int am0 = amask[b*Tc + c0], am1 = amask[b*Tc + c0 + 1];
            if (c0     <= ra && am0) { e0 += exp2f(acc[nt][0]); }
            if (c0 + 1 <= ra && am1) { e0 += exp2f(acc[nt][1]); }
            if (c0     <= rb && am0) { e1 += exp2f(acc[nt][2]); }
            if (c0 + 1 <= rb && am1) { e1 += exp2f(acc[nt][3]); }
        }
        e0 += __shfl_xor_sync(~0u, e0, 1);
        e0 += __shfl_xor_sync(~0u, e0, 2);
        e1 += __shfl_xor_sync(~0u, e1, 1);
        e1 += __shfl_xor_sync(~0u, e1, 2);
        l0 += e0;
        l1 += e1;
    }
    float lg0 = (l0 > 0.f) ? -__log2f(l0) : -60000.f;
    float lg1 = (l1 > 0.f) ? -__log2f(l1) : -60000.f;

    float acco[8][4];
    #pragma unroll
    for (int j = 0; j < 8; j++) {
        #pragma unroll
        for (int k = 0; k < 4; k++) { acco[j][k] = 0.f; }
    }

    // ---------- pass B: P = 2^(S + lg) via ex2.f16x2; colsum; O += P@V (reg A-frags) ----------
    __syncthreads();
    {
        const h16* kp = kbase + (size_t)rowk * Dc + ck;
        cp16(smem_u32(&(*Ks)[0][rowk][ck]),     kp);
        cp16(smem_u32(&(*Ks)[0][rowk][ck + 8]), kp + 8);
        const h16* vp = vbase + (size_t)rowk * Tc + ck;
        cp16(smem_u32(&(*Vs)[0][rowk][ck]),     vp);
        cp16(smem_u32(&(*Vs)[0][rowk][ck + 8]), vp + 8);
        CP_COMMIT();
    }
    for (int jb = 0; jb < nj; jb++) {
        int j0 = jb << 6;
        CP_WAIT0();
        __syncthreads();
        if (jb + 1 < nj) {
            int bf = (jb + 1) & 1;
            const h16* kp = kbase + (size_t)(j0 + 64 + rowk) * Dc + ck;
            cp16(smem_u32(&(*Ks)[bf][rowk][ck]),     kp);
            cp16(smem_u32(&(*Ks)[bf][rowk][ck + 8]), kp + 8);
            const h16* vp = vbase + (size_t)rowk * Tc + j0 + 64 + ck;
            cp16(smem_u32(&(*Vs)[bf][rowk][ck]),     vp);
            cp16(smem_u32(&(*Vs)[bf][rowk][ck + 8]), vp + 8);
        }
        CP_COMMIT();
        compute_S_w(Qs, (*Ks)[jb & 1], wid, lane, acc);
        uint32_t pa[8], pb[8];
        #pragma unroll
        for (int nt = 0; nt < 8; nt++) {
            int cl = nt*8 + (lane & 3) * 2;
            int c0 = j0 + cl;
            int am0 = amask[b*Tc + c0], am1 = amask[b*Tc + c0 + 1];
            float a0 = (c0     <= ra && am0) ? (acc[nt][0] + lg0) : -60000.f;
            float a1 = (c0 + 1 <= ra && am1) ? (acc[nt][1] + lg0) : -60000.f;
            float b0 = (c0     <= rb && am0) ? (acc[nt][2] + lg1) : -60000.f;
            float b1 = (c0 + 1 <= rb && am1) ? (acc[nt][3] + lg1) : -60000.f;
            pa[nt] = ex2h2(a0, a1);
            pb[nt] = ex2h2(b0, b1);
            *(uint32_t*)&Ss[wid*16 + (lane >> 2)][cl]     = pa[nt];
            *(uint32_t*)&Ss[wid*16 + (lane >> 2) + 8][cl] = pb[nt];
        }
        __syncthreads();          // Ss visible for colsum
        if (tid < 64) {
            float s = 0.f;
            #pragma unroll 8
            for (int r = 0; r < 128; r++) { s += __half2float(Ss[r][tid]); }
            g_part[((size_t)bh*8 + qblk)*Tc + j0 + tid] = s;
        }
        // O += P @ V with A-fragments straight from registers
        #pragma unroll
        for (int g = 0; g < 4; g++) {
            int kk = g * 16;
            uint32_t bfr[8][2];
            #pragma unroll
            for (int np = 0; np < 4; np++) {
                uint32_t r0, r1, r2, r3;
                ldsm4(r0, r1, r2, r3,
                      smem_u32(&(*Vs)[jb & 1][np*16 + (lane & 15)][kk + (lane >> 4) * 8]));
                bfr[np*2][0] = r0;   bfr[np*2][1] = r2;
                bfr[np*2+1][0] = r1; bfr[np*2+1][1] = r3;
            }
            #pragma unroll
            for (int nt = 0; nt < 8; nt++) {
                mma_f16(acco[nt], pa[2*g], pb[2*g], pa[2*g + 1], pb[2*g + 1],
                        bfr[nt][0], bfr[nt][1]);
            }
        }
    }

    #pragma unroll
    for (int nt = 0; nt < 8; nt++) {
        int q0 = i0 + wid*16 + (lane >> 2);
        int d0 = nt*8 + (lane & 3) * 2;
        #pragma unroll
        for (int rr = 0; rr < 2; rr++) {
            int q = q0 + rr * 8;
            *(uint32_t*)&g_y[(size_t)(b*Tc + q) * Cc + h*64 + d0] =
                f2h2(acco[nt][rr*2], acco[nt][rr*2 + 1]);
        }
    }
    for (int c = i0 + 128 + tid; c < Tc; c += 256) {
        g_part[((size_t)bh*8 + qblk)*Tc + c] = 0.f;
    }
}

// ---------------- imp reduce ----------------
__global__ void __launch_bounds__(256) impreduce_kernel() {
    int gt = blockIdx.x * 256 + threadIdx.x;
    int b = gt >> 10, t = gt & 1023;
    float s = 0.f;
    const float* p = g_part + (size_t)b * 128 * Tc + t;
    for (int i = 0; i < 128; i++) { s += p[(size_t)i * Tc]; }
    float posn = (float)(Tc - t) / (float)Tc;
    g_imp[gt] = (s / (float)Hc) / (posn + 1e-8f);
}

__global__ void __launch_bounds__(1024) finalize_kernel(const int* __restrict__ amask,
                                                        const float* __restrict__ thrp,
                                                        float* __restrict__ outp) {
    int tid = threadIdx.x;
    float m = -3.4e38f;
    for (int i = tid; i < BT; i += 1024) { m = fmaxf(m, g_imp[i]); }
    __shared__ float red[32];
    #pragma unroll
    for (int o = 16; o; o >>= 1) { m = fmaxf(m, __shfl_xor_sync(~0u, m, o)); }
    if ((tid & 31) == 0) red[tid >> 5] = m;
    __syncthreads();
    if (tid < 32) {
        float v = red[tid];
        #pragma unroll
        for (int o = 16; o; o >>= 1) { v = fmaxf(v, __shfl_xor_sync(~0u, v, o)); }
        if (tid == 0) red[0] = v;
    }
    __syncthreads();
    float maxv = red[0];
    float thr = *thrp;
    float* maskp = outp + (size_t)BT * Cc;
    float* impp  = maskp + BT;
    for (int i = tid; i < BT; i += 1024) {
        int t = i & 1023;
        float iv = g_imp[i];
        if (t < SINKc) iv = maxv + 1.0f;
        float mk = (iv >= thr) ? 1.0f : 0.0f;
        if (t < SINKc) mk = 1.0f;
        if (amask[i] == 0) mk = 0.0f;
        maskp[i] = mk;
        impp[i]  = iv;
    }
}

// ---------------- launch ----------------
extern "C" void kernel_launch(void* const* d_in, const int* in_sizes, int n_in,
                              void* d_out, int out_size) {
    (void)in_sizes; (void)n_in; (void)out_size;
    const float* x      = (const float*)d_in[0];
    const int*   amask  = (const int*)  d_in[1];
    const float* W_attn = (const float*)d_in[2];
    const float* b_attn = (const float*)d_in[3];
    const float* W_proj = (const float*)d_in[4];
    const float* b_proj = (const float*)d_in[5];
    const float* ln1_w  = (const float*)d_in[6];
    const float* ln1_b  = (const float*)d_in[7];
    const float* ln2_w  = (const float*)d_in[8];
    const float* ln2_b  = (const float*)d_in[9];
    const float* W_fc   = (const float*)d_in[10];
    const float* b_fc   = (const float*)d_in[11];
    const float* W_fc2  = (const float*)d_in[12];
    const float* b_fc2  = (const float*)d_in[13];
    const float* thr    = (const float*)d_in[14];
    float* outp = (float*)d_out;

    h16 *ph, *pq, *pk, *pvt, *py, *pfc, *pwat, *pwpt, *pwft, *pwf2t;
    float *px2;
    cudaGetSymbolAddress((void**)&ph,    g_h);
    cudaGetSymbolAddress((void**)&pq,    g_q);
    cudaGetSymbolAddress((void**)&pk,    g_k);
    cudaGetSymbolAddress((void**)&pvt,   g_vt);
    cudaGetSymbolAddress((void**)&py,    g_y);
    cudaGetSymbolAddress((void**)&pfc,   g_fc);
    cudaGetSymbolAddress((void**)&px2,   g_x2);
    cudaGetSymbolAddress((void**)&pwat,  g_wat);
    cudaGetSymbolAddress((void**)&pwpt,  g_wpt);
    cudaGetSymbolAddress((void**)&pwft,  g_wft);
    cudaGetSymbolAddress((void**)&pwf2t, g_wf2t);

    cudaFuncSetAttribute(mma_gemm<1>, cudaFuncAttributeMaxDynamicSharedMemorySize, GSMEM_BYTES);
    cudaFuncSetAttribute(mma_gemm<2>, cudaFuncAttributeMaxDynamicSharedMemorySize, GSMEM_BYTES);
    cudaFuncSetAttribute(mma_gemm<3>, cudaFuncAttributeMaxDynamicSharedMemorySize, GSMEM_BYTES);
    cudaFuncSetAttribute(flash_kernel, cudaFuncAttributeMaxDynamicSharedMemorySize, ATT_SMEM_BYTES);

    trall_kernel<<<12288, 256>>>(W_attn, pwat, W_proj, pwpt, W_fc, pwft, W_fc2, pwf2t);

    ln_kernel<<<BT, 256>>>(x, ln1_w, ln1_b, ph);
    mma_gemm<1><<<dim3(3*Cc/128, BT/128), 256, GSMEM_BYTES>>>(ph, pwat, b_attn, nullptr,
                                                 nullptr, pq, pk, pvt, nullptr, BT, 3*Cc, Cc);
    flash_kernel<<<dim3(Tc/128, Bc*Hc), 256, ATT_SMEM_BYTES>>>(amask);
    impreduce_kernel<<<16, 256>>>();
    mma_gemm<2><<<dim3(Cc/128, BT/128), 256, GSMEM_BYTES>>>(py, pwpt, b_proj, x,
                                               px2, nullptr, nullptr, nullptr, nullptr, BT, Cc, Cc);
    ln_kernel<<<BT, 256>>>(px2, ln2_w, ln2_b, ph);
    mma_gemm<3><<<dim3(4*Cc/128, BT/128), 256, GSMEM_BYTES>>>(ph, pwft, b_fc, nullptr,
                                                 nullptr, nullptr, nullptr, nullptr, pfc, BT, 4*Cc, Cc);
    mma_gemm<2><<<dim3(Cc/128, BT/128), 256, GSMEM_BYTES>>>(pfc, pwf2t, b_fc2, px2,
                                               outp, nullptr, nullptr, nullptr, nullptr, BT, Cc, 4*Cc);
    finalize_kernel<<<1, 1024>>>(amask, thr, outp);
}

// round 16
// speedup vs baseline: 2.3116x; 1.0120x over previous
#include <cuda_runtime.h>
#include <cuda_fp16.h>
#include <cstdint>
#include <math.h>

#define Bc 4
#define Tc 1024
#define Cc 1024
#define Hc 16
#define Dc 64
#define BT (Bc*Tc)
#define SINKc 4
#define QSCALE 0.18033688011112042f   // log2(e)/8

typedef __half h16;

// ---------------- scratch ----------------
__device__ h16   g_h  [(size_t)BT*Cc];
__device__ h16   g_q  [(size_t)BT*Cc];        // (B,H,T,D), pre-scaled by QSCALE
__device__ h16   g_k  [(size_t)BT*Cc];
__device__ h16   g_vt [(size_t)BT*Cc];        // (B,H,D,T)
__device__ h16   g_y  [(size_t)BT*Cc];        // (B,T,C)
__device__ h16   g_fc [(size_t)BT*4*Cc];
__device__ float g_x2 [(size_t)BT*Cc];
__device__ float g_part[(size_t)Bc*Hc*8*Tc];
__device__ float g_imp[BT];
__device__ h16   g_wat [(size_t)3*Cc*Cc];     // [N][K]
__device__ h16   g_wpt [(size_t)Cc*Cc];
__device__ h16   g_wft [(size_t)4*Cc*Cc];
__device__ h16   g_wf2t[(size_t)Cc*4*Cc];

// ---------------- helpers ----------------
__device__ __forceinline__ uint32_t smem_u32(const void* p) {
    uint32_t r;
    asm("{ .reg .u64 t; cvta.to.shared.u64 t, %1; cvt.u32.u64 %0, t; }"
        : "=r"(r) : "l"(p));
    return r;
}
__device__ __forceinline__ void ldsm4(uint32_t& r0, uint32_t& r1, uint32_t& r2, uint32_t& r3, uint32_t a) {
    asm volatile("ldmatrix.sync.aligned.m8n8.x4.shared.b16 {%0,%1,%2,%3},[%4];"
        : "=r"(r0), "=r"(r1), "=r"(r2), "=r"(r3) : "r"(a));
}
__device__ __forceinline__ void mma_f16(float* c, uint32_t a0, uint32_t a1, uint32_t a2, uint32_t a3,
                                        uint32_t b0, uint32_t b1) {
    asm volatile("mma.sync.aligned.m16n8k16.row.col.f32.f16.f16.f32 "
        "{%0,%1,%2,%3},{%4,%5,%6,%7},{%8,%9},{%0,%1,%2,%3};"
        : "+f"(c[0]), "+f"(c[1]), "+f"(c[2]), "+f"(c[3])
        : "r"(a0), "r"(a1), "r"(a2), "r"(a3), "r"(b0), "r"(b1));
}
__device__ __forceinline__ uint32_t f2h2(float a, float b) {
    __half2 h = __floats2half2_rn(a, b);
    uint32_t r;
    memcpy(&r, &h, 4);
    return r;
}
__device__ __forceinline__ uint32_t ex2h2(float a, float b) {
    uint32_t u = f2h2(a, b);
    uint32_t r;
    asm("ex2.approx.f16x2 %0, %1;" : "=r"(r) : "r"(u));
    return r;
}
__device__ __forceinline__ void cp16(uint32_t s, const void* g) {
    asm volatile("cp.async.cg.shared.global [%0], [%1], 16;" :: "r"(s), "l"(g));
}
#define CP_COMMIT() asm volatile("cp.async.commit_group;")
#define CP_WAIT0()  asm volatile("cp.async.wait_group 0;" ::: "memory")
#define CP_WAIT2()  asm volatile("cp.async.wait_group 2;")

// ---------------- fused weight transpose ----------------
__global__ void __launch_bounds__(256) trall_kernel(
    const float* __restrict__ W0, h16* __restrict__ T0,
    const float* __restrict__ W1, h16* __restrict__ T1,
    const float* __restrict__ W2, h16* __restrict__ T2,
    const float* __restrict__ W3, h16* __restrict__ T3)
{
    __shared__ float ts[32][33];
    int bidx = blockIdx.x;
    const float* W; h16* Wt; int K, N, gx, local;
    if (bidx < 3072)      { W = W0; Wt = T0; K = 1024; N = 3072; gx = 96;  local = bidx; }
    else if (bidx < 4096) { W = W1; Wt = T1; K = 1024; N = 1024; gx = 32;  local = bidx - 3072; }
    else if (bidx < 8192) { W = W2; Wt = T2; K = 1024; N = 4096; gx = 128; local = bidx - 4096; }
    else                  { W = W3; Wt = T3; K = 4096; N = 1024; gx = 32;  local = bidx - 8192; }
    int k0 = (local / gx) * 32, n0 = (local % gx) * 32;
    int tx = threadIdx.x & 31, ty = threadIdx.x >> 5;
    #pragma unroll
    for (int i = 0; i < 4; i++) {
        ts[ty + i*8][tx] = W[(size_t)(k0 + ty + i*8) * N + n0 + tx];
    }
    __syncthreads();
    #pragma unroll
    for (int i = 0; i < 4; i++) {
        Wt[(size_t)(n0 + ty + i*8) * K + k0 + tx] = __float2half_rn(ts[tx][ty + i*8]);
    }
}

// ---------------- LayerNorm (fp32 in, fp16 out) ----------------
__global__ void __launch_bounds__(256) ln_kernel(const float* __restrict__ x,
                                                 const float* __restrict__ w,
                                                 const float* __restrict__ b,
                                                 h16* __restrict__ out) {
    int row = blockIdx.x;
    int tid = threadIdx.x;
    const float* xr = x + (size_t)row * Cc;
    float4 v = *(const float4*)(xr + tid * 4);
    float s  = v.x + v.y + v.z + v.w;
    float s2 = v.x*v.x + v.y*v.y + v.z*v.z + v.w*v.w;
    #pragma unroll
    for (int o = 16; o; o >>= 1) {
        s  += __shfl_xor_sync(~0u, s,  o);
        s2 += __shfl_xor_sync(~0u, s2, o);
    }
    __shared__ float ws[8], ws2[8];
    int wid = tid >> 5, lid = tid & 31;
    if (lid == 0) { ws[wid] = s; ws2[wid] = s2; }
    __syncthreads();
    if (tid < 8) {
        float a = ws[tid], a2 = ws2[tid];
        #pragma unroll
        for (int o = 4; o; o >>= 1) {
            a  += __shfl_xor_sync(0xffu, a,  o);
            a2 += __shfl_xor_sync(0xffu, a2, o);
        }
        if (tid == 0) { ws[0] = a; ws2[0] = a2; }
    }
    __syncthreads();
    float mean = ws[0] * (1.0f / Cc);
    float var  = ws2[0] * (1.0f / Cc) - mean * mean;
    float inv  = rsqrtf(var + 1e-5f);
    int c = tid * 4;
    float4 wv = *(const float4*)(w + c);
    float4 bv = *(const float4*)(b + c);
    uint2 pk;
    pk.x = f2h2((v.x - mean) * inv * wv.x + bv.x, (v.y - mean) * inv * wv.y + bv.y);
    pk.y = f2h2((v.z - mean) * inv * wv.z + bv.z, (v.w - mean) * inv * wv.w + bv.w);
    *(uint2*)(out + (size_t)row * Cc + c) = pk;
}

// ---------------- fp16 MMA GEMM 128x128x32, cp.async 4-stage, occ 2 ----------------
#define GSTAGES 4
#define GSMEM_BYTES (GSTAGES * 2 * 128 * 40 * 2)
template<int EPI>
__global__ void __launch_bounds__(256, 2) mma_gemm(
    const h16* __restrict__ A, const h16* __restrict__ Bt,
    const float* __restrict__ bias, const float* __restrict__ res,
    float* __restrict__ outF, h16* __restrict__ outQ,
    h16* __restrict__ outK, h16* __restrict__ outVt,
    h16* __restrict__ outH,
    int M, int N, int K)
{
    extern __shared__ h16 dsm[];
    typedef h16 (*Tile)[128][40];
    Tile As = (Tile)dsm;
    Tile Bs = (Tile)(dsm + (size_t)GSTAGES * 128 * 40);

    int tid = threadIdx.x, lane = tid & 31, wid = tid >> 5;
    int wm = wid & 3, wn = wid >> 2;
    int bm = blockIdx.y * 128, bn = blockIdx.x * 128;

    float acc[2][8][4];
    #pragma unroll
    for (int i = 0; i < 2; i++) {
        #pragma unroll
        for (int j = 0; j < 8; j++) {
            #pragma unroll
            for (int k = 0; k < 4; k++) { acc[i][j][k] = 0.f; }
        }
    }

    int row = tid >> 1, kc = (tid & 1) * 16;
    const h16* Ap = A  + (size_t)(bm + row) * K + kc;
    const h16* Bp = Bt + (size_t)(bn + row) * K + kc;

    #pragma unroll
    for (int s = 0; s < GSTAGES - 1; s++) {
        int k0 = s * 32;
        cp16(smem_u32(&As[s][row][kc]),     Ap + k0);
        cp16(smem_u32(&As[s][row][kc + 8]), Ap + k0 + 8);
        cp16(smem_u32(&Bs[s][row][kc]),     Bp + k0);
        cp16(smem_u32(&Bs[s][row][kc + 8]), Bp + k0 + 8);
        CP_COMMIT();
    }

    int nk = K >> 5;
    for (int it = 0; it < nk; it++) {
        CP_WAIT2();
        __syncthreads();
        int st = it & (GSTAGES - 1);
        int nx = it + GSTAGES - 1;
        if (nx < nk) {
            int sx = nx & (GSTAGES - 1);
            int k0 = nx << 5;
            cp16(smem_u32(&As[sx][row][kc]),     Ap + k0);
            cp16(smem_u32(&As[sx][row][kc + 8]), Ap + k0 + 8);
            cp16(smem_u32(&Bs[sx][row][kc]),     Bp + k0);
            cp16(smem_u32(&Bs[sx][row][kc + 8]), Bp + k0 + 8);
        }
        CP_COMMIT();
        #pragma unroll
        for (int kk = 0; kk < 32; kk += 16) {
            uint32_t af[2][4];
            #pragma unroll
            for (int mt = 0; mt < 2; mt++) {
                ldsm4(af[mt][0], af[mt][1], af[mt][2], af[mt][3],
                      smem_u32(&As[st][wm*32 + mt*16 + (lane & 15)][kk + (lane >> 4) * 8]));
            }
            uint32_t bfr[8][2];
            #pragma unroll
            for (int np = 0; np < 4; np++) {
                uint32_t r0, r1, r2, r3;
                ldsm4(r0, r1, r2, r3,
                      smem_u32(&Bs[st][wn*64 + np*16 + (lane & 15)][kk + (lane >> 4) * 8]));
                bfr[np*2][0] = r0;   bfr[np*2][1] = r2;
                bfr[np*2+1][0] = r1; bfr[np*2+1][1] = r3;
            }
            #pragma unroll
            for (int mt = 0; mt < 2; mt++) {
                #pragma unroll
                for (int nt = 0; nt < 8; nt++) {
                    mma_f16(acc[mt][nt], af[mt][0], af[mt][1], af[mt][2], af[mt][3],
                            bfr[nt][0], bfr[nt][1]);
                }
            }
        }
    }

    #pragma unroll
    for (int mt = 0; mt < 2; mt++) {
        #pragma unroll
        for (int nt = 0; nt < 8; nt++) {
            int r0 = bm + wm*32 + mt*16 + (lane >> 2);
            int c0 = bn + wn*64 + nt*8 + (lane & 3) * 2;
            float bb0 = bias[c0], bb1 = bias[c0 + 1];
            #pragma unroll
            for (int rr = 0; rr < 2; rr++) {
                int rg = r0 + rr * 8;
                float v0 = acc[mt][nt][rr*2 + 0] + bb0;
                float v1 = acc[mt][nt][rr*2 + 1] + bb1;
                if (EPI == 1) {
                    int sec = c0 >> 10, wc = c0 & 1023;
                    int h = wc >> 6, d = wc & 63;
                    int bbi = rg >> 10, t = rg & 1023;
                    if (sec == 0) {
                        *(uint32_t*)&outQ[(((size_t)(bbi*Hc + h))*Tc + t)*Dc + d] =
                            f2h2(v0 * QSCALE, v1 * QSCALE);
                    } else if (sec == 1) {
                        *(uint32_t*)&outK[(((size_t)(bbi*Hc + h))*Tc + t)*Dc + d] = f2h2(v0, v1);
                    } else {
                        size_t vb = (((size_t)(bbi*Hc + h))*Dc + d)*Tc + t;
                        outVt[vb] = __float2half_rn(v0);
                        outVt[vb + Tc] = __float2half_rn(v1);
                    }
                } else if (EPI == 2) {
                    size_t idx = (size_t)rg * N + c0;
                    float2 rv = *(const float2*)(res + idx);
                    float2 o; o.x = v0 + rv.x; o.y = v1 + rv.y;
                    *(float2*)(outF + idx) = o;
                } else {
                    float g0 = 0.5f * v0 * (1.0f + erff(v0 * 0.70710678118654752f));
                    float g1 = 0.5f * v1 * (1.0f + erff(v1 * 0.70710678118654752f));
                    *(uint32_t*)&outH[(size_t)rg * N + c0] = f2h2(g0, g1);
                }
            }
        }
    }
}

// ================ flash: warp-private rows, log2 exp, reg-PV, reg colsum ================
// smem bytes: Qs[128][72] | Ks[2][64][72] | Vs[2][64][72] | wred[8][64]f
#define OFFB_QS 0
#define OFFB_KS 18432
#define OFFB_VS 36864
#define OFFB_WR 55296
#define ATT_SMEM_BYTES 57344

__device__ __forceinline__ void compute_S_w(
    const h16 (*Qs)[72], const h16 (*Ks)[72],
    int wid, int lane, float acc[8][4])
{
    #pragma unroll
    for (int j = 0; j < 8; j++) {
        #pragma unroll
        for (int k = 0; k < 4; k++) { acc[j][k] = 0.f; }
    }
    #pragma unroll
    for (int kk = 0; kk < 64; kk += 16) {
        uint32_t af[4];
        ldsm4(af[0], af[1], af[2], af[3],
              smem_u32(&Qs[wid*16 + (lane & 15)][kk + (lane >> 4) * 8]));
        uint32_t bfr[8][2];
        #pragma unroll
        for (int np = 0; np < 4; np++) {
            uint32_t r0, r1, r2, r3;
            ldsm4(r0, r1, r2, r3,
                  smem_u32(&Ks[np*16 + (lane & 15)][kk + (lane >> 4) * 8]));
            bfr[np*2][0] = r0;   bfr[np*2][1] = r2;
            bfr[np*2+1][0] = r1; bfr[np*2+1][1] = r3;
        }
        #pragma unroll
        for (int nt = 0; nt < 8; nt++) {
            mma_f16(acc[nt], af[0], af[1], af[2], af[3], bfr[nt][0], bfr[nt][1]);
        }
    }
}

__global__ void __launch_bounds__(256, 2) flash_kernel(const int* __restrict__ amask) {
    extern __shared__ char smc[];
    h16 (*Qs)[72] = (h16(*)[72])(smc + OFFB_QS);
    h16 (*Ks)[2][64][72] = (h16(*)[2][64][72])(smc + OFFB_KS);
    h16 (*Vs)[2][64][72] = (h16(*)[2][64][72])(smc + OFFB_VS);
    float (*wred)[64] = (float(*)[64])(smc + OFFB_WR);

    int bh = blockIdx.y, b = bh >> 4, h = bh & 15;
    int qblk = (int)(gridDim.x - 1 - blockIdx.x);
    int i0 = qblk << 7;
    int tid = threadIdx.x, lane = tid & 31, wid = tid >> 5;
    int rowk = tid >> 2, ck = (tid & 3) * 16;
    const h16* kbase = g_k  + ((size_t)bh*Tc) * Dc;
    const h16* vbase = g_vt + ((size_t)bh*Dc) * Tc;

    {
        int row = tid >> 1, c0 = (tid & 1) * 32;
        const h16* qp = g_q + ((size_t)bh*Tc + i0 + row)*Dc + c0;
        #pragma unroll
        for (int c8 = 0; c8 < 32; c8 += 8) {
            *(uint4*)&Qs[row][c0 + c8] = *(const uint4*)(qp + c8);
        }
    }

    int nj = (qblk + 1) * 2;
    float acc[8][4];
    float l0 = 0.f, l1 = 0.f;
    int ra = i0 + wid*16 + (lane >> 2);
    int rb = ra + 8;

    // ---------- pass A: l = sum 2^S ----------
    {
        const h16* kp = kbase + (size_t)rowk * Dc + ck;
        cp16(smem_u32(&(*Ks)[0][rowk][ck]),     kp);
        cp16(smem_u32(&(*Ks)[0][rowk][ck + 8]), kp + 8);
        CP_COMMIT();
    }
    for (int jb = 0; jb < nj; jb++) {
        int j0 = jb << 6;
        CP_WAIT0();
        __syncthreads();
        if (jb + 1 < nj) {
            const h16* kp = kbase + (size_t)(j0 + 64 + rowk) * Dc + ck;
            int bf = (jb + 1) & 1;
            cp16(smem_u32(&(*Ks)[bf][rowk][ck]),     kp);
            cp16(smem_u32(&(*Ks)[bf][rowk][ck + 8]), kp + 8);
        }
        CP_COMMIT();
        compute_S_w(Qs, (*Ks)[jb & 1], wid, lane, acc);
        float e0 = 0.f, e1 = 0.f;
        #pragma unroll
        for (int nt = 0; nt < 8; nt++) {
            int c0 = j0 + nt*8 + (lane & 3) * 2;
            int am0 = amask[b*Tc + c0], am1 = amask[b*Tc + c0 + 1];
            if (c0     <= ra && am0) { e0 += exp2f(acc[nt][0]); }
            if (c0 + 1 <= ra && am1) { e0 += exp2f(acc[nt][1]); }
            if (c0     <= rb && am0) { e1 += exp2f(acc[nt][2]); }
            if (c0 + 1 <= rb && am1) { e1 += exp2f(acc[nt][3]); }
        }
        e0 += __shfl_xor_sync(~0u, e0, 1);
        e0 += __shfl_xor_sync(~0u, e0, 2);
        e1 += __shfl_xor_sync(~0u, e1, 1);
        e1 += __shfl_xor_sync(~0u, e1, 2);
        l0 += e0;
        l1 += e1;
    }
    float lg0 = (l0 > 0.f) ? -__log2f(l0) : -60000.f;
    float lg1 = (l1 > 0.f) ? -__log2f(l1) : -60000.f;

    float acco[8][4];
    #pragma unroll
    for (int j = 0; j < 8; j++) {
        #pragma unroll
        for (int k = 0; k < 4; k++) { acco[j][k] = 0.f; }
    }

    // ---------- pass B: P = 2^(S+lg) via ex2.f16x2; reg colsum; O += P@V ----------
    __syncthreads();
    {
        const h16* kp = kbase + (size_t)rowk * Dc + ck;
        cp16(smem_u32(&(*Ks)[0][rowk][ck]),     kp);
        cp16(smem_u32(&(*Ks)[0][rowk][ck + 8]), kp + 8);
        const h16* vp = vbase + (size_t)rowk * Tc + ck;
        cp16(smem_u32(&(*Vs)[0][rowk][ck]),     vp);
        cp16(smem_u32(&(*Vs)[0][rowk][ck + 8]), vp + 8);
        CP_COMMIT();
    }
    for (int jb = 0; jb < nj; jb++) {
        int j0 = jb << 6;
        CP_WAIT0();
        __syncthreads();          // K/V[jb] visible; prior wred consumed by all
        if (jb + 1 < nj) {
            int bf = (jb + 1) & 1;
            const h16* kp = kbase + (size_t)(j0 + 64 + rowk) * Dc + ck;
            cp16(smem_u32(&(*Ks)[bf][rowk][ck]),     kp);
            cp16(smem_u32(&(*Ks)[bf][rowk][ck + 8]), kp + 8);
            const h16* vp = vbase + (size_t)rowk * Tc + j0 + 64 + ck;
            cp16(smem_u32(&(*Vs)[bf][rowk][ck]),     vp);
            cp16(smem_u32(&(*Vs)[bf][rowk][ck + 8]), vp + 8);
        }
        CP_COMMIT();
        compute_S_w(Qs, (*Ks)[jb & 1], wid, lane, acc);
        uint32_t pa[8], pb[8];
        #pragma unroll
        for (int nt = 0; nt < 8; nt++) {
            int cl = nt*8 + (lane & 3) * 2;
            int c0 = j0 + cl;
            int am0 = amask[b*Tc + c0], am1 = amask[b*Tc + c0 + 1];
            float a0 = (c0     <= ra && am0) ? (acc[nt][0] + lg0) : -60000.f;
            float a1 = (c0 + 1 <= ra && am1) ? (acc[nt][1] + lg0) : -60000.f;
            float b0 = (c0     <= rb && am0) ? (acc[nt][2] + lg1) : -60000.f;
            float b1 = (c0 + 1 <= rb && am1) ? (acc[nt][3] + lg1) : -60000.f;
            pa[nt] = ex2h2(a0, a1);
            pb[nt] = ex2h2(b0, b1);
            // per-warp colsum partials (rows of this warp) via shfl over row-quads
            __half2 ha, hb;
            memcpy(&ha, &pa[nt], 4);
            memcpy(&hb, &pb[nt], 4);
            float cs0 = __low2float(ha)  + __low2float(hb);
            float cs1 = __high2float(ha) + __high2float(hb);
            cs0 += __shfl_xor_sync(~0u, cs0, 4);
            cs0 += __shfl_xor_sync(~0u, cs0, 8);
            cs0 += __shfl_xor_sync(~0u, cs0, 16);
            cs1 += __shfl_xor_sync(~0u, cs1, 4);
            cs1 += __shfl_xor_sync(~0u, cs1, 8);
            cs1 += __shfl_xor_sync(~0u, cs1, 16);
            if (lane < 4) {
                wred[wid][nt*8 + lane*2]     = cs0;
                wred[wid][nt*8 + lane*2 + 1] = cs1;
            }
        }
        __syncthreads();          // wred visible
        if (tid < 64) {
            float s = 0.f;
            #pragma unroll
            for (int w = 0; w < 8; w++) { s += wred[w][tid]; }
            g_part[((size_t)bh*8 + qblk)*Tc + j0 + tid] = s;
        }
        // O += P @ V with A-fragments from registers
        #pragma unroll
        for (int g = 0; g < 4; g++) {
            int kk = g * 16;
            uint32_t bfr[8][2];
            #pragma unroll
            for (int np = 0; np < 4; np++) {
                uint32_t r0, r1, r2, r3;
                ldsm4(r0, r1, r2, r3,
                      smem_u32(&(*Vs)[jb & 1][np*16 + (lane & 15)][kk + (lane >> 4) * 8]));
                bfr[np*2][0] = r0;   bfr[np*2][1] = r2;
                bfr[np*2+1][0] = r1; bfr[np*2+1][1] = r3;
            }
            #pragma unroll
            for (int nt = 0; nt < 8; nt++) {
                mma_f16(acco[nt], pa[2*g], pb[2*g], pa[2*g + 1], pb[2*g + 1],
                        bfr[nt][0], bfr[nt][1]);
            }
        }
    }

    #pragma unroll
    for (int nt = 0; nt < 8; nt++) {
        int q0 = i0 + wid*16 + (lane >> 2);
        int d0 = nt*8 + (lane & 3) * 2;
        #pragma unroll
        for (int rr = 0; rr < 2; rr++) {
            int q = q0 + rr * 8;
            *(uint32_t*)&g_y[(size_t)(b*Tc + q) * Cc + h*64 + d0] =
                f2h2(acco[nt][rr*2], acco[nt][rr*2 + 1]);
        }
    }
    for (int c = i0 + 128 + tid; c < Tc; c += 256) {
        g_part[((size_t)bh*8 + qblk)*Tc + c] = 0.f;
    }
}

// ---------------- imp reduce ----------------
__global__ void __launch_bounds__(256) impreduce_kernel() {
    int gt = blockIdx.x * 256 + threadIdx.x;
    int b = gt >> 10, t = gt & 1023;
    float s = 0.f;
    const float* p = g_part + (size_t)b * 128 * Tc + t;
    for (int i = 0; i < 128; i++) { s += p[(size_t)i * Tc]; }
    float posn = (float)(Tc - t) / (float)Tc;
    g_imp[gt] = (s / (float)Hc) / (posn + 1e-8f);
}

__global__ void __launch_bounds__(1024) finalize_kernel(const int* __restrict__ amask,
                                                        const float* __restrict__ thrp,
                                                        float* __restrict__ outp) {
    int tid = threadIdx.x;
    float m = -3.4e38f;
    for (int i = tid; i < BT; i += 1024) { m = fmaxf(m, g_imp[i]); }
    __shared__ float red[32];
    #pragma unroll
    for (int o = 16; o; o >>= 1) { m = fmaxf(m, __shfl_xor_sync(~0u, m, o)); }
    if ((tid & 31) == 0) red[tid >> 5] = m;
    __syncthreads();
    if (tid < 32) {
        float v = red[tid];
        #pragma unroll
        for (int o = 16; o; o >>= 1) { v = fmaxf(v, __shfl_xor_sync(~0u, v, o)); }
        if (tid == 0) red[0] = v;
    }
    __syncthreads();
    float maxv = red[0];
    float thr = *thrp;
    float* maskp = outp + (size_t)BT * Cc;
    float* impp  = maskp + BT;
    for (int i = tid; i < BT; i += 1024) {
        int t = i & 1023;
        float iv = g_imp[i];
        if (t < SINKc) iv = maxv + 1.0f;
        float mk = (iv >= thr) ? 1.0f : 0.0f;
        if (t < SINKc) mk = 1.0f;
        if (amask[i] == 0) mk = 0.0f;
        maskp[i] = mk;
        impp[i]  = iv;
    }
}

// ---------------- launch ----------------
extern "C" void kernel_launch(void* const* d_in, const int* in_sizes, int n_in,
                              void* d_out, int out_size) {
    (void)in_sizes; (void)n_in; (void)out_size;
    const float* x      = (const float*)d_in[0];
    const int*   amask  = (const int*)  d_in[1];
    const float* W_attn = (const float*)d_in[2];
    const float* b_attn = (const float*)d_in[3];
    const float* W_proj = (const float*)d_in[4];
    const float* b_proj = (const float*)d_in[5];
    const float* ln1_w  = (const float*)d_in[6];
    const float* ln1_b  = (const float*)d_in[7];
    const float* ln2_w  = (const float*)d_in[8];
    const float* ln2_b  = (const float*)d_in[9];
    const float* W_fc   = (const float*)d_in[10];
    const float* b_fc   = (const float*)d_in[11];
    const float* W_fc2  = (const float*)d_in[12];
    const float* b_fc2  = (const float*)d_in[13];
    const float* thr    = (const float*)d_in[14];
    float* outp = (float*)d_out;

    h16 *ph, *pq, *pk, *pvt, *py, *pfc, *pwat, *pwpt, *pwft, *pwf2t;
    float *px2;
    cudaGetSymbolAddress((void**)&ph,    g_h);
    cudaGetSymbolAddress((void**)&pq,    g_q);
    cudaGetSymbolAddress((void**)&pk,    g_k);
    cudaGetSymbolAddress((void**)&pvt,   g_vt);
    cudaGetSymbolAddress((void**)&py,    g_y);
    cudaGetSymbolAddress((void**)&pfc,   g_fc);
    cudaGetSymbolAddress((void**)&px2,   g_x2);
    cudaGetSymbolAddress((void**)&pwat,  g_wat);
    cudaGetSymbolAddress((void**)&pwpt,  g_wpt);
    cudaGetSymbolAddress((void**)&pwft,  g_wft);
    cudaGetSymbolAddress((void**)&pwf2t, g_wf2t);

    cudaFuncSetAttribute(mma_gemm<1>, cudaFuncAttributeMaxDynamicSharedMemorySize, GSMEM_BYTES);
    cudaFuncSetAttribute(mma_gemm<2>, cudaFuncAttributeMaxDynamicSharedMemorySize, GSMEM_BYTES);
    cudaFuncSetAttribute(mma_gemm<3>, cudaFuncAttributeMaxDynamicSharedMemorySize, GSMEM_BYTES);
    cudaFuncSetAttribute(flash_kernel, cudaFuncAttributeMaxDynamicSharedMemorySize, ATT_SMEM_BYTES);

    trall_kernel<<<12288, 256>>>(W_attn, pwat, W_proj, pwpt, W_fc, pwft, W_fc2, pwf2t);

    ln_kernel<<<BT, 256>>>(x, ln1_w, ln1_b, ph);
    mma_gemm<1><<<dim3(3*Cc/128, BT/128), 256, GSMEM_BYTES>>>(ph, pwat, b_attn, nullptr,
                                                 nullptr, pq, pk, pvt, nullptr, BT, 3*Cc, Cc);
    flash_kernel<<<dim3(Tc/128, Bc*Hc), 256, ATT_SMEM_BYTES>>>(amask);
    impreduce_kernel<<<16, 256>>>();
    mma_gemm<2><<<dim3(Cc/128, BT/128), 256, GSMEM_BYTES>>>(py, pwpt, b_proj, x,
                                               px2, nullptr, nullptr, nullptr, nullptr, BT, Cc, Cc);
    ln_kernel<<<BT, 256>>>(px2, ln2_w, ln2_b, ph);
    mma_gemm<3><<<dim3(4*Cc/128, BT/128), 256, GSMEM_BYTES>>>(ph, pwft, b_fc, nullptr,
                                                 nullptr, nullptr, nullptr, nullptr, pfc, BT, 4*Cc, Cc);
    mma_gemm<2><<<dim3(Cc/128, BT/128), 256, GSMEM_BYTES>>>(pfc, pwf2t, b_fc2, px2,
                                               outp, nullptr, nullptr, nullptr, nullptr, BT, Cc, 4*Cc);
    finalize_kernel<<<1, 1024>>>(amask, thr, outp);
}